// round 3
// baseline (speedup 1.0000x reference)
#include <cuda_runtime.h>
#include <cuda_bf16.h>
#include <cstdint>

// Problem constants
#define B_  2
#define S_  2048
#define DM_ 2048
#define H_  16
#define KV_ 4
#define D_  128

// Scratch buffers (static __device__ — no allocation allowed)
__device__ float g_q [(size_t)B_ * S_ * H_  * D_];   // 8.39M floats
__device__ float g_k [(size_t)B_ * S_ * KV_ * D_];   // 2.10M floats
__device__ float g_v [(size_t)B_ * S_ * KV_ * D_];
__device__ float g_ao[(size_t)B_ * S_ * H_  * D_];

// ---------------------------------------------------------------------------
// GEMM (NT): C[M,N] = A[M,K] @ B[N,K]^T + bias.  A,B row-major, K contiguous.
// BM=BN=64, BK=16, 256 threads, 4x4 micro-tile per thread.
// ---------------------------------------------------------------------------
__global__ __launch_bounds__(256) void gemm_nt_kernel(
    const float* __restrict__ A, const float* __restrict__ Bm,
    const float* __restrict__ bias, float* __restrict__ C,
    int M, int N, int K)
{
    __shared__ float As[16][68];
    __shared__ float Bs[16][68];

    const int tid = threadIdx.x;
    const int ty  = tid >> 4;        // 0..15 -> row group
    const int tx  = tid & 15;        // 0..15 -> col group
    const int bm  = blockIdx.y * 64;
    const int bn  = blockIdx.x * 64;

    const int lr = tid >> 2;         // 0..63 tile row for loads
    const int lk = (tid & 3) << 2;   // 0,4,8,12 k-offset

    const float* Ap = A  + (size_t)(bm + lr) * K + lk;
    const float* Bp = Bm + (size_t)(bn + lr) * K + lk;

    float acc[4][4];
    #pragma unroll
    for (int i = 0; i < 4; i++)
        #pragma unroll
        for (int j = 0; j < 4; j++) acc[i][j] = 0.f;

    for (int k0 = 0; k0 < K; k0 += 16) {
        float4 av = *(const float4*)(Ap + k0);
        float4 bv = *(const float4*)(Bp + k0);
        As[lk + 0][lr] = av.x; As[lk + 1][lr] = av.y;
        As[lk + 2][lr] = av.z; As[lk + 3][lr] = av.w;
        Bs[lk + 0][lr] = bv.x; Bs[lk + 1][lr] = bv.y;
        Bs[lk + 2][lr] = bv.z; Bs[lk + 3][lr] = bv.w;
        __syncthreads();

        #pragma unroll
        for (int kk = 0; kk < 16; kk++) {
            float4 a4 = *(const float4*)&As[kk][ty << 2];
            float a[4] = {a4.x, a4.y, a4.z, a4.w};
            float b[4];
            #pragma unroll
            for (int j = 0; j < 4; j++) b[j] = Bs[kk][tx + (j << 4)];
            #pragma unroll
            for (int i = 0; i < 4; i++)
                #pragma unroll
                for (int j = 0; j < 4; j++)
                    acc[i][j] = fmaf(a[i], b[j], acc[i][j]);
        }
        __syncthreads();
    }

    #pragma unroll
    for (int j = 0; j < 4; j++) {
        int col = bn + tx + (j << 4);
        float bb = bias ? bias[col] : 0.f;
        #pragma unroll
        for (int i = 0; i < 4; i++)
            C[(size_t)(bm + (ty << 2) + i) * N + col] = acc[i][j] + bb;
    }
}

// ---------------------------------------------------------------------------
// RoPE (in-place on [B,S,nh,D] tensor). Each thread handles one (d, d+64) pair.
// q' [d]    = q[d]*cos[d]    - q[d+64]*sin[d]        (d < 64)
// q' [d+64] = q[d+64]*cos[d+64] + q[d]*sin[d+64]
// ---------------------------------------------------------------------------
__global__ void rope_kernel(float* __restrict__ t,
                            const float* __restrict__ cs,
                            const float* __restrict__ sn,
                            int nh, int total)
{
    int idx = blockIdx.x * 256 + threadIdx.x;
    if (idx >= total) return;
    int d  = idx & 63;
    int h  = (idx >> 6) % nh;
    int bs = idx / (64 * nh);

    float c0 = cs[(size_t)bs * D_ + d];
    float s0 = sn[(size_t)bs * D_ + d];
    float c1 = cs[(size_t)bs * D_ + d + 64];
    float s1 = sn[(size_t)bs * D_ + d + 64];

    float* p = t + ((size_t)bs * nh + h) * D_;
    float a  = p[d];
    float b2 = p[d + 64];
    p[d]      = a  * c0 - b2 * s0;
    p[d + 64] = b2 * c1 + a  * s1;
}

// ---------------------------------------------------------------------------
// Flash attention (causal, GQA). One block per (q-tile of 64, head, batch).
// 256 threads. fp32 online softmax. Q/K tiles stored transposed in smem
// (d-major, padded stride 65) for conflict-free score loop; V row-major.
// ---------------------------------------------------------------------------
#define ATTN_SMEM_FLOATS (128*65 + 128*65 + 64*128 + 64*65 + 192)

__global__ __launch_bounds__(256) void attn_kernel()
{
    extern __shared__ float sm[];
    float* sQT = sm;                      // [128][65] (d-major)
    float* sKT = sQT + 128 * 65;          // [128][65]
    float* sV  = sKT + 128 * 65;          // [64][128]
    float* sS  = sV  + 64 * 128;          // [64][65]
    float* sMx = sS  + 64 * 65;           // [64]
    float* sL  = sMx + 64;                // [64]
    float* sA  = sL  + 64;                // [64]

    const int tid = threadIdx.x;
    const int qt  = blockIdx.x;
    const int h   = blockIdx.y;
    const int b   = blockIdx.z;
    const int qs  = qt * 64;
    const int kvh = h >> 2;               // GQA: 4 q-heads per kv-head
    const int ty  = tid >> 4;             // 0..15
    const int tx  = tid & 15;             // 0..15
    const int i0  = ty << 2;              // owned rows i0..i0+3
    const int dc0 = tx << 3;              // owned d-cols dc0..dc0+7 (PV/out)
    const float scale = 0.08838834764831845f;  // 1/sqrt(128)

    // Load Q tile, transposed into sQT
    {
        size_t qbase = ((size_t)(b * S_ + qs) * H_ + h) * D_;
        for (int idx = tid; idx < 64 * 32; idx += 256) {
            int row = idx >> 5;
            int d0  = (idx & 31) << 2;
            float4 v = *(const float4*)(g_q + qbase + (size_t)row * (H_ * D_) + d0);
            sQT[(d0 + 0) * 65 + row] = v.x;
            sQT[(d0 + 1) * 65 + row] = v.y;
            sQT[(d0 + 2) * 65 + row] = v.z;
            sQT[(d0 + 3) * 65 + row] = v.w;
        }
    }
    if (tid < 64) { sMx[tid] = -1e30f; sL[tid] = 0.f; }

    float o[4][8];
    #pragma unroll
    for (int i = 0; i < 4; i++)
        #pragma unroll
        for (int c = 0; c < 8; c++) o[i][c] = 0.f;

    for (int kt = 0; kt <= qt; kt++) {
        const int ks = kt * 64;
        // Load K (transposed) and V (row-major)
        {
            size_t kb = ((size_t)(b * S_ + ks) * KV_ + kvh) * D_;
            for (int idx = tid; idx < 64 * 32; idx += 256) {
                int row = idx >> 5;
                int d0  = (idx & 31) << 2;
                float4 kv4 = *(const float4*)(g_k + kb + (size_t)row * (KV_ * D_) + d0);
                sKT[(d0 + 0) * 65 + row] = kv4.x;
                sKT[(d0 + 1) * 65 + row] = kv4.y;
                sKT[(d0 + 2) * 65 + row] = kv4.z;
                sKT[(d0 + 3) * 65 + row] = kv4.w;
                float4 vv = *(const float4*)(g_v + kb + (size_t)row * (KV_ * D_) + d0);
                *(float4*)&sV[row * 128 + d0] = vv;
            }
        }
        __syncthreads();

        // Scores: S[i,j] = sum_d Q[i,d] K[j,d]
        float acc[4][4];
        #pragma unroll
        for (int i = 0; i < 4; i++)
            #pragma unroll
            for (int j = 0; j < 4; j++) acc[i][j] = 0.f;

        #pragma unroll 4
        for (int d = 0; d < 128; d++) {
            float qv[4], kk4[4];
            #pragma unroll
            for (int i = 0; i < 4; i++) qv[i] = sQT[d * 65 + i0 + i];
            #pragma unroll
            for (int j = 0; j < 4; j++) kk4[j] = sKT[d * 65 + tx + (j << 4)];
            #pragma unroll
            for (int i = 0; i < 4; i++)
                #pragma unroll
                for (int j = 0; j < 4; j++)
                    acc[i][j] = fmaf(qv[i], kk4[j], acc[i][j]);
        }

        // Write scores with scale (+ causal mask on diagonal tile)
        if (kt == qt) {
            #pragma unroll
            for (int i = 0; i < 4; i++)
                #pragma unroll
                for (int j = 0; j < 4; j++) {
                    int gr = i0 + i;
                    int gc = tx + (j << 4);
                    sS[gr * 65 + gc] = (gc <= gr) ? acc[i][j] * scale : -1e30f;
                }
        } else {
            #pragma unroll
            for (int i = 0; i < 4; i++)
                #pragma unroll
                for (int j = 0; j < 4; j++)
                    sS[(i0 + i) * 65 + tx + (j << 4)] = acc[i][j] * scale;
        }
        __syncthreads();

        // Online softmax, one thread per row
        if (tid < 64) {
            float mx = sMx[tid];
            #pragma unroll 8
            for (int j = 0; j < 64; j++) mx = fmaxf(mx, sS[tid * 65 + j]);
            float alpha = __expf(sMx[tid] - mx);
            float sum = 0.f;
            #pragma unroll 8
            for (int j = 0; j < 64; j++) {
                float p = __expf(sS[tid * 65 + j] - mx);
                sS[tid * 65 + j] = p;
                sum += p;
            }
            sL[tid]  = sL[tid] * alpha + sum;
            sMx[tid] = mx;
            sA[tid]  = alpha;
        }
        __syncthreads();

        // O = O*alpha + P@V
        float al[4];
        #pragma unroll
        for (int i = 0; i < 4; i++) al[i] = sA[i0 + i];
        #pragma unroll
        for (int i = 0; i < 4; i++)
            #pragma unroll
            for (int c = 0; c < 8; c++) o[i][c] *= al[i];

        #pragma unroll 2
        for (int j = 0; j < 64; j++) {
            float p[4];
            #pragma unroll
            for (int i = 0; i < 4; i++) p[i] = sS[(i0 + i) * 65 + j];
            float4 v0 = *(const float4*)&sV[j * 128 + dc0];
            float4 v1 = *(const float4*)&sV[j * 128 + dc0 + 4];
            #pragma unroll
            for (int i = 0; i < 4; i++) {
                o[i][0] = fmaf(p[i], v0.x, o[i][0]);
                o[i][1] = fmaf(p[i], v0.y, o[i][1]);
                o[i][2] = fmaf(p[i], v0.z, o[i][2]);
                o[i][3] = fmaf(p[i], v0.w, o[i][3]);
                o[i][4] = fmaf(p[i], v1.x, o[i][4]);
                o[i][5] = fmaf(p[i], v1.y, o[i][5]);
                o[i][6] = fmaf(p[i], v1.z, o[i][6]);
                o[i][7] = fmaf(p[i], v1.w, o[i][7]);
            }
        }
        __syncthreads();   // protect sKT/sV/sS before next tile
    }

    // Normalize and write [B,S,H,D]
    #pragma unroll
    for (int i = 0; i < 4; i++) {
        float inv = 1.f / sL[i0 + i];
        float4 w0, w1;
        w0.x = o[i][0] * inv; w0.y = o[i][1] * inv;
        w0.z = o[i][2] * inv; w0.w = o[i][3] * inv;
        w1.x = o[i][4] * inv; w1.y = o[i][5] * inv;
        w1.z = o[i][6] * inv; w1.w = o[i][7] * inv;
        size_t obase = ((size_t)(b * S_ + qs + i0 + i) * H_ + h) * D_ + dc0;
        *(float4*)(g_ao + obase)     = w0;
        *(float4*)(g_ao + obase + 4) = w1;
    }
}

// ---------------------------------------------------------------------------
// kernel_launch
// ---------------------------------------------------------------------------
extern "C" void kernel_launch(void* const* d_in, const int* in_sizes, int n_in,
                              void* d_out, int out_size)
{
    const float* x    = (const float*)d_in[0];
    const float* cosp = (const float*)d_in[1];
    const float* sinp = (const float*)d_in[2];
    // d_in[3] = attention_mask (all ones; reference never uses it)
    const float* Wq = (const float*)d_in[4];
    const float* bq = (const float*)d_in[5];
    const float* Wk = (const float*)d_in[6];
    const float* bk = (const float*)d_in[7];
    const float* Wv = (const float*)d_in[8];
    const float* bv = (const float*)d_in[9];
    const float* Wo = (const float*)d_in[10];
    float* out = (float*)d_out;

    float *q, *k, *v, *ao;
    cudaGetSymbolAddress((void**)&q,  g_q);
    cudaGetSymbolAddress((void**)&k,  g_k);
    cudaGetSymbolAddress((void**)&v,  g_v);
    cudaGetSymbolAddress((void**)&ao, g_ao);

    const int M = B_ * S_;   // 4096

    // QKV projections
    gemm_nt_kernel<<<dim3(DM_ / 64, M / 64), 256>>>(x, Wq, bq, q, M, H_ * D_,  DM_);
    gemm_nt_kernel<<<dim3((KV_ * D_) / 64, M / 64), 256>>>(x, Wk, bk, k, M, KV_ * D_, DM_);
    gemm_nt_kernel<<<dim3((KV_ * D_) / 64, M / 64), 256>>>(x, Wv, bv, v, M, KV_ * D_, DM_);

    // RoPE on q and k
    {
        int tq = B_ * S_ * H_  * 64;   // 4,194,304
        int tk = B_ * S_ * KV_ * 64;   // 1,048,576
        rope_kernel<<<(tq + 255) / 256, 256>>>(q, cosp, sinp, H_,  tq);
        rope_kernel<<<(tk + 255) / 256, 256>>>(k, cosp, sinp, KV_, tk);
    }

    // Attention
    {
        const int smem_bytes = ATTN_SMEM_FLOATS * 4;  // 116,736 B
        cudaFuncSetAttribute(attn_kernel,
                             cudaFuncAttributeMaxDynamicSharedMemorySize,
                             smem_bytes);
        attn_kernel<<<dim3(S_ / 64, H_, B_), 256, smem_bytes>>>();
    }

    // Output projection (no bias)
    gemm_nt_kernel<<<dim3(DM_ / 64, M / 64), 256>>>(ao, Wo, nullptr, out, M, DM_, DM_);
}

// round 4
// speedup vs baseline: 1.4843x; 1.4843x over previous
#include <cuda_runtime.h>
#include <cuda_bf16.h>
#include <cstdint>

// Problem constants
#define B_  2
#define S_  2048
#define DM_ 2048
#define H_  16
#define KV_ 4
#define D_  128

#define XN  ((size_t)B_ * S_ * DM_)        // 8,388,608
#define QN  ((size_t)B_ * S_ * H_ * D_)    // 8,388,608
#define KN  ((size_t)B_ * S_ * KV_ * D_)   // 2,097,152
#define WQN ((size_t)H_ * D_ * DM_)        // 4,194,304
#define WKN ((size_t)KV_ * D_ * DM_)       // 1,048,576
#define WON ((size_t)DM_ * H_ * D_)        // 4,194,304

// fp32 scratch
__device__ float g_q [QN];
__device__ float g_k [KN];
__device__ float g_v [KN];
__device__ float g_ao[QN];

// bf16 hi/lo split scratch
__device__ __nv_bfloat16 g_xhi [XN],  g_xlo [XN];
__device__ __nv_bfloat16 g_wqhi[WQN], g_wqlo[WQN];
__device__ __nv_bfloat16 g_wkhi[WKN], g_wklo[WKN];
__device__ __nv_bfloat16 g_wvhi[WKN], g_wvlo[WKN];
__device__ __nv_bfloat16 g_wohi[WON], g_wolo[WON];
__device__ __nv_bfloat16 g_aohi[QN],  g_aolo[QN];

// ---------------------------------------------------------------------------
// fp32 -> (bf16 hi, bf16 lo) split.  x ≈ hi + lo with ~16 mantissa bits.
// ---------------------------------------------------------------------------
__global__ void split_kernel(const float* __restrict__ in,
                             __nv_bfloat16* __restrict__ hi,
                             __nv_bfloat16* __restrict__ lo, int n4)
{
    int i = blockIdx.x * 256 + threadIdx.x;
    if (i >= n4) return;
    float4 v = ((const float4*)in)[i];
    __nv_bfloat16 h0 = __float2bfloat16(v.x);
    __nv_bfloat16 h1 = __float2bfloat16(v.y);
    __nv_bfloat16 h2 = __float2bfloat16(v.z);
    __nv_bfloat16 h3 = __float2bfloat16(v.w);
    __nv_bfloat16 l0 = __float2bfloat16(v.x - __bfloat162float(h0));
    __nv_bfloat16 l1 = __float2bfloat16(v.y - __bfloat162float(h1));
    __nv_bfloat16 l2 = __float2bfloat16(v.z - __bfloat162float(h2));
    __nv_bfloat16 l3 = __float2bfloat16(v.w - __bfloat162float(h3));
    __nv_bfloat162* hp = (__nv_bfloat162*)hi;
    __nv_bfloat162* lp = (__nv_bfloat162*)lo;
    hp[i * 2 + 0] = __nv_bfloat162(h0, h1);
    hp[i * 2 + 1] = __nv_bfloat162(h2, h3);
    lp[i * 2 + 0] = __nv_bfloat162(l0, l1);
    lp[i * 2 + 1] = __nv_bfloat162(l2, l3);
}

// ---------------------------------------------------------------------------
// bf16 m16n8k16 mma wrapper (fp32 accumulate)
// ---------------------------------------------------------------------------
__device__ __forceinline__ void mma16816(float* c, const uint32_t* a, const uint32_t* b)
{
    asm volatile(
        "mma.sync.aligned.m16n8k16.row.col.f32.bf16.bf16.f32 "
        "{%0,%1,%2,%3}, {%4,%5,%6,%7}, {%8,%9}, {%0,%1,%2,%3};\n"
        : "+f"(c[0]), "+f"(c[1]), "+f"(c[2]), "+f"(c[3])
        : "r"(a[0]), "r"(a[1]), "r"(a[2]), "r"(a[3]),
          "r"(b[0]), "r"(b[1]));
}

// ---------------------------------------------------------------------------
// GEMM (NT) via 3x bf16 MMA: C[M,N] = (Ahi+Alo)[M,K] @ (Bhi+Blo)[N,K]^T + bias
// (dropping the lo*lo term).  Block tile 128x128x32, 8 warps (2x4),
// warp tile 64x32.  smem row stride = 20 u32 (conflict-free frag loads).
// ---------------------------------------------------------------------------
#define SSTRIDE 20

__global__ __launch_bounds__(256) void gemm_bf16x3(
    const __nv_bfloat16* __restrict__ Ahi, const __nv_bfloat16* __restrict__ Alo,
    const __nv_bfloat16* __restrict__ Bhi, const __nv_bfloat16* __restrict__ Blo,
    const float* __restrict__ bias, float* __restrict__ C,
    int M, int N, int K)
{
    __shared__ uint32_t sA[2][128 * SSTRIDE];
    __shared__ uint32_t sB[2][128 * SSTRIDE];

    const int tid  = threadIdx.x;
    const int lane = tid & 31;
    const int warp = tid >> 5;
    const int wm   = warp & 1;          // warp row (2 along M)
    const int wn   = warp >> 1;         // warp col (4 along N)
    const int bm   = blockIdx.y * 128;
    const int bn   = blockIdx.x * 128;

    const int lrow = tid >> 2;          // 0..63
    const int lkc  = tid & 3;           // 16B chunk within 32-elem row

    float acc[4][4][4];
    #pragma unroll
    for (int mf = 0; mf < 4; mf++)
        #pragma unroll
        for (int nf = 0; nf < 4; nf++)
            #pragma unroll
            for (int r = 0; r < 4; r++) acc[mf][nf][r] = 0.f;

    for (int k0 = 0; k0 < K; k0 += 32) {
        #pragma unroll
        for (int r = 0; r < 2; r++) {
            int row = lrow + r * 64;
            size_t ga = (size_t)(bm + row) * K + k0 + lkc * 8;
            size_t gb = (size_t)(bn + row) * K + k0 + lkc * 8;
            *(uint4*)&sA[0][row * SSTRIDE + lkc * 4] = *(const uint4*)(Ahi + ga);
            *(uint4*)&sA[1][row * SSTRIDE + lkc * 4] = *(const uint4*)(Alo + ga);
            *(uint4*)&sB[0][row * SSTRIDE + lkc * 4] = *(const uint4*)(Bhi + gb);
            *(uint4*)&sB[1][row * SSTRIDE + lkc * 4] = *(const uint4*)(Blo + gb);
        }
        __syncthreads();

        #pragma unroll
        for (int kq = 0; kq < 2; kq++) {
            const int kcol = kq * 8 + (lane & 3);
            uint32_t ah[4][4], al[4][4], bh[4][2], bl[4][2];

            const int arow = wm * 64 + (lane >> 2);
            #pragma unroll
            for (int mf = 0; mf < 4; mf++) {
                int rb = (arow + mf * 16) * SSTRIDE + kcol;
                ah[mf][0] = sA[0][rb];
                ah[mf][1] = sA[0][rb + 8 * SSTRIDE];
                ah[mf][2] = sA[0][rb + 4];
                ah[mf][3] = sA[0][rb + 8 * SSTRIDE + 4];
                al[mf][0] = sA[1][rb];
                al[mf][1] = sA[1][rb + 8 * SSTRIDE];
                al[mf][2] = sA[1][rb + 4];
                al[mf][3] = sA[1][rb + 8 * SSTRIDE + 4];
            }
            const int brow = wn * 32 + (lane >> 2);
            #pragma unroll
            for (int nf = 0; nf < 4; nf++) {
                int rb = (brow + nf * 8) * SSTRIDE + kcol;
                bh[nf][0] = sB[0][rb];
                bh[nf][1] = sB[0][rb + 4];
                bl[nf][0] = sB[1][rb];
                bl[nf][1] = sB[1][rb + 4];
            }
            #pragma unroll
            for (int mf = 0; mf < 4; mf++)
                #pragma unroll
                for (int nf = 0; nf < 4; nf++) {
                    mma16816(acc[mf][nf], ah[mf], bh[nf]);
                    mma16816(acc[mf][nf], ah[mf], bl[nf]);
                    mma16816(acc[mf][nf], al[mf], bh[nf]);
                }
        }
        __syncthreads();
    }

    // Epilogue: fp32 write + bias
    #pragma unroll
    for (int mf = 0; mf < 4; mf++) {
        int m0 = bm + wm * 64 + mf * 16 + (lane >> 2);
        #pragma unroll
        for (int nf = 0; nf < 4; nf++) {
            int n0 = bn + wn * 32 + nf * 8 + (lane & 3) * 2;
            float b0 = bias ? bias[n0]     : 0.f;
            float b1 = bias ? bias[n0 + 1] : 0.f;
            C[(size_t)m0 * N + n0]           = acc[mf][nf][0] + b0;
            C[(size_t)m0 * N + n0 + 1]       = acc[mf][nf][1] + b1;
            C[(size_t)(m0 + 8) * N + n0]     = acc[mf][nf][2] + b0;
            C[(size_t)(m0 + 8) * N + n0 + 1] = acc[mf][nf][3] + b1;
        }
    }
}

// ---------------------------------------------------------------------------
// RoPE (in-place on [B,S,nh,D] tensor), unchanged from R2.
// ---------------------------------------------------------------------------
__global__ void rope_kernel(float* __restrict__ t,
                            const float* __restrict__ cs,
                            const float* __restrict__ sn,
                            int nh, int total)
{
    int idx = blockIdx.x * 256 + threadIdx.x;
    if (idx >= total) return;
    int d  = idx & 63;
    int h  = (idx >> 6) % nh;
    int bs = idx / (64 * nh);

    float c0 = cs[(size_t)bs * D_ + d];
    float s0 = sn[(size_t)bs * D_ + d];
    float c1 = cs[(size_t)bs * D_ + d + 64];
    float s1 = sn[(size_t)bs * D_ + d + 64];

    float* p = t + ((size_t)bs * nh + h) * D_;
    float a  = p[d];
    float b2 = p[d + 64];
    p[d]      = a  * c0 - b2 * s0;
    p[d + 64] = b2 * c1 + a  * s1;
}

// ---------------------------------------------------------------------------
// Flash attention (causal, GQA), fp32, unchanged from R2 (passed @ 7e-7).
// ---------------------------------------------------------------------------
#define ATTN_SMEM_FLOATS (128*65 + 128*65 + 64*128 + 64*65 + 192)

__global__ __launch_bounds__(256) void attn_kernel()
{
    extern __shared__ float sm[];
    float* sQT = sm;
    float* sKT = sQT + 128 * 65;
    float* sV  = sKT + 128 * 65;
    float* sS  = sV  + 64 * 128;
    float* sMx = sS  + 64 * 65;
    float* sL  = sMx + 64;
    float* sA  = sL  + 64;

    const int tid = threadIdx.x;
    const int qt  = blockIdx.x;
    const int h   = blockIdx.y;
    const int b   = blockIdx.z;
    const int qs  = qt * 64;
    const int kvh = h >> 2;
    const int ty  = tid >> 4;
    const int tx  = tid & 15;
    const int i0  = ty << 2;
    const int dc0 = tx << 3;
    const float scale = 0.08838834764831845f;

    {
        size_t qbase = ((size_t)(b * S_ + qs) * H_ + h) * D_;
        for (int idx = tid; idx < 64 * 32; idx += 256) {
            int row = idx >> 5;
            int d0  = (idx & 31) << 2;
            float4 v = *(const float4*)(g_q + qbase + (size_t)row * (H_ * D_) + d0);
            sQT[(d0 + 0) * 65 + row] = v.x;
            sQT[(d0 + 1) * 65 + row] = v.y;
            sQT[(d0 + 2) * 65 + row] = v.z;
            sQT[(d0 + 3) * 65 + row] = v.w;
        }
    }
    if (tid < 64) { sMx[tid] = -1e30f; sL[tid] = 0.f; }

    float o[4][8];
    #pragma unroll
    for (int i = 0; i < 4; i++)
        #pragma unroll
        for (int c = 0; c < 8; c++) o[i][c] = 0.f;

    for (int kt = 0; kt <= qt; kt++) {
        const int ks = kt * 64;
        {
            size_t kb = ((size_t)(b * S_ + ks) * KV_ + kvh) * D_;
            for (int idx = tid; idx < 64 * 32; idx += 256) {
                int row = idx >> 5;
                int d0  = (idx & 31) << 2;
                float4 kv4 = *(const float4*)(g_k + kb + (size_t)row * (KV_ * D_) + d0);
                sKT[(d0 + 0) * 65 + row] = kv4.x;
                sKT[(d0 + 1) * 65 + row] = kv4.y;
                sKT[(d0 + 2) * 65 + row] = kv4.z;
                sKT[(d0 + 3) * 65 + row] = kv4.w;
                float4 vv = *(const float4*)(g_v + kb + (size_t)row * (KV_ * D_) + d0);
                *(float4*)&sV[row * 128 + d0] = vv;
            }
        }
        __syncthreads();

        float acc[4][4];
        #pragma unroll
        for (int i = 0; i < 4; i++)
            #pragma unroll
            for (int j = 0; j < 4; j++) acc[i][j] = 0.f;

        #pragma unroll 4
        for (int d = 0; d < 128; d++) {
            float qv[4], kk4[4];
            #pragma unroll
            for (int i = 0; i < 4; i++) qv[i] = sQT[d * 65 + i0 + i];
            #pragma unroll
            for (int j = 0; j < 4; j++) kk4[j] = sKT[d * 65 + tx + (j << 4)];
            #pragma unroll
            for (int i = 0; i < 4; i++)
                #pragma unroll
                for (int j = 0; j < 4; j++)
                    acc[i][j] = fmaf(qv[i], kk4[j], acc[i][j]);
        }

        if (kt == qt) {
            #pragma unroll
            for (int i = 0; i < 4; i++)
                #pragma unroll
                for (int j = 0; j < 4; j++) {
                    int gr = i0 + i;
                    int gc = tx + (j << 4);
                    sS[gr * 65 + gc] = (gc <= gr) ? acc[i][j] * scale : -1e30f;
                }
        } else {
            #pragma unroll
            for (int i = 0; i < 4; i++)
                #pragma unroll
                for (int j = 0; j < 4; j++)
                    sS[(i0 + i) * 65 + tx + (j << 4)] = acc[i][j] * scale;
        }
        __syncthreads();

        if (tid < 64) {
            float mx = sMx[tid];
            #pragma unroll 8
            for (int j = 0; j < 64; j++) mx = fmaxf(mx, sS[tid * 65 + j]);
            float alpha = __expf(sMx[tid] - mx);
            float sum = 0.f;
            #pragma unroll 8
            for (int j = 0; j < 64; j++) {
                float p = __expf(sS[tid * 65 + j] - mx);
                sS[tid * 65 + j] = p;
                sum += p;
            }
            sL[tid]  = sL[tid] * alpha + sum;
            sMx[tid] = mx;
            sA[tid]  = alpha;
        }
        __syncthreads();

        float al[4];
        #pragma unroll
        for (int i = 0; i < 4; i++) al[i] = sA[i0 + i];
        #pragma unroll
        for (int i = 0; i < 4; i++)
            #pragma unroll
            for (int c = 0; c < 8; c++) o[i][c] *= al[i];

        #pragma unroll 2
        for (int j = 0; j < 64; j++) {
            float p[4];
            #pragma unroll
            for (int i = 0; i < 4; i++) p[i] = sS[(i0 + i) * 65 + j];
            float4 v0 = *(const float4*)&sV[j * 128 + dc0];
            float4 v1 = *(const float4*)&sV[j * 128 + dc0 + 4];
            #pragma unroll
            for (int i = 0; i < 4; i++) {
                o[i][0] = fmaf(p[i], v0.x, o[i][0]);
                o[i][1] = fmaf(p[i], v0.y, o[i][1]);
                o[i][2] = fmaf(p[i], v0.z, o[i][2]);
                o[i][3] = fmaf(p[i], v0.w, o[i][3]);
                o[i][4] = fmaf(p[i], v1.x, o[i][4]);
                o[i][5] = fmaf(p[i], v1.y, o[i][5]);
                o[i][6] = fmaf(p[i], v1.z, o[i][6]);
                o[i][7] = fmaf(p[i], v1.w, o[i][7]);
            }
        }
        __syncthreads();
    }

    #pragma unroll
    for (int i = 0; i < 4; i++) {
        float inv = 1.f / sL[i0 + i];
        float4 w0, w1;
        w0.x = o[i][0] * inv; w0.y = o[i][1] * inv;
        w0.z = o[i][2] * inv; w0.w = o[i][3] * inv;
        w1.x = o[i][4] * inv; w1.y = o[i][5] * inv;
        w1.z = o[i][6] * inv; w1.w = o[i][7] * inv;
        size_t obase = ((size_t)(b * S_ + qs + i0 + i) * H_ + h) * D_ + dc0;
        *(float4*)(g_ao + obase)     = w0;
        *(float4*)(g_ao + obase + 4) = w1;
    }
}

// ---------------------------------------------------------------------------
// kernel_launch
// ---------------------------------------------------------------------------
extern "C" void kernel_launch(void* const* d_in, const int* in_sizes, int n_in,
                              void* d_out, int out_size)
{
    const float* x    = (const float*)d_in[0];
    const float* cosp = (const float*)d_in[1];
    const float* sinp = (const float*)d_in[2];
    // d_in[3] = attention_mask (all ones; unused by reference)
    const float* Wq = (const float*)d_in[4];
    const float* bq = (const float*)d_in[5];
    const float* Wk = (const float*)d_in[6];
    const float* bk = (const float*)d_in[7];
    const float* Wv = (const float*)d_in[8];
    const float* bv = (const float*)d_in[9];
    const float* Wo = (const float*)d_in[10];
    float* out = (float*)d_out;

    float *q, *k, *v, *ao;
    cudaGetSymbolAddress((void**)&q,  g_q);
    cudaGetSymbolAddress((void**)&k,  g_k);
    cudaGetSymbolAddress((void**)&v,  g_v);
    cudaGetSymbolAddress((void**)&ao, g_ao);

    __nv_bfloat16 *xhi, *xlo, *wqhi, *wqlo, *wkhi, *wklo, *wvhi, *wvlo, *wohi, *wolo, *aohi, *aolo;
    cudaGetSymbolAddress((void**)&xhi,  g_xhi);  cudaGetSymbolAddress((void**)&xlo,  g_xlo);
    cudaGetSymbolAddress((void**)&wqhi, g_wqhi); cudaGetSymbolAddress((void**)&wqlo, g_wqlo);
    cudaGetSymbolAddress((void**)&wkhi, g_wkhi); cudaGetSymbolAddress((void**)&wklo, g_wklo);
    cudaGetSymbolAddress((void**)&wvhi, g_wvhi); cudaGetSymbolAddress((void**)&wvlo, g_wvlo);
    cudaGetSymbolAddress((void**)&wohi, g_wohi); cudaGetSymbolAddress((void**)&wolo, g_wolo);
    cudaGetSymbolAddress((void**)&aohi, g_aohi); cudaGetSymbolAddress((void**)&aolo, g_aolo);

    const int M = B_ * S_;   // 4096

    // hi/lo splits for GEMM operands
    split_kernel<<<(int)(XN  / 4 + 255) / 256, 256>>>(x,  xhi,  xlo,  (int)(XN  / 4));
    split_kernel<<<(int)(WQN / 4 + 255) / 256, 256>>>(Wq, wqhi, wqlo, (int)(WQN / 4));
    split_kernel<<<(int)(WKN / 4 + 255) / 256, 256>>>(Wk, wkhi, wklo, (int)(WKN / 4));
    split_kernel<<<(int)(WKN / 4 + 255) / 256, 256>>>(Wv, wvhi, wvlo, (int)(WKN / 4));
    split_kernel<<<(int)(WON / 4 + 255) / 256, 256>>>(Wo, wohi, wolo, (int)(WON / 4));

    // QKV projections (bf16x3 tensor-core GEMM)
    gemm_bf16x3<<<dim3((H_ * D_) / 128, M / 128), 256>>>(xhi, xlo, wqhi, wqlo, bq, q, M, H_ * D_,  DM_);
    gemm_bf16x3<<<dim3((KV_ * D_) / 128, M / 128), 256>>>(xhi, xlo, wkhi, wklo, bk, k, M, KV_ * D_, DM_);
    gemm_bf16x3<<<dim3((KV_ * D_) / 128, M / 128), 256>>>(xhi, xlo, wvhi, wvlo, bv, v, M, KV_ * D_, DM_);

    // RoPE
    {
        int tq = B_ * S_ * H_  * 64;
        int tk = B_ * S_ * KV_ * 64;
        rope_kernel<<<(tq + 255) / 256, 256>>>(q, cosp, sinp, H_,  tq);
        rope_kernel<<<(tk + 255) / 256, 256>>>(k, cosp, sinp, KV_, tk);
    }

    // Attention (fp32 flash)
    {
        const int smem_bytes = ATTN_SMEM_FLOATS * 4;
        cudaFuncSetAttribute(attn_kernel,
                             cudaFuncAttributeMaxDynamicSharedMemorySize,
                             smem_bytes);
        attn_kernel<<<dim3(S_ / 64, H_, B_), 256, smem_bytes>>>();
    }

    // Split attention output, then O projection (bf16x3, no bias)
    split_kernel<<<(int)(QN / 4 + 255) / 256, 256>>>(ao, aohi, aolo, (int)(QN / 4));
    gemm_bf16x3<<<dim3(DM_ / 128, M / 128), 256>>>(aohi, aolo, wohi, wolo, nullptr, out, M, DM_, DM_);
}

// round 5
// speedup vs baseline: 3.0958x; 2.0858x over previous
#include <cuda_runtime.h>
#include <cuda_bf16.h>
#include <cstdint>

// Problem constants
#define B_  2
#define S_  2048
#define DM_ 2048
#define H_  16
#define KV_ 4
#define D_  128

#define XN  ((size_t)B_ * S_ * DM_)        // 8,388,608
#define QN  ((size_t)B_ * S_ * H_ * D_)    // 8,388,608
#define KN  ((size_t)B_ * S_ * KV_ * D_)   // 2,097,152
#define WQN ((size_t)H_ * D_ * DM_)        // 4,194,304
#define WKN ((size_t)KV_ * D_ * DM_)       // 1,048,576
#define WON ((size_t)DM_ * H_ * D_)        // 4,194,304

// fp32 scratch
__device__ float g_q [QN];
__device__ float g_k [KN];
__device__ float g_v [KN];
__device__ float g_ao[QN];

// bf16 hi/lo split scratch
__device__ __nv_bfloat16 g_xhi [XN],  g_xlo [XN];
__device__ __nv_bfloat16 g_wqhi[WQN], g_wqlo[WQN];
__device__ __nv_bfloat16 g_wkhi[WKN], g_wklo[WKN];
__device__ __nv_bfloat16 g_wvhi[WKN], g_wvlo[WKN];
__device__ __nv_bfloat16 g_wohi[WON], g_wolo[WON];
__device__ __nv_bfloat16 g_aohi[QN],  g_aolo[QN];
__device__ __nv_bfloat16 g_qhi [QN],  g_qlo [QN];
__device__ __nv_bfloat16 g_khi [KN],  g_klo [KN];
__device__ __nv_bfloat16 g_vthi[KN],  g_vtlo[KN];   // [B][KV][D][S]

// ---------------------------------------------------------------------------
// helpers
// ---------------------------------------------------------------------------
__device__ __forceinline__ void mma16816(float* c, const uint32_t* a, const uint32_t* b)
{
    asm volatile(
        "mma.sync.aligned.m16n8k16.row.col.f32.bf16.bf16.f32 "
        "{%0,%1,%2,%3}, {%4,%5,%6,%7}, {%8,%9}, {%0,%1,%2,%3};\n"
        : "+f"(c[0]), "+f"(c[1]), "+f"(c[2]), "+f"(c[3])
        : "r"(a[0]), "r"(a[1]), "r"(a[2]), "r"(a[3]),
          "r"(b[0]), "r"(b[1]));
}

__device__ __forceinline__ void cp16(uint32_t smem_byte_addr, const void* gptr)
{
    asm volatile("cp.async.cg.shared.global [%0], [%1], 16;\n"
                 :: "r"(smem_byte_addr), "l"(gptr));
}
#define CP_COMMIT() asm volatile("cp.async.commit_group;\n" ::: "memory")
#define CP_WAIT0()  asm volatile("cp.async.wait_group 0;\n" ::: "memory")

// pack two floats to bf16x2 (x -> low half), plus residual pack
__device__ __forceinline__ void pack_hilo(float a, float b, uint32_t& hi, uint32_t& lo)
{
    __nv_bfloat16 h0 = __float2bfloat16(a);
    __nv_bfloat16 h1 = __float2bfloat16(b);
    __nv_bfloat16 l0 = __float2bfloat16(a - __bfloat162float(h0));
    __nv_bfloat16 l1 = __float2bfloat16(b - __bfloat162float(h1));
    hi = ((uint32_t)*(uint16_t*)&h1 << 16) | *(uint16_t*)&h0;
    lo = ((uint32_t)*(uint16_t*)&l1 << 16) | *(uint16_t*)&l0;
}

// ---------------------------------------------------------------------------
// fp32 -> (bf16 hi, bf16 lo) split
// ---------------------------------------------------------------------------
__global__ void split_kernel(const float* __restrict__ in,
                             __nv_bfloat16* __restrict__ hi,
                             __nv_bfloat16* __restrict__ lo, int n4)
{
    int i = blockIdx.x * 256 + threadIdx.x;
    if (i >= n4) return;
    float4 v = ((const float4*)in)[i];
    uint32_t h0, l0, h1, l1;
    pack_hilo(v.x, v.y, h0, l0);
    pack_hilo(v.z, v.w, h1, l1);
    ((uint2*)hi)[i] = make_uint2(h0, h1);
    ((uint2*)lo)[i] = make_uint2(l0, l1);
}

// ---------------------------------------------------------------------------
// V transpose + split: g_v [B][S][KV][D] fp32 -> g_vt{hi,lo} [B][KV][D][S]
// ---------------------------------------------------------------------------
__global__ void vtrans_kernel(const float* __restrict__ v,
                              __nv_bfloat16* __restrict__ vthi,
                              __nv_bfloat16* __restrict__ vtlo)
{
    __shared__ float ts[32][33];
    const int bkv = blockIdx.z;               // b*KV + kv
    const int b   = bkv >> 2, kv = bkv & 3;
    const int s0  = blockIdx.x * 32, d0 = blockIdx.y * 32;
    const int tx  = threadIdx.x, ty = threadIdx.y;   // 32 x 8

    #pragma unroll
    for (int i = 0; i < 4; i++) {
        int s = s0 + ty + i * 8;
        ts[ty + i * 8][tx] = v[((size_t)(b * S_ + s) * KV_ + kv) * D_ + d0 + tx];
    }
    __syncthreads();
    #pragma unroll
    for (int i = 0; i < 4; i++) {
        int d = d0 + ty + i * 8;
        float val = ts[tx][ty + i * 8];
        __nv_bfloat16 h = __float2bfloat16(val);
        __nv_bfloat16 l = __float2bfloat16(val - __bfloat162float(h));
        size_t idx = ((size_t)bkv * D_ + d) * S_ + s0 + tx;
        vthi[idx] = h;
        vtlo[idx] = l;
    }
}

// ---------------------------------------------------------------------------
// GEMM (NT) via 3x bf16 MMA, 2-stage cp.async double buffer.
// C[M,N] = (Ahi+Alo)[M,K] @ (Bhi+Blo)[N,K]^T + bias
// Block tile 128x128x32, 8 warps (2x4), warp tile 64x32.
// ---------------------------------------------------------------------------
#define SSTRIDE 20
#define G_HALF  (128 * SSTRIDE)        // u32 per (stage, hi/lo) buffer: 2560
#define G_STG   (2 * G_HALF)           // u32 per stage (hi+lo): 5120
#define GEMM_SMEM_BYTES (4 * G_STG * 4)  // sA(2 stg) + sB(2 stg) = 81920 B

__global__ __launch_bounds__(256) void gemm_bf16x3(
    const __nv_bfloat16* __restrict__ Ahi, const __nv_bfloat16* __restrict__ Alo,
    const __nv_bfloat16* __restrict__ Bhi, const __nv_bfloat16* __restrict__ Blo,
    const float* __restrict__ bias, float* __restrict__ C,
    int M, int N, int K)
{
    extern __shared__ uint32_t sm[];
    uint32_t* sA = sm;                 // [2 stg][2 hilo][128*SSTRIDE]
    uint32_t* sB = sm + 2 * G_STG;

    const int tid  = threadIdx.x;
    const int lane = tid & 31;
    const int warp = tid >> 5;
    const int wm   = warp & 1;
    const int wn   = warp >> 1;
    const int bm   = blockIdx.y * 128;
    const int bn   = blockIdx.x * 128;

    const int lrow = tid >> 2;
    const int lkc  = tid & 3;

    const uint32_t saB = (uint32_t)__cvta_generic_to_shared(sA);
    const uint32_t sbB = (uint32_t)__cvta_generic_to_shared(sB);

    float acc[4][4][4];
    #pragma unroll
    for (int mf = 0; mf < 4; mf++)
        #pragma unroll
        for (int nf = 0; nf < 4; nf++)
            #pragma unroll
            for (int r = 0; r < 4; r++) acc[mf][nf][r] = 0.f;

    const int niter = K / 32;

    // async load of one stage
    auto load_stage = [&](int st, int k0) {
        #pragma unroll
        for (int r = 0; r < 2; r++) {
            int row = lrow + r * 64;
            size_t ga = (size_t)(bm + row) * K + k0 + lkc * 8;
            size_t gb = (size_t)(bn + row) * K + k0 + lkc * 8;
            uint32_t off = (uint32_t)(row * SSTRIDE + lkc * 4) * 4;
            uint32_t sbase = (uint32_t)(st * G_STG) * 4;
            cp16(saB + sbase + off,                Ahi + ga);
            cp16(saB + sbase + G_HALF * 4 + off,   Alo + ga);
            cp16(sbB + sbase + off,                Bhi + gb);
            cp16(sbB + sbase + G_HALF * 4 + off,   Blo + gb);
        }
    };

    load_stage(0, 0);
    CP_COMMIT();
    CP_WAIT0();
    __syncthreads();

    for (int it = 0; it < niter; it++) {
        if (it + 1 < niter) {
            load_stage((it + 1) & 1, (it + 1) * 32);
            CP_COMMIT();
        }

        const uint32_t* Ah = sA + (it & 1) * G_STG;
        const uint32_t* Al = Ah + G_HALF;
        const uint32_t* Bh = sB + (it & 1) * G_STG;
        const uint32_t* Bl = Bh + G_HALF;

        #pragma unroll
        for (int kq = 0; kq < 2; kq++) {
            const int kcol = kq * 8 + (lane & 3);
            uint32_t ah[4][4], al[4][4], bh[4][2], bl[4][2];

            const int arow = wm * 64 + (lane >> 2);
            #pragma unroll
            for (int mf = 0; mf < 4; mf++) {
                int rb = (arow + mf * 16) * SSTRIDE + kcol;
                ah[mf][0] = Ah[rb];
                ah[mf][1] = Ah[rb + 8 * SSTRIDE];
                ah[mf][2] = Ah[rb + 4];
                ah[mf][3] = Ah[rb + 8 * SSTRIDE + 4];
                al[mf][0] = Al[rb];
                al[mf][1] = Al[rb + 8 * SSTRIDE];
                al[mf][2] = Al[rb + 4];
                al[mf][3] = Al[rb + 8 * SSTRIDE + 4];
            }
            const int brow = wn * 32 + (lane >> 2);
            #pragma unroll
            for (int nf = 0; nf < 4; nf++) {
                int rb = (brow + nf * 8) * SSTRIDE + kcol;
                bh[nf][0] = Bh[rb];
                bh[nf][1] = Bh[rb + 4];
                bl[nf][0] = Bl[rb];
                bl[nf][1] = Bl[rb + 4];
            }
            #pragma unroll
            for (int mf = 0; mf < 4; mf++)
                #pragma unroll
                for (int nf = 0; nf < 4; nf++) {
                    mma16816(acc[mf][nf], ah[mf], bh[nf]);
                    mma16816(acc[mf][nf], ah[mf], bl[nf]);
                    mma16816(acc[mf][nf], al[mf], bh[nf]);
                }
        }

        if (it + 1 < niter) CP_WAIT0();
        __syncthreads();
    }

    #pragma unroll
    for (int mf = 0; mf < 4; mf++) {
        int m0 = bm + wm * 64 + mf * 16 + (lane >> 2);
        #pragma unroll
        for (int nf = 0; nf < 4; nf++) {
            int n0 = bn + wn * 32 + nf * 8 + (lane & 3) * 2;
            float b0 = bias ? bias[n0]     : 0.f;
            float b1 = bias ? bias[n0 + 1] : 0.f;
            C[(size_t)m0 * N + n0]           = acc[mf][nf][0] + b0;
            C[(size_t)m0 * N + n0 + 1]       = acc[mf][nf][1] + b1;
            C[(size_t)(m0 + 8) * N + n0]     = acc[mf][nf][2] + b0;
            C[(size_t)(m0 + 8) * N + n0 + 1] = acc[mf][nf][3] + b1;
        }
    }
}

// ---------------------------------------------------------------------------
// RoPE (in-place on [B,S,nh,D] tensor)
// ---------------------------------------------------------------------------
__global__ void rope_kernel(float* __restrict__ t,
                            const float* __restrict__ cs,
                            const float* __restrict__ sn,
                            int nh, int total)
{
    int idx = blockIdx.x * 256 + threadIdx.x;
    if (idx >= total) return;
    int d  = idx & 63;
    int h  = (idx >> 6) % nh;
    int bs = idx / (64 * nh);

    float c0 = cs[(size_t)bs * D_ + d];
    float s0 = sn[(size_t)bs * D_ + d];
    float c1 = cs[(size_t)bs * D_ + d + 64];
    float s1 = sn[(size_t)bs * D_ + d + 64];

    float* p = t + ((size_t)bs * nh + h) * D_;
    float a  = p[d];
    float b2 = p[d + 64];
    p[d]      = a  * c0 - b2 * s0;
    p[d + 64] = b2 * c1 + a  * s1;
}

// ---------------------------------------------------------------------------
// MMA flash attention (causal, GQA), bf16x3.
// Block: BQ=64 q-rows x (head, batch). 128 threads = 4 warps, warp tile M=16.
// QK^T: A=Q[16x128], B=K[64x128] (K-major). PV: A=P (built in regs from the
// softmaxed QK accumulator - layouts coincide), B=V^T from [D][S] bf16 tiles.
// smem u32 strides: Q/K rows 68 (128 bf16 + pad), VT rows 36 (64 bf16 + pad).
// ---------------------------------------------------------------------------
#define AQS 68
#define AVS 36
#define A_QOFF (64 * AQS)                  // u32 offset hi->lo
#define A_VOFF (128 * AVS)
#define ATTN_SMEM_BYTES ((2*64*AQS + 2*64*AQS + 2*128*AVS) * 4)  // 106,496

__global__ __launch_bounds__(128) void attn_mma_kernel()
{
    extern __shared__ uint32_t smu[];
    uint32_t* sQ  = smu;                       // [2][64][AQS]
    uint32_t* sK  = sQ + 2 * 64 * AQS;         // [2][64][AQS]
    uint32_t* sVT = sK + 2 * 64 * AQS;         // [2][128][AVS]

    const int tid  = threadIdx.x;
    const int lane = tid & 31;
    const int warp = tid >> 5;                 // 0..3
    const int g    = lane >> 2;                // 0..7
    const int t    = lane & 3;                 // 0..3
    const int qt   = gridDim.x - 1 - blockIdx.x;   // long blocks first
    const int h    = blockIdx.y;
    const int b    = blockIdx.z;
    const int qs   = qt * 64;
    const int kvh  = h >> 2;
    const float scale = 0.08838834764831845f;

    // Load Q tile (hi/lo)
    #pragma unroll
    for (int it = 0; it < 8; it++) {
        int idx = tid + it * 128;
        int row = idx >> 4;
        int c4  = idx & 15;
        size_t gq = ((size_t)((b * S_ + qs + row) * H_ + h)) * D_ + c4 * 8;
        *(uint4*)&sQ[row * AQS + c4 * 4]          = *(const uint4*)(g_qhi + gq);
        *(uint4*)&sQ[A_QOFF + row * AQS + c4 * 4] = *(const uint4*)(g_qlo + gq);
    }

    float o[16][4];
    #pragma unroll
    for (int nf = 0; nf < 16; nf++)
        #pragma unroll
        for (int r = 0; r < 4; r++) o[nf][r] = 0.f;
    float mrow[2] = {-1e30f, -1e30f};
    float lrow[2] = {0.f, 0.f};

    for (int kt = 0; kt <= qt; kt++) {
        __syncthreads();   // protect smem vs previous iteration reads (and Q writes on kt=0)
        const int ks = kt * 64;

        #pragma unroll
        for (int it = 0; it < 8; it++) {
            int idx = tid + it * 128;
            int row = idx >> 4, c4 = idx & 15;
            size_t gk = ((size_t)((b * S_ + ks + row) * KV_ + kvh)) * D_ + c4 * 8;
            *(uint4*)&sK[row * AQS + c4 * 4]          = *(const uint4*)(g_khi + gk);
            *(uint4*)&sK[A_QOFF + row * AQS + c4 * 4] = *(const uint4*)(g_klo + gk);
            int vrow = idx >> 3, vc = idx & 7;
            size_t gv = ((size_t)((b * KV_ + kvh) * D_ + vrow)) * S_ + ks + vc * 8;
            *(uint4*)&sVT[vrow * AVS + vc * 4]          = *(const uint4*)(g_vthi + gv);
            *(uint4*)&sVT[A_VOFF + vrow * AVS + vc * 4] = *(const uint4*)(g_vtlo + gv);
        }
        __syncthreads();

        // ---- QK^T ----
        float acc[8][4];
        #pragma unroll
        for (int nf = 0; nf < 8; nf++)
            #pragma unroll
            for (int r = 0; r < 4; r++) acc[nf][r] = 0.f;

        const int arow = warp * 16 + g;
        #pragma unroll
        for (int kq = 0; kq < 8; kq++) {
            const int kcol = kq * 8 + t;
            uint32_t ah[4], al[4];
            ah[0] = sQ[arow * AQS + kcol];
            ah[1] = sQ[(arow + 8) * AQS + kcol];
            ah[2] = sQ[arow * AQS + kcol + 4];
            ah[3] = sQ[(arow + 8) * AQS + kcol + 4];
            al[0] = sQ[A_QOFF + arow * AQS + kcol];
            al[1] = sQ[A_QOFF + (arow + 8) * AQS + kcol];
            al[2] = sQ[A_QOFF + arow * AQS + kcol + 4];
            al[3] = sQ[A_QOFF + (arow + 8) * AQS + kcol + 4];
            #pragma unroll
            for (int nf = 0; nf < 8; nf++) {
                const int brow = nf * 8 + g;
                uint32_t bh[2], bl[2];
                bh[0] = sK[brow * AQS + kcol];
                bh[1] = sK[brow * AQS + kcol + 4];
                bl[0] = sK[A_QOFF + brow * AQS + kcol];
                bl[1] = sK[A_QOFF + brow * AQS + kcol + 4];
                mma16816(acc[nf], ah, bh);
                mma16816(acc[nf], ah, bl);
                mma16816(acc[nf], al, bh);
            }
        }

        // ---- scale + causal mask ----
        if (kt == qt) {
            const int gr = warp * 16 + g;   // qs == ks: compare local indices
            #pragma unroll
            for (int nf = 0; nf < 8; nf++) {
                int c0 = nf * 8 + 2 * t;
                acc[nf][0] = (c0     <= gr    ) ? acc[nf][0] * scale : -1e30f;
                acc[nf][1] = (c0 + 1 <= gr    ) ? acc[nf][1] * scale : -1e30f;
                acc[nf][2] = (c0     <= gr + 8) ? acc[nf][2] * scale : -1e30f;
                acc[nf][3] = (c0 + 1 <= gr + 8) ? acc[nf][3] * scale : -1e30f;
            }
        } else {
            #pragma unroll
            for (int nf = 0; nf < 8; nf++)
                #pragma unroll
                for (int r = 0; r < 4; r++) acc[nf][r] *= scale;
        }

        // ---- online softmax (rows g and g+8; 4 lanes share a row) ----
        float mx0 = -1e30f, mx1 = -1e30f;
        #pragma unroll
        for (int nf = 0; nf < 8; nf++) {
            mx0 = fmaxf(mx0, fmaxf(acc[nf][0], acc[nf][1]));
            mx1 = fmaxf(mx1, fmaxf(acc[nf][2], acc[nf][3]));
        }
        mx0 = fmaxf(mx0, __shfl_xor_sync(0xffffffffu, mx0, 1));
        mx0 = fmaxf(mx0, __shfl_xor_sync(0xffffffffu, mx0, 2));
        mx1 = fmaxf(mx1, __shfl_xor_sync(0xffffffffu, mx1, 1));
        mx1 = fmaxf(mx1, __shfl_xor_sync(0xffffffffu, mx1, 2));

        float nm0 = fmaxf(mrow[0], mx0), nm1 = fmaxf(mrow[1], mx1);
        float alpha0 = __expf(mrow[0] - nm0), alpha1 = __expf(mrow[1] - nm1);
        mrow[0] = nm0; mrow[1] = nm1;

        float sum0 = 0.f, sum1 = 0.f;
        #pragma unroll
        for (int nf = 0; nf < 8; nf++) {
            acc[nf][0] = __expf(acc[nf][0] - nm0); sum0 += acc[nf][0];
            acc[nf][1] = __expf(acc[nf][1] - nm0); sum0 += acc[nf][1];
            acc[nf][2] = __expf(acc[nf][2] - nm1); sum1 += acc[nf][2];
            acc[nf][3] = __expf(acc[nf][3] - nm1); sum1 += acc[nf][3];
        }
        sum0 += __shfl_xor_sync(0xffffffffu, sum0, 1);
        sum0 += __shfl_xor_sync(0xffffffffu, sum0, 2);
        sum1 += __shfl_xor_sync(0xffffffffu, sum1, 1);
        sum1 += __shfl_xor_sync(0xffffffffu, sum1, 2);
        lrow[0] = lrow[0] * alpha0 + sum0;
        lrow[1] = lrow[1] * alpha1 + sum1;

        #pragma unroll
        for (int nf = 0; nf < 16; nf++) {
            o[nf][0] *= alpha0; o[nf][1] *= alpha0;
            o[nf][2] *= alpha1; o[nf][3] *= alpha1;
        }

        // ---- P @ V : A-fragments built from acc in registers ----
        #pragma unroll
        for (int kq = 0; kq < 4; kq++) {
            uint32_t pah[4], pal[4];
            pack_hilo(acc[2*kq  ][0], acc[2*kq  ][1], pah[0], pal[0]);
            pack_hilo(acc[2*kq  ][2], acc[2*kq  ][3], pah[1], pal[1]);
            pack_hilo(acc[2*kq+1][0], acc[2*kq+1][1], pah[2], pal[2]);
            pack_hilo(acc[2*kq+1][2], acc[2*kq+1][3], pah[3], pal[3]);
            const int kcol = kq * 8 + t;
            #pragma unroll
            for (int nf = 0; nf < 16; nf++) {
                const int brow = nf * 8 + g;
                uint32_t bh[2], bl[2];
                bh[0] = sVT[brow * AVS + kcol];
                bh[1] = sVT[brow * AVS + kcol + 4];
                bl[0] = sVT[A_VOFF + brow * AVS + kcol];
                bl[1] = sVT[A_VOFF + brow * AVS + kcol + 4];
                mma16816(o[nf], pah, bh);
                mma16816(o[nf], pah, bl);
                mma16816(o[nf], pal, bh);
            }
        }
    }

    // ---- epilogue: normalize, write [B,S,H,D] ----
    float inv0 = 1.f / lrow[0], inv1 = 1.f / lrow[1];
    size_t base0 = ((size_t)((b * S_ + qs + warp * 16 + g)) * H_ + h) * D_;
    size_t base1 = base0 + (size_t)8 * H_ * D_;
    #pragma unroll
    for (int nf = 0; nf < 16; nf++) {
        int d0 = nf * 8 + 2 * t;
        *(float2*)(g_ao + base0 + d0) = make_float2(o[nf][0] * inv0, o[nf][1] * inv0);
        *(float2*)(g_ao + base1 + d0) = make_float2(o[nf][2] * inv1, o[nf][3] * inv1);
    }
}

// ---------------------------------------------------------------------------
// kernel_launch
// ---------------------------------------------------------------------------
extern "C" void kernel_launch(void* const* d_in, const int* in_sizes, int n_in,
                              void* d_out, int out_size)
{
    const float* x    = (const float*)d_in[0];
    const float* cosp = (const float*)d_in[1];
    const float* sinp = (const float*)d_in[2];
    // d_in[3] = attention_mask (all ones; unused by reference)
    const float* Wq = (const float*)d_in[4];
    const float* bq = (const float*)d_in[5];
    const float* Wk = (const float*)d_in[6];
    const float* bk = (const float*)d_in[7];
    const float* Wv = (const float*)d_in[8];
    const float* bv = (const float*)d_in[9];
    const float* Wo = (const float*)d_in[10];
    float* out = (float*)d_out;

    float *q, *k, *v, *ao;
    cudaGetSymbolAddress((void**)&q,  g_q);
    cudaGetSymbolAddress((void**)&k,  g_k);
    cudaGetSymbolAddress((void**)&v,  g_v);
    cudaGetSymbolAddress((void**)&ao, g_ao);

    __nv_bfloat16 *xhi, *xlo, *wqhi, *wqlo, *wkhi, *wklo, *wvhi, *wvlo, *wohi, *wolo;
    __nv_bfloat16 *aohi, *aolo, *qhi, *qlo, *khi, *klo, *vthi, *vtlo;
    cudaGetSymbolAddress((void**)&xhi,  g_xhi);  cudaGetSymbolAddress((void**)&xlo,  g_xlo);
    cudaGetSymbolAddress((void**)&wqhi, g_wqhi); cudaGetSymbolAddress((void**)&wqlo, g_wqlo);
    cudaGetSymbolAddress((void**)&wkhi, g_wkhi); cudaGetSymbolAddress((void**)&wklo, g_wklo);
    cudaGetSymbolAddress((void**)&wvhi, g_wvhi); cudaGetSymbolAddress((void**)&wvlo, g_wvlo);
    cudaGetSymbolAddress((void**)&wohi, g_wohi); cudaGetSymbolAddress((void**)&wolo, g_wolo);
    cudaGetSymbolAddress((void**)&aohi, g_aohi); cudaGetSymbolAddress((void**)&aolo, g_aolo);
    cudaGetSymbolAddress((void**)&qhi,  g_qhi);  cudaGetSymbolAddress((void**)&qlo,  g_qlo);
    cudaGetSymbolAddress((void**)&khi,  g_khi);  cudaGetSymbolAddress((void**)&klo,  g_klo);
    cudaGetSymbolAddress((void**)&vthi, g_vthi); cudaGetSymbolAddress((void**)&vtlo, g_vtlo);

    const int M = B_ * S_;   // 4096

    // hi/lo splits for GEMM operands
    split_kernel<<<(int)(XN  / 4 + 255) / 256, 256>>>(x,  xhi,  xlo,  (int)(XN  / 4));
    split_kernel<<<(int)(WQN / 4 + 255) / 256, 256>>>(Wq, wqhi, wqlo, (int)(WQN / 4));
    split_kernel<<<(int)(WKN / 4 + 255) / 256, 256>>>(Wk, wkhi, wklo, (int)(WKN / 4));
    split_kernel<<<(int)(WKN / 4 + 255) / 256, 256>>>(Wv, wvhi, wvlo, (int)(WKN / 4));
    split_kernel<<<(int)(WON / 4 + 255) / 256, 256>>>(Wo, wohi, wolo, (int)(WON / 4));

    cudaFuncSetAttribute(gemm_bf16x3, cudaFuncAttributeMaxDynamicSharedMemorySize,
                         GEMM_SMEM_BYTES);

    // QKV projections
    gemm_bf16x3<<<dim3((H_ * D_) / 128, M / 128), 256, GEMM_SMEM_BYTES>>>(
        xhi, xlo, wqhi, wqlo, bq, q, M, H_ * D_,  DM_);
    gemm_bf16x3<<<dim3((KV_ * D_) / 128, M / 128), 256, GEMM_SMEM_BYTES>>>(
        xhi, xlo, wkhi, wklo, bk, k, M, KV_ * D_, DM_);
    gemm_bf16x3<<<dim3((KV_ * D_) / 128, M / 128), 256, GEMM_SMEM_BYTES>>>(
        xhi, xlo, wvhi, wvlo, bv, v, M, KV_ * D_, DM_);

    // RoPE
    {
        int tq = B_ * S_ * H_  * 64;
        int tk = B_ * S_ * KV_ * 64;
        rope_kernel<<<(tq + 255) / 256, 256>>>(q, cosp, sinp, H_,  tq);
        rope_kernel<<<(tk + 255) / 256, 256>>>(k, cosp, sinp, KV_, tk);
    }

    // Split post-RoPE q/k; transpose+split V
    split_kernel<<<(int)(QN / 4 + 255) / 256, 256>>>(q, qhi, qlo, (int)(QN / 4));
    split_kernel<<<(int)(KN / 4 + 255) / 256, 256>>>(k, khi, klo, (int)(KN / 4));
    vtrans_kernel<<<dim3(S_ / 32, D_ / 32, B_ * KV_), dim3(32, 8)>>>(v, vthi, vtlo);

    // MMA flash attention
    cudaFuncSetAttribute(attn_mma_kernel, cudaFuncAttributeMaxDynamicSharedMemorySize,
                         ATTN_SMEM_BYTES);
    attn_mma_kernel<<<dim3(S_ / 64, H_, B_), 128, ATTN_SMEM_BYTES>>>();

    // Split attention output, then O projection
    split_kernel<<<(int)(QN / 4 + 255) / 256, 256>>>(ao, aohi, aolo, (int)(QN / 4));
    gemm_bf16x3<<<dim3(DM_ / 128, M / 128), 256, GEMM_SMEM_BYTES>>>(
        aohi, aolo, wohi, wolo, nullptr, out, M, DM_, DM_);
}

// round 6
// speedup vs baseline: 3.2415x; 1.0470x over previous
#include <cuda_runtime.h>
#include <cuda_bf16.h>
#include <cstdint>

// Problem constants
#define B_  2
#define S_  2048
#define DM_ 2048
#define H_  16
#define KV_ 4
#define D_  128

#define XN  ((size_t)B_ * S_ * DM_)        // 8,388,608
#define QN  ((size_t)B_ * S_ * H_ * D_)    // 8,388,608
#define KN  ((size_t)B_ * S_ * KV_ * D_)   // 2,097,152
#define WQN ((size_t)H_ * D_ * DM_)        // 4,194,304
#define WKN ((size_t)KV_ * D_ * DM_)       // 1,048,576
#define WON ((size_t)DM_ * H_ * D_)        // 4,194,304

// fp32 scratch (pre-RoPE / pre-transpose)
__device__ float g_q [QN];
__device__ float g_k [KN];
__device__ float g_v [KN];

// bf16 hi/lo split scratch
__device__ __nv_bfloat16 g_xhi [XN],  g_xlo [XN];
__device__ __nv_bfloat16 g_wqhi[WQN], g_wqlo[WQN];
__device__ __nv_bfloat16 g_wkhi[WKN], g_wklo[WKN];
__device__ __nv_bfloat16 g_wvhi[WKN], g_wvlo[WKN];
__device__ __nv_bfloat16 g_wohi[WON], g_wolo[WON];
__device__ __nv_bfloat16 g_aohi[QN],  g_aolo[QN];
__device__ __nv_bfloat16 g_qhi [QN],  g_qlo [QN];
__device__ __nv_bfloat16 g_khi [KN],  g_klo [KN];
__device__ __nv_bfloat16 g_vthi[KN],  g_vtlo[KN];   // [B][KV][D][S]

// ---------------------------------------------------------------------------
// helpers
// ---------------------------------------------------------------------------
__device__ __forceinline__ void mma16816(float* c, const uint32_t* a, const uint32_t* b)
{
    asm volatile(
        "mma.sync.aligned.m16n8k16.row.col.f32.bf16.bf16.f32 "
        "{%0,%1,%2,%3}, {%4,%5,%6,%7}, {%8,%9}, {%0,%1,%2,%3};\n"
        : "+f"(c[0]), "+f"(c[1]), "+f"(c[2]), "+f"(c[3])
        : "r"(a[0]), "r"(a[1]), "r"(a[2]), "r"(a[3]),
          "r"(b[0]), "r"(b[1]));
}

__device__ __forceinline__ void ldsm_x4(uint32_t* r, uint32_t addr)
{
    asm volatile("ldmatrix.sync.aligned.m8n8.x4.shared.b16 {%0,%1,%2,%3}, [%4];\n"
                 : "=r"(r[0]), "=r"(r[1]), "=r"(r[2]), "=r"(r[3]) : "r"(addr));
}

__device__ __forceinline__ void cp16(uint32_t smem_byte_addr, const void* gptr)
{
    asm volatile("cp.async.cg.shared.global [%0], [%1], 16;\n"
                 :: "r"(smem_byte_addr), "l"(gptr));
}
#define CP_COMMIT() asm volatile("cp.async.commit_group;\n" ::: "memory")
#define CP_WAIT0()  asm volatile("cp.async.wait_group 0;\n" ::: "memory")

__device__ __forceinline__ void pack_hilo(float a, float b, uint32_t& hi, uint32_t& lo)
{
    __nv_bfloat16 h0 = __float2bfloat16(a);
    __nv_bfloat16 h1 = __float2bfloat16(b);
    __nv_bfloat16 l0 = __float2bfloat16(a - __bfloat162float(h0));
    __nv_bfloat16 l1 = __float2bfloat16(b - __bfloat162float(h1));
    hi = ((uint32_t)*(uint16_t*)&h1 << 16) | *(uint16_t*)&h0;
    lo = ((uint32_t)*(uint16_t*)&l1 << 16) | *(uint16_t*)&l0;
}

// ---------------------------------------------------------------------------
// fp32 -> (bf16 hi, bf16 lo) split
// ---------------------------------------------------------------------------
__global__ void split_kernel(const float* __restrict__ in,
                             __nv_bfloat16* __restrict__ hi,
                             __nv_bfloat16* __restrict__ lo, int n4)
{
    int i = blockIdx.x * 256 + threadIdx.x;
    if (i >= n4) return;
    float4 v = ((const float4*)in)[i];
    uint32_t h0, l0, h1, l1;
    pack_hilo(v.x, v.y, h0, l0);
    pack_hilo(v.z, v.w, h1, l1);
    ((uint2*)hi)[i] = make_uint2(h0, h1);
    ((uint2*)lo)[i] = make_uint2(l0, l1);
}

// ---------------------------------------------------------------------------
// Fused RoPE + hi/lo split: reads fp32 [B,S,nh,D], writes bf16 hi/lo.
// ---------------------------------------------------------------------------
__global__ void rope_split_kernel(const float* __restrict__ t,
                                  const float* __restrict__ cs,
                                  const float* __restrict__ sn,
                                  __nv_bfloat16* __restrict__ hi,
                                  __nv_bfloat16* __restrict__ lo,
                                  int nh, int total)
{
    int idx = blockIdx.x * 256 + threadIdx.x;
    if (idx >= total) return;
    int d  = idx & 63;
    int h  = (idx >> 6) % nh;
    int bs = idx / (64 * nh);

    float c0 = cs[(size_t)bs * D_ + d];
    float s0 = sn[(size_t)bs * D_ + d];
    float c1 = cs[(size_t)bs * D_ + d + 64];
    float s1 = sn[(size_t)bs * D_ + d + 64];

    size_t base = ((size_t)bs * nh + h) * D_;
    float a  = t[base + d];
    float b2 = t[base + d + 64];
    float r0 = a  * c0 - b2 * s0;
    float r1 = b2 * c1 + a  * s1;

    __nv_bfloat16 h0 = __float2bfloat16(r0);
    __nv_bfloat16 h1 = __float2bfloat16(r1);
    hi[base + d]      = h0;
    hi[base + d + 64] = h1;
    lo[base + d]      = __float2bfloat16(r0 - __bfloat162float(h0));
    lo[base + d + 64] = __float2bfloat16(r1 - __bfloat162float(h1));
}

// ---------------------------------------------------------------------------
// V transpose + split: g_v [B][S][KV][D] fp32 -> g_vt{hi,lo} [B][KV][D][S]
// ---------------------------------------------------------------------------
__global__ void vtrans_kernel(const float* __restrict__ v,
                              __nv_bfloat16* __restrict__ vthi,
                              __nv_bfloat16* __restrict__ vtlo)
{
    __shared__ float ts[32][33];
    const int bkv = blockIdx.z;
    const int b   = bkv >> 2, kv = bkv & 3;
    const int s0  = blockIdx.x * 32, d0 = blockIdx.y * 32;
    const int tx  = threadIdx.x, ty = threadIdx.y;   // 32 x 8

    #pragma unroll
    for (int i = 0; i < 4; i++) {
        int s = s0 + ty + i * 8;
        ts[ty + i * 8][tx] = v[((size_t)(b * S_ + s) * KV_ + kv) * D_ + d0 + tx];
    }
    __syncthreads();
    #pragma unroll
    for (int i = 0; i < 4; i++) {
        int d = d0 + ty + i * 8;
        float val = ts[tx][ty + i * 8];
        __nv_bfloat16 h = __float2bfloat16(val);
        __nv_bfloat16 l = __float2bfloat16(val - __bfloat162float(h));
        size_t idx = ((size_t)bkv * D_ + d) * S_ + s0 + tx;
        vthi[idx] = h;
        vtlo[idx] = l;
    }
}

// ---------------------------------------------------------------------------
// GEMM (NT) via 3x bf16 MMA, 2-stage cp.async double buffer + ldmatrix.
// Block tile 128x128x32, 8 warps (2x4), warp tile 64x32.
// ---------------------------------------------------------------------------
#define SSTRIDE 20
#define G_HALF  (128 * SSTRIDE)          // u32 per (stage, hi/lo) buffer
#define G_STG   (2 * G_HALF)             // u32 per stage (hi+lo)
#define G_HLO_B (G_HALF * 4)             // byte offset hi->lo within stage
#define GEMM_SMEM_BYTES (4 * G_STG * 4)  // 81920 B

__global__ __launch_bounds__(256) void gemm_bf16x3(
    const __nv_bfloat16* __restrict__ Ahi, const __nv_bfloat16* __restrict__ Alo,
    const __nv_bfloat16* __restrict__ Bhi, const __nv_bfloat16* __restrict__ Blo,
    const float* __restrict__ bias, float* __restrict__ C,
    int M, int N, int K)
{
    extern __shared__ uint32_t sm[];
    uint32_t* sA = sm;
    uint32_t* sB = sm + 2 * G_STG;

    const int tid  = threadIdx.x;
    const int lane = tid & 31;
    const int warp = tid >> 5;
    const int wm   = warp & 1;
    const int wn   = warp >> 1;
    const int bm   = blockIdx.y * 128;
    const int bn   = blockIdx.x * 128;

    const int lrow = tid >> 2;
    const int lkc  = tid & 3;

    const uint32_t saB = (uint32_t)__cvta_generic_to_shared(sA);
    const uint32_t sbB = (uint32_t)__cvta_generic_to_shared(sB);

    // ldmatrix lane geometry
    const int a_row = (lane & 7) + ((lane >> 3) & 1) * 8;
    const int a_chk = ((lane >> 4) & 1) * 4;
    const int b_row = (lane & 7) + ((lane >> 4) & 1) * 8;
    const int b_chk = ((lane >> 3) & 1) * 4;

    uint32_t aoff[4], boff[2];
    #pragma unroll
    for (int mf = 0; mf < 4; mf++)
        aoff[mf] = (uint32_t)(((wm * 64 + mf * 16 + a_row) * SSTRIDE + a_chk) * 4);
    #pragma unroll
    for (int p = 0; p < 2; p++)
        boff[p] = (uint32_t)(((wn * 32 + p * 16 + b_row) * SSTRIDE + b_chk) * 4);

    float acc[4][4][4];
    #pragma unroll
    for (int mf = 0; mf < 4; mf++)
        #pragma unroll
        for (int nf = 0; nf < 4; nf++)
            #pragma unroll
            for (int r = 0; r < 4; r++) acc[mf][nf][r] = 0.f;

    const int niter = K / 32;

    auto load_stage = [&](int st, int k0) {
        #pragma unroll
        for (int r = 0; r < 2; r++) {
            int row = lrow + r * 64;
            size_t ga = (size_t)(bm + row) * K + k0 + lkc * 8;
            size_t gb = (size_t)(bn + row) * K + k0 + lkc * 8;
            uint32_t off   = (uint32_t)(row * SSTRIDE + lkc * 4) * 4;
            uint32_t sbase = (uint32_t)(st * G_STG) * 4;
            cp16(saB + sbase + off,             Ahi + ga);
            cp16(saB + sbase + G_HLO_B + off,   Alo + ga);
            cp16(sbB + sbase + off,             Bhi + gb);
            cp16(sbB + sbase + G_HLO_B + off,   Blo + gb);
        }
    };

    load_stage(0, 0);
    CP_COMMIT();
    CP_WAIT0();
    __syncthreads();

    for (int it = 0; it < niter; it++) {
        if (it + 1 < niter) {
            load_stage((it + 1) & 1, (it + 1) * 32);
            CP_COMMIT();
        }

        const uint32_t stgA = saB + (uint32_t)((it & 1) * G_STG) * 4;
        const uint32_t stgB = sbB + (uint32_t)((it & 1) * G_STG) * 4;

        #pragma unroll
        for (int kq = 0; kq < 2; kq++) {
            const uint32_t ko = kq * 32;   // 8 u32 = 32 bytes
            uint32_t ah[4][4], al[4][4], bh[4][2], bl[4][2];

            #pragma unroll
            for (int mf = 0; mf < 4; mf++) {
                ldsm_x4(ah[mf], stgA + aoff[mf] + ko);
                ldsm_x4(al[mf], stgA + G_HLO_B + aoff[mf] + ko);
            }
            #pragma unroll
            for (int p = 0; p < 2; p++) {
                uint32_t r[4];
                ldsm_x4(r, stgB + boff[p] + ko);
                bh[2*p][0] = r[0]; bh[2*p][1] = r[1];
                bh[2*p+1][0] = r[2]; bh[2*p+1][1] = r[3];
                ldsm_x4(r, stgB + G_HLO_B + boff[p] + ko);
                bl[2*p][0] = r[0]; bl[2*p][1] = r[1];
                bl[2*p+1][0] = r[2]; bl[2*p+1][1] = r[3];
            }
            #pragma unroll
            for (int mf = 0; mf < 4; mf++)
                #pragma unroll
                for (int nf = 0; nf < 4; nf++) {
                    mma16816(acc[mf][nf], ah[mf], bh[nf]);
                    mma16816(acc[mf][nf], ah[mf], bl[nf]);
                    mma16816(acc[mf][nf], al[mf], bh[nf]);
                }
        }

        if (it + 1 < niter) CP_WAIT0();
        __syncthreads();
    }

    #pragma unroll
    for (int mf = 0; mf < 4; mf++) {
        int m0 = bm + wm * 64 + mf * 16 + (lane >> 2);
        #pragma unroll
        for (int nf = 0; nf < 4; nf++) {
            int n0 = bn + wn * 32 + nf * 8 + (lane & 3) * 2;
            float b0 = bias ? bias[n0]     : 0.f;
            float b1 = bias ? bias[n0 + 1] : 0.f;
            C[(size_t)m0 * N + n0]           = acc[mf][nf][0] + b0;
            C[(size_t)m0 * N + n0 + 1]       = acc[mf][nf][1] + b1;
            C[(size_t)(m0 + 8) * N + n0]     = acc[mf][nf][2] + b0;
            C[(size_t)(m0 + 8) * N + n0 + 1] = acc[mf][nf][3] + b1;
        }
    }
}

// ---------------------------------------------------------------------------
// MMA flash attention (causal, GQA), bf16x3, ldmatrix + cp.async loads.
// 128 threads = 4 warps, warp tile M=16, BQ=BK=64.
// ---------------------------------------------------------------------------
#define AQS 68
#define AVS 36
#define A_QOFF (64 * AQS)
#define A_VOFF (128 * AVS)
#define QLO_B (A_QOFF * 4)
#define VLO_B (A_VOFF * 4)
#define ATTN_SMEM_BYTES ((2*64*AQS + 2*64*AQS + 2*128*AVS) * 4)  // 106,496

__global__ __launch_bounds__(128) void attn_mma_kernel()
{
    extern __shared__ uint32_t smu[];
    uint32_t* sQ  = smu;                       // [2][64][AQS]
    uint32_t* sK  = sQ + 2 * 64 * AQS;         // [2][64][AQS]
    uint32_t* sVT = sK + 2 * 64 * AQS;         // [2][128][AVS]

    const int tid  = threadIdx.x;
    const int lane = tid & 31;
    const int warp = tid >> 5;
    const int g    = lane >> 2;
    const int t    = lane & 3;
    const int qt   = gridDim.x - 1 - blockIdx.x;
    const int h    = blockIdx.y;
    const int b    = blockIdx.z;
    const int qs   = qt * 64;
    const int kvh  = h >> 2;
    const float scale = 0.08838834764831845f;

    const uint32_t smB   = (uint32_t)__cvta_generic_to_shared(smu);
    const uint32_t sQ_b  = smB;
    const uint32_t sK_b  = smB + 2 * 64 * AQS * 4;
    const uint32_t sVT_b = smB + 4 * 64 * AQS * 4;

    // ldmatrix lane geometry
    const int a_row = (lane & 7) + ((lane >> 3) & 1) * 8;
    const int a_chk = ((lane >> 4) & 1) * 4;
    const int b_row = (lane & 7) + ((lane >> 4) & 1) * 8;
    const int b_chk = ((lane >> 3) & 1) * 4;

    const uint32_t qoff = (uint32_t)(((warp * 16 + a_row) * AQS + a_chk) * 4);
    uint32_t koff[4], voff[8];
    #pragma unroll
    for (int p = 0; p < 4; p++)
        koff[p] = (uint32_t)(((p * 16 + b_row) * AQS + b_chk) * 4);
    #pragma unroll
    for (int p = 0; p < 8; p++)
        voff[p] = (uint32_t)(((p * 16 + b_row) * AVS + b_chk) * 4);

    // Load Q tile (hi/lo) - plain stores, covered by first __syncthreads
    #pragma unroll
    for (int it = 0; it < 8; it++) {
        int idx = tid + it * 128;
        int row = idx >> 4;
        int c4  = idx & 15;
        size_t gq = ((size_t)((b * S_ + qs + row) * H_ + h)) * D_ + c4 * 8;
        *(uint4*)&sQ[row * AQS + c4 * 4]          = *(const uint4*)(g_qhi + gq);
        *(uint4*)&sQ[A_QOFF + row * AQS + c4 * 4] = *(const uint4*)(g_qlo + gq);
    }

    float o[16][4];
    #pragma unroll
    for (int nf = 0; nf < 16; nf++)
        #pragma unroll
        for (int r = 0; r < 4; r++) o[nf][r] = 0.f;
    float mrow[2] = {-1e30f, -1e30f};
    float lrow[2] = {0.f, 0.f};

    for (int kt = 0; kt <= qt; kt++) {
        __syncthreads();   // prior reads done (and Q stores on kt=0)
        const int ks = kt * 64;

        #pragma unroll
        for (int it = 0; it < 8; it++) {
            int idx = tid + it * 128;
            int row = idx >> 4, c4 = idx & 15;
            size_t gk = ((size_t)((b * S_ + ks + row) * KV_ + kvh)) * D_ + c4 * 8;
            uint32_t kd = sK_b + (uint32_t)((row * AQS + c4 * 4) * 4);
            cp16(kd,         g_khi + gk);
            cp16(kd + QLO_B, g_klo + gk);
            int vrow = idx >> 3, vc = idx & 7;
            size_t gv = ((size_t)((b * KV_ + kvh) * D_ + vrow)) * S_ + ks + vc * 8;
            uint32_t vd = sVT_b + (uint32_t)((vrow * AVS + vc * 4) * 4);
            cp16(vd,         g_vthi + gv);
            cp16(vd + VLO_B, g_vtlo + gv);
        }
        CP_COMMIT();
        CP_WAIT0();
        __syncthreads();

        // ---- QK^T ----
        float acc[8][4];
        #pragma unroll
        for (int nf = 0; nf < 8; nf++)
            #pragma unroll
            for (int r = 0; r < 4; r++) acc[nf][r] = 0.f;

        #pragma unroll
        for (int kq = 0; kq < 8; kq++) {
            const uint32_t ko = kq * 32;
            uint32_t ah[4], al[4];
            ldsm_x4(ah, sQ_b + qoff + ko);
            ldsm_x4(al, sQ_b + QLO_B + qoff + ko);
            #pragma unroll
            for (int p = 0; p < 4; p++) {
                uint32_t rh[4], rl[4];
                ldsm_x4(rh, sK_b + koff[p] + ko);
                ldsm_x4(rl, sK_b + QLO_B + koff[p] + ko);
                mma16816(acc[2*p],   ah, rh);
                mma16816(acc[2*p],   ah, rl);
                mma16816(acc[2*p],   al, rh);
                mma16816(acc[2*p+1], ah, rh + 2);
                mma16816(acc[2*p+1], ah, rl + 2);
                mma16816(acc[2*p+1], al, rh + 2);
            }
        }

        // ---- scale + causal mask ----
        if (kt == qt) {
            const int gr = warp * 16 + g;
            #pragma unroll
            for (int nf = 0; nf < 8; nf++) {
                int c0 = nf * 8 + 2 * t;
                acc[nf][0] = (c0     <= gr    ) ? acc[nf][0] * scale : -1e30f;
                acc[nf][1] = (c0 + 1 <= gr    ) ? acc[nf][1] * scale : -1e30f;
                acc[nf][2] = (c0     <= gr + 8) ? acc[nf][2] * scale : -1e30f;
                acc[nf][3] = (c0 + 1 <= gr + 8) ? acc[nf][3] * scale : -1e30f;
            }
        } else {
            #pragma unroll
            for (int nf = 0; nf < 8; nf++)
                #pragma unroll
                for (int r = 0; r < 4; r++) acc[nf][r] *= scale;
        }

        // ---- online softmax ----
        float mx0 = -1e30f, mx1 = -1e30f;
        #pragma unroll
        for (int nf = 0; nf < 8; nf++) {
            mx0 = fmaxf(mx0, fmaxf(acc[nf][0], acc[nf][1]));
            mx1 = fmaxf(mx1, fmaxf(acc[nf][2], acc[nf][3]));
        }
        mx0 = fmaxf(mx0, __shfl_xor_sync(0xffffffffu, mx0, 1));
        mx0 = fmaxf(mx0, __shfl_xor_sync(0xffffffffu, mx0, 2));
        mx1 = fmaxf(mx1, __shfl_xor_sync(0xffffffffu, mx1, 1));
        mx1 = fmaxf(mx1, __shfl_xor_sync(0xffffffffu, mx1, 2));

        float nm0 = fmaxf(mrow[0], mx0), nm1 = fmaxf(mrow[1], mx1);
        float alpha0 = __expf(mrow[0] - nm0), alpha1 = __expf(mrow[1] - nm1);
        mrow[0] = nm0; mrow[1] = nm1;

        float sum0 = 0.f, sum1 = 0.f;
        #pragma unroll
        for (int nf = 0; nf < 8; nf++) {
            acc[nf][0] = __expf(acc[nf][0] - nm0); sum0 += acc[nf][0];
            acc[nf][1] = __expf(acc[nf][1] - nm0); sum0 += acc[nf][1];
            acc[nf][2] = __expf(acc[nf][2] - nm1); sum1 += acc[nf][2];
            acc[nf][3] = __expf(acc[nf][3] - nm1); sum1 += acc[nf][3];
        }
        sum0 += __shfl_xor_sync(0xffffffffu, sum0, 1);
        sum0 += __shfl_xor_sync(0xffffffffu, sum0, 2);
        sum1 += __shfl_xor_sync(0xffffffffu, sum1, 1);
        sum1 += __shfl_xor_sync(0xffffffffu, sum1, 2);
        lrow[0] = lrow[0] * alpha0 + sum0;
        lrow[1] = lrow[1] * alpha1 + sum1;

        #pragma unroll
        for (int nf = 0; nf < 16; nf++) {
            o[nf][0] *= alpha0; o[nf][1] *= alpha0;
            o[nf][2] *= alpha1; o[nf][3] *= alpha1;
        }

        // ---- P @ V (P built in regs from acc) ----
        #pragma unroll
        for (int kq = 0; kq < 4; kq++) {
            uint32_t pah[4], pal[4];
            pack_hilo(acc[2*kq  ][0], acc[2*kq  ][1], pah[0], pal[0]);
            pack_hilo(acc[2*kq  ][2], acc[2*kq  ][3], pah[1], pal[1]);
            pack_hilo(acc[2*kq+1][0], acc[2*kq+1][1], pah[2], pal[2]);
            pack_hilo(acc[2*kq+1][2], acc[2*kq+1][3], pah[3], pal[3]);
            const uint32_t ko = kq * 32;
            #pragma unroll
            for (int p = 0; p < 8; p++) {
                uint32_t rh[4], rl[4];
                ldsm_x4(rh, sVT_b + voff[p] + ko);
                ldsm_x4(rl, sVT_b + VLO_B + voff[p] + ko);
                mma16816(o[2*p],   pah, rh);
                mma16816(o[2*p],   pah, rl);
                mma16816(o[2*p],   pal, rh);
                mma16816(o[2*p+1], pah, rh + 2);
                mma16816(o[2*p+1], pah, rl + 2);
                mma16816(o[2*p+1], pal, rh + 2);
            }
        }
    }

    // ---- epilogue: normalize, write bf16 hi/lo directly ----
    float inv0 = 1.f / lrow[0], inv1 = 1.f / lrow[1];
    size_t base0 = ((size_t)((b * S_ + qs + warp * 16 + g)) * H_ + h) * D_;
    size_t base1 = base0 + (size_t)8 * H_ * D_;
    #pragma unroll
    for (int nf = 0; nf < 16; nf++) {
        int d0 = nf * 8 + 2 * t;
        uint32_t hh, ll;
        pack_hilo(o[nf][0] * inv0, o[nf][1] * inv0, hh, ll);
        *(uint32_t*)&g_aohi[base0 + d0] = hh;
        *(uint32_t*)&g_aolo[base0 + d0] = ll;
        pack_hilo(o[nf][2] * inv1, o[nf][3] * inv1, hh, ll);
        *(uint32_t*)&g_aohi[base1 + d0] = hh;
        *(uint32_t*)&g_aolo[base1 + d0] = ll;
    }
}

// ---------------------------------------------------------------------------
// kernel_launch
// ---------------------------------------------------------------------------
extern "C" void kernel_launch(void* const* d_in, const int* in_sizes, int n_in,
                              void* d_out, int out_size)
{
    const float* x    = (const float*)d_in[0];
    const float* cosp = (const float*)d_in[1];
    const float* sinp = (const float*)d_in[2];
    // d_in[3] = attention_mask (all ones; unused by reference)
    const float* Wq = (const float*)d_in[4];
    const float* bq = (const float*)d_in[5];
    const float* Wk = (const float*)d_in[6];
    const float* bk = (const float*)d_in[7];
    const float* Wv = (const float*)d_in[8];
    const float* bv = (const float*)d_in[9];
    const float* Wo = (const float*)d_in[10];
    float* out = (float*)d_out;

    float *q, *k, *v;
    cudaGetSymbolAddress((void**)&q, g_q);
    cudaGetSymbolAddress((void**)&k, g_k);
    cudaGetSymbolAddress((void**)&v, g_v);

    __nv_bfloat16 *xhi, *xlo, *wqhi, *wqlo, *wkhi, *wklo, *wvhi, *wvlo, *wohi, *wolo;
    __nv_bfloat16 *aohi, *aolo, *qhi, *qlo, *khi, *klo, *vthi, *vtlo;
    cudaGetSymbolAddress((void**)&xhi,  g_xhi);  cudaGetSymbolAddress((void**)&xlo,  g_xlo);
    cudaGetSymbolAddress((void**)&wqhi, g_wqhi); cudaGetSymbolAddress((void**)&wqlo, g_wqlo);
    cudaGetSymbolAddress((void**)&wkhi, g_wkhi); cudaGetSymbolAddress((void**)&wklo, g_wklo);
    cudaGetSymbolAddress((void**)&wvhi, g_wvhi); cudaGetSymbolAddress((void**)&wvlo, g_wvlo);
    cudaGetSymbolAddress((void**)&wohi, g_wohi); cudaGetSymbolAddress((void**)&wolo, g_wolo);
    cudaGetSymbolAddress((void**)&aohi, g_aohi); cudaGetSymbolAddress((void**)&aolo, g_aolo);
    cudaGetSymbolAddress((void**)&qhi,  g_qhi);  cudaGetSymbolAddress((void**)&qlo,  g_qlo);
    cudaGetSymbolAddress((void**)&khi,  g_khi);  cudaGetSymbolAddress((void**)&klo,  g_klo);
    cudaGetSymbolAddress((void**)&vthi, g_vthi); cudaGetSymbolAddress((void**)&vtlo, g_vtlo);

    const int M = B_ * S_;   // 4096

    // hi/lo splits for GEMM operands
    split_kernel<<<(int)(XN  / 4 + 255) / 256, 256>>>(x,  xhi,  xlo,  (int)(XN  / 4));
    split_kernel<<<(int)(WQN / 4 + 255) / 256, 256>>>(Wq, wqhi, wqlo, (int)(WQN / 4));
    split_kernel<<<(int)(WKN / 4 + 255) / 256, 256>>>(Wk, wkhi, wklo, (int)(WKN / 4));
    split_kernel<<<(int)(WKN / 4 + 255) / 256, 256>>>(Wv, wvhi, wvlo, (int)(WKN / 4));
    split_kernel<<<(int)(WON / 4 + 255) / 256, 256>>>(Wo, wohi, wolo, (int)(WON / 4));

    cudaFuncSetAttribute(gemm_bf16x3, cudaFuncAttributeMaxDynamicSharedMemorySize,
                         GEMM_SMEM_BYTES);

    // QKV projections
    gemm_bf16x3<<<dim3((H_ * D_) / 128, M / 128), 256, GEMM_SMEM_BYTES>>>(
        xhi, xlo, wqhi, wqlo, bq, q, M, H_ * D_,  DM_);
    gemm_bf16x3<<<dim3((KV_ * D_) / 128, M / 128), 256, GEMM_SMEM_BYTES>>>(
        xhi, xlo, wkhi, wklo, bk, k, M, KV_ * D_, DM_);
    gemm_bf16x3<<<dim3((KV_ * D_) / 128, M / 128), 256, GEMM_SMEM_BYTES>>>(
        xhi, xlo, wvhi, wvlo, bv, v, M, KV_ * D_, DM_);

    // Fused RoPE + split; V transpose + split
    {
        int tq = B_ * S_ * H_  * 64;
        int tk = B_ * S_ * KV_ * 64;
        rope_split_kernel<<<(tq + 255) / 256, 256>>>(q, cosp, sinp, qhi, qlo, H_,  tq);
        rope_split_kernel<<<(tk + 255) / 256, 256>>>(k, cosp, sinp, khi, klo, KV_, tk);
        vtrans_kernel<<<dim3(S_ / 32, D_ / 32, B_ * KV_), dim3(32, 8)>>>(v, vthi, vtlo);
    }

    // MMA flash attention (writes ao hi/lo directly)
    cudaFuncSetAttribute(attn_mma_kernel, cudaFuncAttributeMaxDynamicSharedMemorySize,
                         ATTN_SMEM_BYTES);
    attn_mma_kernel<<<dim3(S_ / 64, H_, B_), 128, ATTN_SMEM_BYTES>>>();

    // O projection
    gemm_bf16x3<<<dim3(DM_ / 128, M / 128), 256, GEMM_SMEM_BYTES>>>(
        aohi, aolo, wohi, wolo, nullptr, out, M, DM_, DM_);
}

// round 8
// speedup vs baseline: 3.4284x; 1.0577x over previous
#include <cuda_runtime.h>
#include <cuda_bf16.h>
#include <cstdint>

// Problem constants
#define B_  2
#define S_  2048
#define DM_ 2048
#define H_  16
#define KV_ 4
#define D_  128

#define XN  ((size_t)B_ * S_ * DM_)        // 8,388,608
#define QN  ((size_t)B_ * S_ * H_ * D_)    // 8,388,608
#define KN  ((size_t)B_ * S_ * KV_ * D_)   // 2,097,152
#define WQN ((size_t)H_ * D_ * DM_)        // 4,194,304
#define WKN ((size_t)KV_ * D_ * DM_)       // 1,048,576
#define WON ((size_t)DM_ * H_ * D_)        // 4,194,304

// fp32 scratch (pre-RoPE / pre-transpose)
__device__ float g_q [QN];
__device__ float g_k [KN];
__device__ float g_v [KN];

// bf16 hi/lo split scratch
__device__ __nv_bfloat16 g_xhi [XN],  g_xlo [XN];
__device__ __nv_bfloat16 g_wqhi[WQN], g_wqlo[WQN];
__device__ __nv_bfloat16 g_wkhi[WKN], g_wklo[WKN];
__device__ __nv_bfloat16 g_wvhi[WKN], g_wvlo[WKN];
__device__ __nv_bfloat16 g_wohi[WON], g_wolo[WON];
__device__ __nv_bfloat16 g_aohi[QN],  g_aolo[QN];
__device__ __nv_bfloat16 g_qhi [QN],  g_qlo [QN];
__device__ __nv_bfloat16 g_khi [KN],  g_klo [KN];
__device__ __nv_bfloat16 g_vthi[KN],  g_vtlo[KN];   // [B][KV][D][S]

// ---------------------------------------------------------------------------
// helpers
// ---------------------------------------------------------------------------
__device__ __forceinline__ void mma16816(float* c, const uint32_t* a, const uint32_t* b)
{
    asm volatile(
        "mma.sync.aligned.m16n8k16.row.col.f32.bf16.bf16.f32 "
        "{%0,%1,%2,%3}, {%4,%5,%6,%7}, {%8,%9}, {%0,%1,%2,%3};\n"
        : "+f"(c[0]), "+f"(c[1]), "+f"(c[2]), "+f"(c[3])
        : "r"(a[0]), "r"(a[1]), "r"(a[2]), "r"(a[3]),
          "r"(b[0]), "r"(b[1]));
}

__device__ __forceinline__ void ldsm_x4(uint32_t* r, uint32_t addr)
{
    asm volatile("ldmatrix.sync.aligned.m8n8.x4.shared.b16 {%0,%1,%2,%3}, [%4];\n"
                 : "=r"(r[0]), "=r"(r[1]), "=r"(r[2]), "=r"(r[3]) : "r"(addr));
}

__device__ __forceinline__ void cp16(uint32_t smem_byte_addr, const void* gptr)
{
    asm volatile("cp.async.cg.shared.global [%0], [%1], 16;\n"
                 :: "r"(smem_byte_addr), "l"(gptr));
}
#define CP_COMMIT() asm volatile("cp.async.commit_group;\n" ::: "memory")
#define CP_WAIT0()  asm volatile("cp.async.wait_group 0;\n" ::: "memory")
#define CP_WAIT1()  asm volatile("cp.async.wait_group 1;\n" ::: "memory")

__device__ __forceinline__ void pack_hilo(float a, float b, uint32_t& hi, uint32_t& lo)
{
    __nv_bfloat16 h0 = __float2bfloat16(a);
    __nv_bfloat16 h1 = __float2bfloat16(b);
    __nv_bfloat16 l0 = __float2bfloat16(a - __bfloat162float(h0));
    __nv_bfloat16 l1 = __float2bfloat16(b - __bfloat162float(h1));
    hi = ((uint32_t)*(uint16_t*)&h1 << 16) | *(uint16_t*)&h0;
    lo = ((uint32_t)*(uint16_t*)&l1 << 16) | *(uint16_t*)&l0;
}

// ---------------------------------------------------------------------------
// Segmented fp32 -> bf16 hi/lo split: all 5 tensors in one launch.
// ---------------------------------------------------------------------------
struct SplitSegs {
    const float* in[5];
    __nv_bfloat16* hi[5];
    __nv_bfloat16* lo[5];
    int end[5];        // cumulative end, in float4 units
};

__global__ void split_all_kernel(SplitSegs segs)
{
    int idx = blockIdx.x * 256 + threadIdx.x;
    if (idx >= segs.end[4]) return;
    int s = 0;
    if (idx >= segs.end[0]) s = 1;
    if (idx >= segs.end[1]) s = 2;
    if (idx >= segs.end[2]) s = 3;
    if (idx >= segs.end[3]) s = 4;
    int base = s ? segs.end[s - 1] : 0;
    int i = idx - base;

    float4 v = ((const float4*)segs.in[s])[i];
    uint32_t h0, l0, h1, l1;
    pack_hilo(v.x, v.y, h0, l0);
    pack_hilo(v.z, v.w, h1, l1);
    ((uint2*)segs.hi[s])[i] = make_uint2(h0, h1);
    ((uint2*)segs.lo[s])[i] = make_uint2(l0, l1);
}

// ---------------------------------------------------------------------------
// Fused RoPE + hi/lo split
// ---------------------------------------------------------------------------
__global__ void rope_split_kernel(const float* __restrict__ t,
                                  const float* __restrict__ cs,
                                  const float* __restrict__ sn,
                                  __nv_bfloat16* __restrict__ hi,
                                  __nv_bfloat16* __restrict__ lo,
                                  int nh, int total)
{
    int idx = blockIdx.x * 256 + threadIdx.x;
    if (idx >= total) return;
    int d  = idx & 63;
    int h  = (idx >> 6) % nh;
    int bs = idx / (64 * nh);

    float c0 = cs[(size_t)bs * D_ + d];
    float s0 = sn[(size_t)bs * D_ + d];
    float c1 = cs[(size_t)bs * D_ + d + 64];
    float s1 = sn[(size_t)bs * D_ + d + 64];

    size_t base = ((size_t)bs * nh + h) * D_;
    float a  = t[base + d];
    float b2 = t[base + d + 64];
    float r0 = a  * c0 - b2 * s0;
    float r1 = b2 * c1 + a  * s1;

    __nv_bfloat16 h0 = __float2bfloat16(r0);
    __nv_bfloat16 h1 = __float2bfloat16(r1);
    hi[base + d]      = h0;
    hi[base + d + 64] = h1;
    lo[base + d]      = __float2bfloat16(r0 - __bfloat162float(h0));
    lo[base + d + 64] = __float2bfloat16(r1 - __bfloat162float(h1));
}

// ---------------------------------------------------------------------------
// V transpose + split: g_v [B][S][KV][D] fp32 -> g_vt{hi,lo} [B][KV][D][S]
// ---------------------------------------------------------------------------
__global__ void vtrans_kernel(const float* __restrict__ v,
                              __nv_bfloat16* __restrict__ vthi,
                              __nv_bfloat16* __restrict__ vtlo)
{
    __shared__ float ts[32][33];
    const int bkv = blockIdx.z;
    const int b   = bkv >> 2, kv = bkv & 3;
    const int s0  = blockIdx.x * 32, d0 = blockIdx.y * 32;
    const int tx  = threadIdx.x, ty = threadIdx.y;   // 32 x 8

    #pragma unroll
    for (int i = 0; i < 4; i++) {
        int s = s0 + ty + i * 8;
        ts[ty + i * 8][tx] = v[((size_t)(b * S_ + s) * KV_ + kv) * D_ + d0 + tx];
    }
    __syncthreads();
    #pragma unroll
    for (int i = 0; i < 4; i++) {
        int d = d0 + ty + i * 8;
        float val = ts[tx][ty + i * 8];
        __nv_bfloat16 h = __float2bfloat16(val);
        __nv_bfloat16 l = __float2bfloat16(val - __bfloat162float(h));
        size_t idx = ((size_t)bkv * D_ + d) * S_ + s0 + tx;
        vthi[idx] = h;
        vtlo[idx] = l;
    }
}

// ---------------------------------------------------------------------------
// GEMM core (NT) via 3x bf16 MMA, 2-stage cp.async + ldmatrix.
// Block tile 128x128x32, 8 warps (2x4), warp tile 64x32.
// ---------------------------------------------------------------------------
#define SSTRIDE 20
#define G_HALF  (128 * SSTRIDE)
#define G_STG   (2 * G_HALF)
#define G_HLO_B (G_HALF * 4)
#define GEMM_SMEM_BYTES (4 * G_STG * 4)  // 81920 B

__device__ __forceinline__ void gemm_core(
    const __nv_bfloat16* __restrict__ Ahi, const __nv_bfloat16* __restrict__ Alo,
    const __nv_bfloat16* __restrict__ Bhi, const __nv_bfloat16* __restrict__ Blo,
    const float* __restrict__ bias, float* __restrict__ C,
    int N, int K, int bm, int bn)
{
    extern __shared__ uint32_t sm[];
    uint32_t* sA = sm;
    uint32_t* sB = sm + 2 * G_STG;

    const int tid  = threadIdx.x;
    const int lane = tid & 31;
    const int warp = tid >> 5;
    const int wm   = warp & 1;
    const int wn   = warp >> 1;

    const int lrow = tid >> 2;
    const int lkc  = tid & 3;

    const uint32_t saB = (uint32_t)__cvta_generic_to_shared(sA);
    const uint32_t sbB = (uint32_t)__cvta_generic_to_shared(sB);

    const int a_row = (lane & 7) + ((lane >> 3) & 1) * 8;
    const int a_chk = ((lane >> 4) & 1) * 4;
    const int b_row = (lane & 7) + ((lane >> 4) & 1) * 8;
    const int b_chk = ((lane >> 3) & 1) * 4;

    uint32_t aoff[4], boff[2];
    #pragma unroll
    for (int mf = 0; mf < 4; mf++)
        aoff[mf] = (uint32_t)(((wm * 64 + mf * 16 + a_row) * SSTRIDE + a_chk) * 4);
    #pragma unroll
    for (int p = 0; p < 2; p++)
        boff[p] = (uint32_t)(((wn * 32 + p * 16 + b_row) * SSTRIDE + b_chk) * 4);

    float acc[4][4][4];
    #pragma unroll
    for (int mf = 0; mf < 4; mf++)
        #pragma unroll
        for (int nf = 0; nf < 4; nf++)
            #pragma unroll
            for (int r = 0; r < 4; r++) acc[mf][nf][r] = 0.f;

    const int niter = K / 32;

    auto load_stage = [&](int st, int k0) {
        #pragma unroll
        for (int r = 0; r < 2; r++) {
            int row = lrow + r * 64;
            size_t ga = (size_t)(bm + row) * K + k0 + lkc * 8;
            size_t gb = (size_t)(bn + row) * K + k0 + lkc * 8;
            uint32_t off   = (uint32_t)(row * SSTRIDE + lkc * 4) * 4;
            uint32_t sbase = (uint32_t)(st * G_STG) * 4;
            cp16(saB + sbase + off,             Ahi + ga);
            cp16(saB + sbase + G_HLO_B + off,   Alo + ga);
            cp16(sbB + sbase + off,             Bhi + gb);
            cp16(sbB + sbase + G_HLO_B + off,   Blo + gb);
        }
    };

    load_stage(0, 0);
    CP_COMMIT();
    CP_WAIT0();
    __syncthreads();

    for (int it = 0; it < niter; it++) {
        if (it + 1 < niter) {
            load_stage((it + 1) & 1, (it + 1) * 32);
            CP_COMMIT();
        }

        const uint32_t stgA = saB + (uint32_t)((it & 1) * G_STG) * 4;
        const uint32_t stgB = sbB + (uint32_t)((it & 1) * G_STG) * 4;

        #pragma unroll
        for (int kq = 0; kq < 2; kq++) {
            const uint32_t ko = kq * 32;
            uint32_t ah[4][4], al[4][4], bh[4][2], bl[4][2];

            #pragma unroll
            for (int mf = 0; mf < 4; mf++) {
                ldsm_x4(ah[mf], stgA + aoff[mf] + ko);
                ldsm_x4(al[mf], stgA + G_HLO_B + aoff[mf] + ko);
            }
            #pragma unroll
            for (int p = 0; p < 2; p++) {
                uint32_t r[4];
                ldsm_x4(r, stgB + boff[p] + ko);
                bh[2*p][0] = r[0]; bh[2*p][1] = r[1];
                bh[2*p+1][0] = r[2]; bh[2*p+1][1] = r[3];
                ldsm_x4(r, stgB + G_HLO_B + boff[p] + ko);
                bl[2*p][0] = r[0]; bl[2*p][1] = r[1];
                bl[2*p+1][0] = r[2]; bl[2*p+1][1] = r[3];
            }
            #pragma unroll
            for (int mf = 0; mf < 4; mf++)
                #pragma unroll
                for (int nf = 0; nf < 4; nf++) {
                    mma16816(acc[mf][nf], ah[mf], bh[nf]);
                    mma16816(acc[mf][nf], ah[mf], bl[nf]);
                    mma16816(acc[mf][nf], al[mf], bh[nf]);
                }
        }

        if (it + 1 < niter) CP_WAIT0();
        __syncthreads();
    }

    #pragma unroll
    for (int mf = 0; mf < 4; mf++) {
        int m0 = bm + wm * 64 + mf * 16 + (lane >> 2);
        #pragma unroll
        for (int nf = 0; nf < 4; nf++) {
            int n0 = bn + wn * 32 + nf * 8 + (lane & 3) * 2;
            float b0 = bias ? bias[n0]     : 0.f;
            float b1 = bias ? bias[n0 + 1] : 0.f;
            C[(size_t)m0 * N + n0]           = acc[mf][nf][0] + b0;
            C[(size_t)m0 * N + n0 + 1]       = acc[mf][nf][1] + b1;
            C[(size_t)(m0 + 8) * N + n0]     = acc[mf][nf][2] + b0;
            C[(size_t)(m0 + 8) * N + n0 + 1] = acc[mf][nf][3] + b1;
        }
    }
}

// O-projection GEMM (plain)
__global__ __launch_bounds__(256) void gemm_bf16x3(
    const __nv_bfloat16* __restrict__ Ahi, const __nv_bfloat16* __restrict__ Alo,
    const __nv_bfloat16* __restrict__ Bhi, const __nv_bfloat16* __restrict__ Blo,
    const float* __restrict__ bias, float* __restrict__ C, int N, int K)
{
    gemm_core(Ahi, Alo, Bhi, Blo, bias, C, N, K, blockIdx.y * 128, blockIdx.x * 128);
}

// Fused QKV projection: grid.x = 24 column tiles (16 Q, 4 K, 4 V)
__global__ __launch_bounds__(256) void gemm_qkv(
    const __nv_bfloat16* __restrict__ xhi, const __nv_bfloat16* __restrict__ xlo,
    const __nv_bfloat16* __restrict__ wqhi, const __nv_bfloat16* __restrict__ wqlo,
    const __nv_bfloat16* __restrict__ wkhi, const __nv_bfloat16* __restrict__ wklo,
    const __nv_bfloat16* __restrict__ wvhi, const __nv_bfloat16* __restrict__ wvlo,
    const float* __restrict__ bq, const float* __restrict__ bk,
    const float* __restrict__ bv,
    float* __restrict__ q, float* __restrict__ k, float* __restrict__ v)
{
    const int ct = blockIdx.x;
    const __nv_bfloat16 *Bhi, *Blo;
    const float* bias;
    float* C;
    int N, bn;
    if (ct < 16)      { Bhi = wqhi; Blo = wqlo; bias = bq; C = q; N = 2048; bn = ct * 128; }
    else if (ct < 20) { Bhi = wkhi; Blo = wklo; bias = bk; C = k; N = 512;  bn = (ct - 16) * 128; }
    else              { Bhi = wvhi; Blo = wvlo; bias = bv; C = v; N = 512;  bn = (ct - 20) * 128; }
    gemm_core(xhi, xlo, Bhi, Blo, bias, C, N, DM_, blockIdx.y * 128, bn);
}

// ---------------------------------------------------------------------------
// MMA flash attention (causal, GQA), bf16x3, ldmatrix + split-group cp.async:
// K in one commit group, V in another; V load hides behind QK^T + softmax.
// ---------------------------------------------------------------------------
#define AQS 68
#define AVS 36
#define A_QOFF (64 * AQS)
#define A_VOFF (128 * AVS)
#define QLO_B (A_QOFF * 4)
#define VLO_B (A_VOFF * 4)
#define ATTN_SMEM_BYTES ((2*64*AQS + 2*64*AQS + 2*128*AVS) * 4)  // 106,496

__global__ __launch_bounds__(128) void attn_mma_kernel()
{
    extern __shared__ uint32_t smu[];
    uint32_t* sQ  = smu;                       // [2][64][AQS]

    const int tid  = threadIdx.x;
    const int lane = tid & 31;
    const int warp = tid >> 5;
    const int g    = lane >> 2;
    const int t    = lane & 3;
    const int qt   = gridDim.x - 1 - blockIdx.x;
    const int h    = blockIdx.y;
    const int b    = blockIdx.z;
    const int qs   = qt * 64;
    const int kvh  = h >> 2;
    const float scale = 0.08838834764831845f;

    const uint32_t smB   = (uint32_t)__cvta_generic_to_shared(smu);
    const uint32_t sQ_b  = smB;
    const uint32_t sK_b  = smB + 2 * 64 * AQS * 4;
    const uint32_t sVT_b = smB + 4 * 64 * AQS * 4;

    const int a_row = (lane & 7) + ((lane >> 3) & 1) * 8;
    const int a_chk = ((lane >> 4) & 1) * 4;
    const int b_row = (lane & 7) + ((lane >> 4) & 1) * 8;
    const int b_chk = ((lane >> 3) & 1) * 4;

    const uint32_t qoff = (uint32_t)(((warp * 16 + a_row) * AQS + a_chk) * 4);
    uint32_t koff[4], voff[8];
    #pragma unroll
    for (int p = 0; p < 4; p++)
        koff[p] = (uint32_t)(((p * 16 + b_row) * AQS + b_chk) * 4);
    #pragma unroll
    for (int p = 0; p < 8; p++)
        voff[p] = (uint32_t)(((p * 16 + b_row) * AVS + b_chk) * 4);

    // Load Q tile (hi/lo)
    #pragma unroll
    for (int it = 0; it < 8; it++) {
        int idx = tid + it * 128;
        int row = idx >> 4;
        int c4  = idx & 15;
        size_t gq = ((size_t)((b * S_ + qs + row) * H_ + h)) * D_ + c4 * 8;
        *(uint4*)&sQ[row * AQS + c4 * 4]          = *(const uint4*)(g_qhi + gq);
        *(uint4*)&sQ[A_QOFF + row * AQS + c4 * 4] = *(const uint4*)(g_qlo + gq);
    }

    float o[16][4];
    #pragma unroll
    for (int nf = 0; nf < 16; nf++)
        #pragma unroll
        for (int r = 0; r < 4; r++) o[nf][r] = 0.f;
    float mrow[2] = {-1e30f, -1e30f};
    float lrow[2] = {0.f, 0.f};

    for (int kt = 0; kt <= qt; kt++) {
        __syncthreads();   // all reads of smem from prior iter done
        const int ks = kt * 64;

        // group 1: K tile
        #pragma unroll
        for (int it = 0; it < 8; it++) {
            int idx = tid + it * 128;
            int row = idx >> 4, c4 = idx & 15;
            size_t gk = ((size_t)((b * S_ + ks + row) * KV_ + kvh)) * D_ + c4 * 8;
            uint32_t kd = sK_b + (uint32_t)((row * AQS + c4 * 4) * 4);
            cp16(kd,         g_khi + gk);
            cp16(kd + QLO_B, g_klo + gk);
        }
        CP_COMMIT();
        // group 2: V tile (waited on only after QK + softmax)
        #pragma unroll
        for (int it = 0; it < 8; it++) {
            int idx = tid + it * 128;
            int vrow = idx >> 3, vc = idx & 7;
            size_t gv = ((size_t)((b * KV_ + kvh) * D_ + vrow)) * S_ + ks + vc * 8;
            uint32_t vd = sVT_b + (uint32_t)((vrow * AVS + vc * 4) * 4);
            cp16(vd,         g_vthi + gv);
            cp16(vd + VLO_B, g_vtlo + gv);
        }
        CP_COMMIT();

        CP_WAIT1();        // K arrived; V may still be in flight
        __syncthreads();

        // ---- QK^T ----
        float acc[8][4];
        #pragma unroll
        for (int nf = 0; nf < 8; nf++)
            #pragma unroll
            for (int r = 0; r < 4; r++) acc[nf][r] = 0.f;

        #pragma unroll
        for (int kq = 0; kq < 8; kq++) {
            const uint32_t ko = kq * 32;
            uint32_t ah[4], al[4];
            ldsm_x4(ah, sQ_b + qoff + ko);
            ldsm_x4(al, sQ_b + QLO_B + qoff + ko);
            #pragma unroll
            for (int p = 0; p < 4; p++) {
                uint32_t rh[4], rl[4];
                ldsm_x4(rh, sK_b + koff[p] + ko);
                ldsm_x4(rl, sK_b + QLO_B + koff[p] + ko);
                mma16816(acc[2*p],   ah, rh);
                mma16816(acc[2*p],   ah, rl);
                mma16816(acc[2*p],   al, rh);
                mma16816(acc[2*p+1], ah, rh + 2);
                mma16816(acc[2*p+1], ah, rl + 2);
                mma16816(acc[2*p+1], al, rh + 2);
            }
        }

        // ---- scale + causal mask ----
        if (kt == qt) {
            const int gr = warp * 16 + g;
            #pragma unroll
            for (int nf = 0; nf < 8; nf++) {
                int c0 = nf * 8 + 2 * t;
                acc[nf][0] = (c0     <= gr    ) ? acc[nf][0] * scale : -1e30f;
                acc[nf][1] = (c0 + 1 <= gr    ) ? acc[nf][1] * scale : -1e30f;
                acc[nf][2] = (c0     <= gr + 8) ? acc[nf][2] * scale : -1e30f;
                acc[nf][3] = (c0 + 1 <= gr + 8) ? acc[nf][3] * scale : -1e30f;
            }
        } else {
            #pragma unroll
            for (int nf = 0; nf < 8; nf++)
                #pragma unroll
                for (int r = 0; r < 4; r++) acc[nf][r] *= scale;
        }

        // ---- online softmax ----
        float mx0 = -1e30f, mx1 = -1e30f;
        #pragma unroll
        for (int nf = 0; nf < 8; nf++) {
            mx0 = fmaxf(mx0, fmaxf(acc[nf][0], acc[nf][1]));
            mx1 = fmaxf(mx1, fmaxf(acc[nf][2], acc[nf][3]));
        }
        mx0 = fmaxf(mx0, __shfl_xor_sync(0xffffffffu, mx0, 1));
        mx0 = fmaxf(mx0, __shfl_xor_sync(0xffffffffu, mx0, 2));
        mx1 = fmaxf(mx1, __shfl_xor_sync(0xffffffffu, mx1, 1));
        mx1 = fmaxf(mx1, __shfl_xor_sync(0xffffffffu, mx1, 2));

        float nm0 = fmaxf(mrow[0], mx0), nm1 = fmaxf(mrow[1], mx1);
        float alpha0 = __expf(mrow[0] - nm0), alpha1 = __expf(mrow[1] - nm1);
        mrow[0] = nm0; mrow[1] = nm1;

        float sum0 = 0.f, sum1 = 0.f;
        #pragma unroll
        for (int nf = 0; nf < 8; nf++) {
            acc[nf][0] = __expf(acc[nf][0] - nm0); sum0 += acc[nf][0];
            acc[nf][1] = __expf(acc[nf][1] - nm0); sum0 += acc[nf][1];
            acc[nf][2] = __expf(acc[nf][2] - nm1); sum1 += acc[nf][2];
            acc[nf][3] = __expf(acc[nf][3] - nm1); sum1 += acc[nf][3];
        }
        sum0 += __shfl_xor_sync(0xffffffffu, sum0, 1);
        sum0 += __shfl_xor_sync(0xffffffffu, sum0, 2);
        sum1 += __shfl_xor_sync(0xffffffffu, sum1, 1);
        sum1 += __shfl_xor_sync(0xffffffffu, sum1, 2);
        lrow[0] = lrow[0] * alpha0 + sum0;
        lrow[1] = lrow[1] * alpha1 + sum1;

        #pragma unroll
        for (int nf = 0; nf < 16; nf++) {
            o[nf][0] *= alpha0; o[nf][1] *= alpha0;
            o[nf][2] *= alpha1; o[nf][3] *= alpha1;
        }

        CP_WAIT0();        // V arrived
        __syncthreads();

        // ---- P @ V (P built in regs from acc) ----
        #pragma unroll
        for (int kq = 0; kq < 4; kq++) {
            uint32_t pah[4], pal[4];
            pack_hilo(acc[2*kq  ][0], acc[2*kq  ][1], pah[0], pal[0]);
            pack_hilo(acc[2*kq  ][2], acc[2*kq  ][3], pah[1], pal[1]);
            pack_hilo(acc[2*kq+1][0], acc[2*kq+1][1], pah[2], pal[2]);
            pack_hilo(acc[2*kq+1][2], acc[2*kq+1][3], pah[3], pal[3]);
            const uint32_t ko = kq * 32;
            #pragma unroll
            for (int p = 0; p < 8; p++) {
                uint32_t rh[4], rl[4];
                ldsm_x4(rh, sVT_b + voff[p] + ko);
                ldsm_x4(rl, sVT_b + VLO_B + voff[p] + ko);
                mma16816(o[2*p],   pah, rh);
                mma16816(o[2*p],   pah, rl);
                mma16816(o[2*p],   pal, rh);
                mma16816(o[2*p+1], pah, rh + 2);
                mma16816(o[2*p+1], pah, rl + 2);
                mma16816(o[2*p+1], pal, rh + 2);
            }
        }
    }

    // ---- epilogue: normalize, write bf16 hi/lo directly ----
    float inv0 = 1.f / lrow[0], inv1 = 1.f / lrow[1];
    size_t base0 = ((size_t)((b * S_ + qs + warp * 16 + g)) * H_ + h) * D_;
    size_t base1 = base0 + (size_t)8 * H_ * D_;
    #pragma unroll
    for (int nf = 0; nf < 16; nf++) {
        int d0 = nf * 8 + 2 * t;
        uint32_t hh, ll;
        pack_hilo(o[nf][0] * inv0, o[nf][1] * inv0, hh, ll);
        *(uint32_t*)&g_aohi[base0 + d0] = hh;
        *(uint32_t*)&g_aolo[base0 + d0] = ll;
        pack_hilo(o[nf][2] * inv1, o[nf][3] * inv1, hh, ll);
        *(uint32_t*)&g_aohi[base1 + d0] = hh;
        *(uint32_t*)&g_aolo[base1 + d0] = ll;
    }
}

// ---------------------------------------------------------------------------
// kernel_launch
// ---------------------------------------------------------------------------
extern "C" void kernel_launch(void* const* d_in, const int* in_sizes, int n_in,
                              void* d_out, int out_size)
{
    const float* x    = (const float*)d_in[0];
    const float* cosp = (const float*)d_in[1];
    const float* sinp = (const float*)d_in[2];
    // d_in[3] = attention_mask (all ones; unused by reference)
    const float* Wq = (const float*)d_in[4];
    const float* bq = (const float*)d_in[5];
    const float* Wk = (const float*)d_in[6];
    const float* bk = (const float*)d_in[7];
    const float* Wv = (const float*)d_in[8];
    const float* bv = (const float*)d_in[9];
    const float* Wo = (const float*)d_in[10];
    float* out = (float*)d_out;

    float *q, *k, *v;
    cudaGetSymbolAddress((void**)&q, g_q);
    cudaGetSymbolAddress((void**)&k, g_k);
    cudaGetSymbolAddress((void**)&v, g_v);

    __nv_bfloat16 *xhi, *xlo, *wqhi, *wqlo, *wkhi, *wklo, *wvhi, *wvlo, *wohi, *wolo;
    __nv_bfloat16 *aohi, *aolo, *qhi, *qlo, *khi, *klo, *vthi, *vtlo;
    cudaGetSymbolAddress((void**)&xhi,  g_xhi);  cudaGetSymbolAddress((void**)&xlo,  g_xlo);
    cudaGetSymbolAddress((void**)&wqhi, g_wqhi); cudaGetSymbolAddress((void**)&wqlo, g_wqlo);
    cudaGetSymbolAddress((void**)&wkhi, g_wkhi); cudaGetSymbolAddress((void**)&wklo, g_wklo);
    cudaGetSymbolAddress((void**)&wvhi, g_wvhi); cudaGetSymbolAddress((void**)&wvlo, g_wvlo);
    cudaGetSymbolAddress((void**)&wohi, g_wohi); cudaGetSymbolAddress((void**)&wolo, g_wolo);
    cudaGetSymbolAddress((void**)&aohi, g_aohi); cudaGetSymbolAddress((void**)&aolo, g_aolo);
    cudaGetSymbolAddress((void**)&qhi,  g_qhi);  cudaGetSymbolAddress((void**)&qlo,  g_qlo);
    cudaGetSymbolAddress((void**)&khi,  g_khi);  cudaGetSymbolAddress((void**)&klo,  g_klo);
    cudaGetSymbolAddress((void**)&vthi, g_vthi); cudaGetSymbolAddress((void**)&vtlo, g_vtlo);

    const int M = B_ * S_;   // 4096

    // One segmented split launch for x + 4 weights
    {
        SplitSegs s;
        s.in[0] = x;  s.hi[0] = xhi;  s.lo[0] = xlo;
        s.in[1] = Wq; s.hi[1] = wqhi; s.lo[1] = wqlo;
        s.in[2] = Wk; s.hi[2] = wkhi; s.lo[2] = wklo;
        s.in[3] = Wv; s.hi[3] = wvhi; s.lo[3] = wvlo;
        s.in[4] = Wo; s.hi[4] = wohi; s.lo[4] = wolo;
        int c0 = (int)(XN / 4);
        int c1 = c0 + (int)(WQN / 4);
        int c2 = c1 + (int)(WKN / 4);
        int c3 = c2 + (int)(WKN / 4);
        int c4 = c3 + (int)(WON / 4);
        s.end[0] = c0; s.end[1] = c1; s.end[2] = c2; s.end[3] = c3; s.end[4] = c4;
        split_all_kernel<<<(c4 + 255) / 256, 256>>>(s);
    }

    cudaFuncSetAttribute(gemm_qkv,    cudaFuncAttributeMaxDynamicSharedMemorySize, GEMM_SMEM_BYTES);
    cudaFuncSetAttribute(gemm_bf16x3, cudaFuncAttributeMaxDynamicSharedMemorySize, GEMM_SMEM_BYTES);

    // Fused QKV projection (one launch, 24x32 = 768 blocks)
    gemm_qkv<<<dim3(24, M / 128), 256, GEMM_SMEM_BYTES>>>(
        xhi, xlo, wqhi, wqlo, wkhi, wklo, wvhi, wvlo, bq, bk, bv, q, k, v);

    // Fused RoPE + split; V transpose + split
    {
        int tq = B_ * S_ * H_  * 64;
        int tk = B_ * S_ * KV_ * 64;
        rope_split_kernel<<<(tq + 255) / 256, 256>>>(q, cosp, sinp, qhi, qlo, H_,  tq);
        rope_split_kernel<<<(tk + 255) / 256, 256>>>(k, cosp, sinp, khi, klo, KV_, tk);
        vtrans_kernel<<<dim3(S_ / 32, D_ / 32, B_ * KV_), dim3(32, 8)>>>(v, vthi, vtlo);
    }

    // MMA flash attention
    cudaFuncSetAttribute(attn_mma_kernel, cudaFuncAttributeMaxDynamicSharedMemorySize,
                         ATTN_SMEM_BYTES);
    attn_mma_kernel<<<dim3(S_ / 64, H_, B_), 128, ATTN_SMEM_BYTES>>>();

    // O projection (N = DM_, K = DM_ — the R6 bug was passing M here as N)
    gemm_bf16x3<<<dim3(DM_ / 128, M / 128), 256, GEMM_SMEM_BYTES>>>(
        aohi, aolo, wohi, wolo, nullptr, out, DM_, DM_);
}

// round 10
// speedup vs baseline: 4.5170x; 1.3175x over previous
#include <cuda_runtime.h>
#include <cuda_fp16.h>
#include <cstdint>

// Problem constants
#define B_  2
#define S_  2048
#define DM_ 2048
#define H_  16
#define KV_ 4
#define D_  128

#define XN  ((size_t)B_ * S_ * DM_)
#define QN  ((size_t)B_ * S_ * H_ * D_)
#define KN  ((size_t)B_ * S_ * KV_ * D_)
#define WQN ((size_t)H_ * D_ * DM_)
#define WKN ((size_t)KV_ * D_ * DM_)
#define WON ((size_t)DM_ * H_ * D_)

// fp32 scratch (pre-RoPE / pre-transpose)
__device__ float g_q [QN];
__device__ float g_k [KN];
__device__ float g_v [KN];

// fp16 scratch. A-side operands: hi/lo pairs. B-side operands: single fp16.
__device__ __half g_xhi [XN],  g_xlo [XN];
__device__ __half g_wq  [WQN];
__device__ __half g_wk  [WKN];
__device__ __half g_wv  [WKN];
__device__ __half g_wo  [WON];
__device__ __half g_aohi[QN],  g_aolo[QN];
__device__ __half g_qhi [QN],  g_qlo [QN];
__device__ __half g_kh  [KN];
__device__ __half g_vth [KN];               // [B][KV][D][S]

// ---------------------------------------------------------------------------
// helpers
// ---------------------------------------------------------------------------
__device__ __forceinline__ void mma16816(float* c, const uint32_t* a, const uint32_t* b)
{
    asm volatile(
        "mma.sync.aligned.m16n8k16.row.col.f32.f16.f16.f32 "
        "{%0,%1,%2,%3}, {%4,%5,%6,%7}, {%8,%9}, {%0,%1,%2,%3};\n"
        : "+f"(c[0]), "+f"(c[1]), "+f"(c[2]), "+f"(c[3])
        : "r"(a[0]), "r"(a[1]), "r"(a[2]), "r"(a[3]),
          "r"(b[0]), "r"(b[1]));
}

__device__ __forceinline__ void ldsm_x4(uint32_t* r, uint32_t addr)
{
    asm volatile("ldmatrix.sync.aligned.m8n8.x4.shared.b16 {%0,%1,%2,%3}, [%4];\n"
                 : "=r"(r[0]), "=r"(r[1]), "=r"(r[2]), "=r"(r[3]) : "r"(addr));
}

__device__ __forceinline__ void cp16(uint32_t smem_byte_addr, const void* gptr)
{
    asm volatile("cp.async.cg.shared.global [%0], [%1], 16;\n"
                 :: "r"(smem_byte_addr), "l"(gptr));
}
#define CP_COMMIT() asm volatile("cp.async.commit_group;\n" ::: "memory")
#define CP_WAIT0()  asm volatile("cp.async.wait_group 0;\n" ::: "memory")
#define CP_WAIT1()  asm volatile("cp.async.wait_group 1;\n" ::: "memory")

__device__ __forceinline__ uint32_t pack_h2(float a, float b)
{
    __half h0 = __float2half(a), h1 = __float2half(b);
    return ((uint32_t)__half_as_ushort(h1) << 16) | __half_as_ushort(h0);
}

__device__ __forceinline__ void pack_hilo_h(float a, float b, uint32_t& hi, uint32_t& lo)
{
    __half h0 = __float2half(a), h1 = __float2half(b);
    float r0 = a - __half2float(h0), r1 = b - __half2float(h1);
    hi = ((uint32_t)__half_as_ushort(h1) << 16) | __half_as_ushort(h0);
    lo = ((uint32_t)__half_as_ushort(__float2half(r1)) << 16)
       |  __half_as_ushort(__float2half(r0));
}

// ---------------------------------------------------------------------------
// Segmented fp32 -> fp16 split: x gets hi/lo, weights get single (lo == null).
// ---------------------------------------------------------------------------
struct SplitSegs {
    const float* in[5];
    __half* hi[5];
    __half* lo[5];
    int end[5];        // cumulative end, in float4 units
};

__global__ void split_all_kernel(SplitSegs segs)
{
    int idx = blockIdx.x * 256 + threadIdx.x;
    if (idx >= segs.end[4]) return;
    int s = 0;
    if (idx >= segs.end[0]) s = 1;
    if (idx >= segs.end[1]) s = 2;
    if (idx >= segs.end[2]) s = 3;
    if (idx >= segs.end[3]) s = 4;
    int base = s ? segs.end[s - 1] : 0;
    int i = idx - base;

    float4 v = ((const float4*)segs.in[s])[i];
    if (segs.lo[s]) {
        uint32_t h0, l0, h1, l1;
        pack_hilo_h(v.x, v.y, h0, l0);
        pack_hilo_h(v.z, v.w, h1, l1);
        ((uint2*)segs.hi[s])[i] = make_uint2(h0, h1);
        ((uint2*)segs.lo[s])[i] = make_uint2(l0, l1);
    } else {
        ((uint2*)segs.hi[s])[i] = make_uint2(pack_h2(v.x, v.y), pack_h2(v.z, v.w));
    }
}

// ---------------------------------------------------------------------------
// Fused RoPE + fp16 split (hi/lo if lo != null, else single)
// ---------------------------------------------------------------------------
__global__ void rope_split_kernel(const float* __restrict__ t,
                                  const float* __restrict__ cs,
                                  const float* __restrict__ sn,
                                  __half* __restrict__ hi,
                                  __half* __restrict__ lo,
                                  int nh, int total)
{
    int idx = blockIdx.x * 256 + threadIdx.x;
    if (idx >= total) return;
    int d  = idx & 63;
    int h  = (idx >> 6) % nh;
    int bs = idx / (64 * nh);

    float c0 = cs[(size_t)bs * D_ + d];
    float s0 = sn[(size_t)bs * D_ + d];
    float c1 = cs[(size_t)bs * D_ + d + 64];
    float s1 = sn[(size_t)bs * D_ + d + 64];

    size_t base = ((size_t)bs * nh + h) * D_;
    float a  = t[base + d];
    float b2 = t[base + d + 64];
    float r0 = a  * c0 - b2 * s0;
    float r1 = b2 * c1 + a  * s1;

    __half h0 = __float2half(r0);
    __half h1 = __float2half(r1);
    hi[base + d]      = h0;
    hi[base + d + 64] = h1;
    if (lo) {
        lo[base + d]      = __float2half(r0 - __half2float(h0));
        lo[base + d + 64] = __float2half(r1 - __half2float(h1));
    }
}

// ---------------------------------------------------------------------------
// V transpose + fp16: g_v [B][S][KV][D] fp32 -> g_vth [B][KV][D][S]
// ---------------------------------------------------------------------------
__global__ void vtrans_kernel(const float* __restrict__ v,
                              __half* __restrict__ vth)
{
    __shared__ float ts[32][33];
    const int bkv = blockIdx.z;
    const int b   = bkv >> 2, kv = bkv & 3;
    const int s0  = blockIdx.x * 32, d0 = blockIdx.y * 32;
    const int tx  = threadIdx.x, ty = threadIdx.y;   // 32 x 8

    #pragma unroll
    for (int i = 0; i < 4; i++) {
        int s = s0 + ty + i * 8;
        ts[ty + i * 8][tx] = v[((size_t)(b * S_ + s) * KV_ + kv) * D_ + d0 + tx];
    }
    __syncthreads();
    #pragma unroll
    for (int i = 0; i < 4; i++) {
        int d = d0 + ty + i * 8;
        size_t idx = ((size_t)bkv * D_ + d) * S_ + s0 + tx;
        vth[idx] = __float2half(ts[tx][ty + i * 8]);
    }
}

// ---------------------------------------------------------------------------
// GEMM core (NT), fp16 2-term: C = (Ahi+Alo)[M,K] @ B[N,K]^T + bias.
// 2-stage cp.async + ldmatrix. Block 128x128x32, 8 warps, warp tile 64x32.
// smem stage: [Ahi][Alo][B] regions of 128*SSTRIDE u32 each.
// ---------------------------------------------------------------------------
#define SSTRIDE 20
#define G_HALF  (128 * SSTRIDE)          // u32 per region
#define G_STG   (3 * G_HALF)             // u32 per stage
#define G_ALO_B (G_HALF * 4)
#define G_B_B   (2 * G_HALF * 4)
#define GEMM_SMEM_BYTES (2 * G_STG * 4)  // 61440

__device__ __forceinline__ void gemm_core(
    const __half* __restrict__ Ahi, const __half* __restrict__ Alo,
    const __half* __restrict__ Bm,
    const float* __restrict__ bias, float* __restrict__ C,
    int N, int K, int bm, int bn)
{
    extern __shared__ uint32_t sm[];

    const int tid  = threadIdx.x;
    const int lane = tid & 31;
    const int warp = tid >> 5;
    const int wm   = warp & 1;
    const int wn   = warp >> 1;

    const int lrow = tid >> 2;
    const int lkc  = tid & 3;

    const uint32_t smB = (uint32_t)__cvta_generic_to_shared(sm);

    const int a_row = (lane & 7) + ((lane >> 3) & 1) * 8;
    const int a_chk = ((lane >> 4) & 1) * 4;
    const int b_row = (lane & 7) + ((lane >> 4) & 1) * 8;
    const int b_chk = ((lane >> 3) & 1) * 4;

    uint32_t aoff[4], boff[2];
    #pragma unroll
    for (int mf = 0; mf < 4; mf++)
        aoff[mf] = (uint32_t)(((wm * 64 + mf * 16 + a_row) * SSTRIDE + a_chk) * 4);
    #pragma unroll
    for (int p = 0; p < 2; p++)
        boff[p] = (uint32_t)(((wn * 32 + p * 16 + b_row) * SSTRIDE + b_chk) * 4);

    float acc[4][4][4];
    #pragma unroll
    for (int mf = 0; mf < 4; mf++)
        #pragma unroll
        for (int nf = 0; nf < 4; nf++)
            #pragma unroll
            for (int r = 0; r < 4; r++) acc[mf][nf][r] = 0.f;

    const int niter = K / 32;

    auto load_stage = [&](int st, int k0) {
        uint32_t sbase = (uint32_t)(st * G_STG) * 4;
        #pragma unroll
        for (int r = 0; r < 2; r++) {
            int row = lrow + r * 64;
            size_t ga = (size_t)(bm + row) * K + k0 + lkc * 8;
            size_t gb = (size_t)(bn + row) * K + k0 + lkc * 8;
            uint32_t off = (uint32_t)(row * SSTRIDE + lkc * 4) * 4;
            cp16(smB + sbase + off,           Ahi + ga);
            cp16(smB + sbase + G_ALO_B + off, Alo + ga);
            cp16(smB + sbase + G_B_B + off,   Bm  + gb);
        }
    };

    load_stage(0, 0);
    CP_COMMIT();
    CP_WAIT0();
    __syncthreads();

    for (int it = 0; it < niter; it++) {
        if (it + 1 < niter) {
            load_stage((it + 1) & 1, (it + 1) * 32);
            CP_COMMIT();
        }

        const uint32_t stg = smB + (uint32_t)((it & 1) * G_STG) * 4;

        #pragma unroll
        for (int kq = 0; kq < 2; kq++) {
            const uint32_t ko = kq * 32;
            uint32_t ah[4][4], al[4][4], bh[4][2];

            #pragma unroll
            for (int mf = 0; mf < 4; mf++) {
                ldsm_x4(ah[mf], stg + aoff[mf] + ko);
                ldsm_x4(al[mf], stg + G_ALO_B + aoff[mf] + ko);
            }
            #pragma unroll
            for (int p = 0; p < 2; p++) {
                uint32_t r[4];
                ldsm_x4(r, stg + G_B_B + boff[p] + ko);
                bh[2*p][0] = r[0]; bh[2*p][1] = r[1];
                bh[2*p+1][0] = r[2]; bh[2*p+1][1] = r[3];
            }
            #pragma unroll
            for (int mf = 0; mf < 4; mf++)
                #pragma unroll
                for (int nf = 0; nf < 4; nf++) {
                    mma16816(acc[mf][nf], ah[mf], bh[nf]);
                    mma16816(acc[mf][nf], al[mf], bh[nf]);
                }
        }

        if (it + 1 < niter) CP_WAIT0();
        __syncthreads();
    }

    #pragma unroll
    for (int mf = 0; mf < 4; mf++) {
        int m0 = bm + wm * 64 + mf * 16 + (lane >> 2);
        #pragma unroll
        for (int nf = 0; nf < 4; nf++) {
            int n0 = bn + wn * 32 + nf * 8 + (lane & 3) * 2;
            float b0 = bias ? bias[n0]     : 0.f;
            float b1 = bias ? bias[n0 + 1] : 0.f;
            C[(size_t)m0 * N + n0]           = acc[mf][nf][0] + b0;
            C[(size_t)m0 * N + n0 + 1]       = acc[mf][nf][1] + b1;
            C[(size_t)(m0 + 8) * N + n0]     = acc[mf][nf][2] + b0;
            C[(size_t)(m0 + 8) * N + n0 + 1] = acc[mf][nf][3] + b1;
        }
    }
}

// O-projection GEMM
__global__ __launch_bounds__(256) void gemm_o(
    const __half* __restrict__ Ahi, const __half* __restrict__ Alo,
    const __half* __restrict__ Bm, float* __restrict__ C, int N, int K)
{
    gemm_core(Ahi, Alo, Bm, nullptr, C, N, K, blockIdx.y * 128, blockIdx.x * 128);
}

// Fused QKV projection: grid.x = 24 column tiles (16 Q, 4 K, 4 V)
__global__ __launch_bounds__(256) void gemm_qkv(
    const __half* __restrict__ xhi, const __half* __restrict__ xlo,
    const __half* __restrict__ wq, const __half* __restrict__ wk,
    const __half* __restrict__ wv,
    const float* __restrict__ bq, const float* __restrict__ bk,
    const float* __restrict__ bv,
    float* __restrict__ q, float* __restrict__ k, float* __restrict__ v)
{
    const int ct = blockIdx.x;
    const __half* Bm;
    const float* bias;
    float* C;
    int N, bn;
    if (ct < 16)      { Bm = wq; bias = bq; C = q; N = 2048; bn = ct * 128; }
    else if (ct < 20) { Bm = wk; bias = bk; C = k; N = 512;  bn = (ct - 16) * 128; }
    else              { Bm = wv; bias = bv; C = v; N = 512;  bn = (ct - 20) * 128; }
    gemm_core(xhi, xlo, Bm, bias, C, N, DM_, blockIdx.y * 128, bn);
}

// ---------------------------------------------------------------------------
// MMA flash attention (causal, GQA), fp16 2-term.
// Q hi/lo in smem; K, V^T single fp16 (half the load traffic of R7).
// K/V in separate cp.async commit groups: V hides behind QK + softmax.
// ---------------------------------------------------------------------------
#define AQS 68
#define AVS 36
#define A_QOFF (64 * AQS)
#define QLO_B (A_QOFF * 4)
#define ATTN_SMEM_BYTES ((2*64*AQS + 64*AQS + 128*AVS) * 4)  // 70,656

__global__ __launch_bounds__(128) void attn_mma_kernel()
{
    extern __shared__ uint32_t smu[];
    uint32_t* sQ  = smu;                       // [2][64][AQS]

    const int tid  = threadIdx.x;
    const int lane = tid & 31;
    const int warp = tid >> 5;
    const int g    = lane >> 2;
    const int t    = lane & 3;
    const int qt   = gridDim.x - 1 - blockIdx.x;
    const int h    = blockIdx.y;
    const int b    = blockIdx.z;
    const int qs   = qt * 64;
    const int kvh  = h >> 2;
    const float scale = 0.08838834764831845f;

    const uint32_t smB   = (uint32_t)__cvta_generic_to_shared(smu);
    const uint32_t sQ_b  = smB;
    const uint32_t sK_b  = smB + 2 * 64 * AQS * 4;
    const uint32_t sVT_b = sK_b + 64 * AQS * 4;

    const int a_row = (lane & 7) + ((lane >> 3) & 1) * 8;
    const int a_chk = ((lane >> 4) & 1) * 4;
    const int b_row = (lane & 7) + ((lane >> 4) & 1) * 8;
    const int b_chk = ((lane >> 3) & 1) * 4;

    const uint32_t qoff = (uint32_t)(((warp * 16 + a_row) * AQS + a_chk) * 4);
    uint32_t koff[4], voff[8];
    #pragma unroll
    for (int p = 0; p < 4; p++)
        koff[p] = (uint32_t)(((p * 16 + b_row) * AQS + b_chk) * 4);
    #pragma unroll
    for (int p = 0; p < 8; p++)
        voff[p] = (uint32_t)(((p * 16 + b_row) * AVS + b_chk) * 4);

    // Load Q tile (hi/lo) - plain stores, covered by first __syncthreads
    #pragma unroll
    for (int it = 0; it < 8; it++) {
        int idx = tid + it * 128;
        int row = idx >> 4;
        int c4  = idx & 15;
        size_t gq = ((size_t)((b * S_ + qs + row) * H_ + h)) * D_ + c4 * 8;
        *(uint4*)&sQ[row * AQS + c4 * 4]          = *(const uint4*)(g_qhi + gq);
        *(uint4*)&sQ[A_QOFF + row * AQS + c4 * 4] = *(const uint4*)(g_qlo + gq);
    }

    float o[16][4];
    #pragma unroll
    for (int nf = 0; nf < 16; nf++)
        #pragma unroll
        for (int r = 0; r < 4; r++) o[nf][r] = 0.f;
    float mrow[2] = {-1e30f, -1e30f};
    float lrow[2] = {0.f, 0.f};

    for (int kt = 0; kt <= qt; kt++) {
        __syncthreads();
        const int ks = kt * 64;

        // group 1: K tile (single fp16, 16 KB)
        #pragma unroll
        for (int it = 0; it < 8; it++) {
            int idx = tid + it * 128;
            int row = idx >> 4, c4 = idx & 15;
            size_t gk = ((size_t)((b * S_ + ks + row) * KV_ + kvh)) * D_ + c4 * 8;
            cp16(sK_b + (uint32_t)((row * AQS + c4 * 4) * 4), g_kh + gk);
        }
        CP_COMMIT();
        // group 2: V tile (single fp16, 16 KB)
        #pragma unroll
        for (int it = 0; it < 8; it++) {
            int idx = tid + it * 128;
            int vrow = idx >> 3, vc = idx & 7;
            size_t gv = ((size_t)((b * KV_ + kvh) * D_ + vrow)) * S_ + ks + vc * 8;
            cp16(sVT_b + (uint32_t)((vrow * AVS + vc * 4) * 4), g_vth + gv);
        }
        CP_COMMIT();

        CP_WAIT1();        // K arrived; V may still be in flight
        __syncthreads();

        // ---- QK^T (2-term: Qhi*K + Qlo*K) ----
        float acc[8][4];
        #pragma unroll
        for (int nf = 0; nf < 8; nf++)
            #pragma unroll
            for (int r = 0; r < 4; r++) acc[nf][r] = 0.f;

        #pragma unroll
        for (int kq = 0; kq < 8; kq++) {
            const uint32_t ko = kq * 32;
            uint32_t ah[4], al[4];
            ldsm_x4(ah, sQ_b + qoff + ko);
            ldsm_x4(al, sQ_b + QLO_B + qoff + ko);
            #pragma unroll
            for (int p = 0; p < 4; p++) {
                uint32_t rh[4];
                ldsm_x4(rh, sK_b + koff[p] + ko);
                mma16816(acc[2*p],   ah, rh);
                mma16816(acc[2*p],   al, rh);
                mma16816(acc[2*p+1], ah, rh + 2);
                mma16816(acc[2*p+1], al, rh + 2);
            }
        }

        // ---- scale + causal mask ----
        if (kt == qt) {
            const int gr = warp * 16 + g;
            #pragma unroll
            for (int nf = 0; nf < 8; nf++) {
                int c0 = nf * 8 + 2 * t;
                acc[nf][0] = (c0     <= gr    ) ? acc[nf][0] * scale : -1e30f;
                acc[nf][1] = (c0 + 1 <= gr    ) ? acc[nf][1] * scale : -1e30f;
                acc[nf][2] = (c0     <= gr + 8) ? acc[nf][2] * scale : -1e30f;
                acc[nf][3] = (c0 + 1 <= gr + 8) ? acc[nf][3] * scale : -1e30f;
            }
        } else {
            #pragma unroll
            for (int nf = 0; nf < 8; nf++)
                #pragma unroll
                for (int r = 0; r < 4; r++) acc[nf][r] *= scale;
        }

        // ---- online softmax ----
        float mx0 = -1e30f, mx1 = -1e30f;
        #pragma unroll
        for (int nf = 0; nf < 8; nf++) {
            mx0 = fmaxf(mx0, fmaxf(acc[nf][0], acc[nf][1]));
            mx1 = fmaxf(mx1, fmaxf(acc[nf][2], acc[nf][3]));
        }
        mx0 = fmaxf(mx0, __shfl_xor_sync(0xffffffffu, mx0, 1));
        mx0 = fmaxf(mx0, __shfl_xor_sync(0xffffffffu, mx0, 2));
        mx1 = fmaxf(mx1, __shfl_xor_sync(0xffffffffu, mx1, 1));
        mx1 = fmaxf(mx1, __shfl_xor_sync(0xffffffffu, mx1, 2));

        float nm0 = fmaxf(mrow[0], mx0), nm1 = fmaxf(mrow[1], mx1);
        float alpha0 = __expf(mrow[0] - nm0), alpha1 = __expf(mrow[1] - nm1);
        mrow[0] = nm0; mrow[1] = nm1;

        float sum0 = 0.f, sum1 = 0.f;
        #pragma unroll
        for (int nf = 0; nf < 8; nf++) {
            acc[nf][0] = __expf(acc[nf][0] - nm0); sum0 += acc[nf][0];
            acc[nf][1] = __expf(acc[nf][1] - nm0); sum0 += acc[nf][1];
            acc[nf][2] = __expf(acc[nf][2] - nm1); sum1 += acc[nf][2];
            acc[nf][3] = __expf(acc[nf][3] - nm1); sum1 += acc[nf][3];
        }
        sum0 += __shfl_xor_sync(0xffffffffu, sum0, 1);
        sum0 += __shfl_xor_sync(0xffffffffu, sum0, 2);
        sum1 += __shfl_xor_sync(0xffffffffu, sum1, 1);
        sum1 += __shfl_xor_sync(0xffffffffu, sum1, 2);
        lrow[0] = lrow[0] * alpha0 + sum0;
        lrow[1] = lrow[1] * alpha1 + sum1;

        #pragma unroll
        for (int nf = 0; nf < 16; nf++) {
            o[nf][0] *= alpha0; o[nf][1] *= alpha0;
            o[nf][2] *= alpha1; o[nf][3] *= alpha1;
        }

        CP_WAIT0();        // V arrived
        __syncthreads();

        // ---- P @ V (P split hi/lo in regs; V single) ----
        #pragma unroll
        for (int kq = 0; kq < 4; kq++) {
            uint32_t pah[4], pal[4];
            pack_hilo_h(acc[2*kq  ][0], acc[2*kq  ][1], pah[0], pal[0]);
            pack_hilo_h(acc[2*kq  ][2], acc[2*kq  ][3], pah[1], pal[1]);
            pack_hilo_h(acc[2*kq+1][0], acc[2*kq+1][1], pah[2], pal[2]);
            pack_hilo_h(acc[2*kq+1][2], acc[2*kq+1][3], pah[3], pal[3]);
            const uint32_t ko = kq * 32;
            #pragma unroll
            for (int p = 0; p < 8; p++) {
                uint32_t rh[4];
                ldsm_x4(rh, sVT_b + voff[p] + ko);
                mma16816(o[2*p],   pah, rh);
                mma16816(o[2*p],   pal, rh);
                mma16816(o[2*p+1], pah, rh + 2);
                mma16816(o[2*p+1], pal, rh + 2);
            }
        }
    }

    // ---- epilogue: normalize, write ao hi/lo fp16 ----
    float inv0 = 1.f / lrow[0], inv1 = 1.f / lrow[1];
    size_t base0 = ((size_t)((b * S_ + qs + warp * 16 + g)) * H_ + h) * D_;
    size_t base1 = base0 + (size_t)8 * H_ * D_;
    #pragma unroll
    for (int nf = 0; nf < 16; nf++) {
        int d0 = nf * 8 + 2 * t;
        uint32_t hh, ll;
        pack_hilo_h(o[nf][0] * inv0, o[nf][1] * inv0, hh, ll);
        *(uint32_t*)&g_aohi[base0 + d0] = hh;
        *(uint32_t*)&g_aolo[base0 + d0] = ll;
        pack_hilo_h(o[nf][2] * inv1, o[nf][3] * inv1, hh, ll);
        *(uint32_t*)&g_aohi[base1 + d0] = hh;
        *(uint32_t*)&g_aolo[base1 + d0] = ll;
    }
}

// ---------------------------------------------------------------------------
// kernel_launch
// ---------------------------------------------------------------------------
extern "C" void kernel_launch(void* const* d_in, const int* in_sizes, int n_in,
                              void* d_out, int out_size)
{
    const float* x    = (const float*)d_in[0];
    const float* cosp = (const float*)d_in[1];
    const float* sinp = (const float*)d_in[2];
    // d_in[3] = attention_mask (all ones; unused by reference)
    const float* Wq = (const float*)d_in[4];
    const float* bq = (const float*)d_in[5];
    const float* Wk = (const float*)d_in[6];
    const float* bk = (const float*)d_in[7];
    const float* Wv = (const float*)d_in[8];
    const float* bv = (const float*)d_in[9];
    const float* Wo = (const float*)d_in[10];
    float* out = (float*)d_out;

    float *q, *k, *v;
    cudaGetSymbolAddress((void**)&q, g_q);
    cudaGetSymbolAddress((void**)&k, g_k);
    cudaGetSymbolAddress((void**)&v, g_v);

    __half *xhi, *xlo, *wq, *wk, *wv, *wo, *aohi, *aolo, *qhi, *qlo, *kh, *vth;
    cudaGetSymbolAddress((void**)&xhi,  g_xhi);  cudaGetSymbolAddress((void**)&xlo,  g_xlo);
    cudaGetSymbolAddress((void**)&wq,   g_wq);
    cudaGetSymbolAddress((void**)&wk,   g_wk);
    cudaGetSymbolAddress((void**)&wv,   g_wv);
    cudaGetSymbolAddress((void**)&wo,   g_wo);
    cudaGetSymbolAddress((void**)&aohi, g_aohi); cudaGetSymbolAddress((void**)&aolo, g_aolo);
    cudaGetSymbolAddress((void**)&qhi,  g_qhi);  cudaGetSymbolAddress((void**)&qlo,  g_qlo);
    cudaGetSymbolAddress((void**)&kh,   g_kh);
    cudaGetSymbolAddress((void**)&vth,  g_vth);

    const int M = B_ * S_;   // 4096

    // One segmented split launch: x -> hi/lo, weights -> single fp16
    {
        SplitSegs s;
        s.in[0] = x;  s.hi[0] = xhi; s.lo[0] = xlo;
        s.in[1] = Wq; s.hi[1] = wq;  s.lo[1] = nullptr;
        s.in[2] = Wk; s.hi[2] = wk;  s.lo[2] = nullptr;
        s.in[3] = Wv; s.hi[3] = wv;  s.lo[3] = nullptr;
        s.in[4] = Wo; s.hi[4] = wo;  s.lo[4] = nullptr;
        int c0 = (int)(XN / 4);
        int c1 = c0 + (int)(WQN / 4);
        int c2 = c1 + (int)(WKN / 4);
        int c3 = c2 + (int)(WKN / 4);
        int c4 = c3 + (int)(WON / 4);
        s.end[0] = c0; s.end[1] = c1; s.end[2] = c2; s.end[3] = c3; s.end[4] = c4;
        split_all_kernel<<<(c4 + 255) / 256, 256>>>(s);
    }

    cudaFuncSetAttribute(gemm_qkv, cudaFuncAttributeMaxDynamicSharedMemorySize, GEMM_SMEM_BYTES);
    cudaFuncSetAttribute(gemm_o,   cudaFuncAttributeMaxDynamicSharedMemorySize, GEMM_SMEM_BYTES);

    // Fused QKV projection (one launch, 24x32 = 768 blocks)
    gemm_qkv<<<dim3(24, M / 128), 256, GEMM_SMEM_BYTES>>>(
        xhi, xlo, wq, wk, wv, bq, bk, bv, q, k, v);

    // Fused RoPE + split (q hi/lo, k single); V transpose (single)
    {
        int tq = B_ * S_ * H_  * 64;
        int tk = B_ * S_ * KV_ * 64;
        rope_split_kernel<<<(tq + 255) / 256, 256>>>(q, cosp, sinp, qhi, qlo, H_,  tq);
        rope_split_kernel<<<(tk + 255) / 256, 256>>>(k, cosp, sinp, kh, nullptr, KV_, tk);
        vtrans_kernel<<<dim3(S_ / 32, D_ / 32, B_ * KV_), dim3(32, 8)>>>(v, vth);
    }

    // MMA flash attention
    cudaFuncSetAttribute(attn_mma_kernel, cudaFuncAttributeMaxDynamicSharedMemorySize,
                         ATTN_SMEM_BYTES);
    attn_mma_kernel<<<dim3(S_ / 64, H_, B_), 128, ATTN_SMEM_BYTES>>>();

    // O projection
    gemm_o<<<dim3(DM_ / 128, M / 128), 256, GEMM_SMEM_BYTES>>>(
        aohi, aolo, wo, out, DM_, DM_);
}

// round 11
// speedup vs baseline: 4.7632x; 1.0545x over previous
#include <cuda_runtime.h>
#include <cuda_fp16.h>
#include <cstdint>

// Problem constants
#define B_  2
#define S_  2048
#define DM_ 2048
#define H_  16
#define KV_ 4
#define D_  128

#define XN  ((size_t)B_ * S_ * DM_)
#define QN  ((size_t)B_ * S_ * H_ * D_)
#define KN  ((size_t)B_ * S_ * KV_ * D_)
#define WQN ((size_t)H_ * D_ * DM_)
#define WKN ((size_t)KV_ * D_ * DM_)
#define WON ((size_t)DM_ * H_ * D_)

// fp32 scratch (pre-RoPE / pre-transpose)
__device__ float g_q [QN];
__device__ float g_k [KN];
__device__ float g_v [KN];

// fp16 scratch. A-side operands: hi/lo pairs. B-side operands: single fp16.
__device__ __half g_xhi [XN],  g_xlo [XN];
__device__ __half g_wq  [WQN];
__device__ __half g_wk  [WKN];
__device__ __half g_wv  [WKN];
__device__ __half g_wo  [WON];
__device__ __half g_aohi[QN],  g_aolo[QN];
__device__ __half g_qhi [QN],  g_qlo [QN];
__device__ __half g_kh  [KN];
__device__ __half g_vth [KN];               // [B][KV][D][S]

// ---------------------------------------------------------------------------
// helpers
// ---------------------------------------------------------------------------
__device__ __forceinline__ void mma16816(float* c, const uint32_t* a, const uint32_t* b)
{
    asm volatile(
        "mma.sync.aligned.m16n8k16.row.col.f32.f16.f16.f32 "
        "{%0,%1,%2,%3}, {%4,%5,%6,%7}, {%8,%9}, {%0,%1,%2,%3};\n"
        : "+f"(c[0]), "+f"(c[1]), "+f"(c[2]), "+f"(c[3])
        : "r"(a[0]), "r"(a[1]), "r"(a[2]), "r"(a[3]),
          "r"(b[0]), "r"(b[1]));
}

__device__ __forceinline__ void ldsm_x4(uint32_t* r, uint32_t addr)
{
    asm volatile("ldmatrix.sync.aligned.m8n8.x4.shared.b16 {%0,%1,%2,%3}, [%4];\n"
                 : "=r"(r[0]), "=r"(r[1]), "=r"(r[2]), "=r"(r[3]) : "r"(addr));
}

__device__ __forceinline__ void cp16(uint32_t smem_byte_addr, const void* gptr)
{
    asm volatile("cp.async.cg.shared.global [%0], [%1], 16;\n"
                 :: "r"(smem_byte_addr), "l"(gptr));
}
#define CP_COMMIT() asm volatile("cp.async.commit_group;\n" ::: "memory")
template <int N> __device__ __forceinline__ void cp_wait()
{
    asm volatile("cp.async.wait_group %0;\n" :: "n"(N) : "memory");
}

__device__ __forceinline__ uint32_t pack_h2(float a, float b)
{
    __half h0 = __float2half(a), h1 = __float2half(b);
    return ((uint32_t)__half_as_ushort(h1) << 16) | __half_as_ushort(h0);
}

__device__ __forceinline__ void pack_hilo_h(float a, float b, uint32_t& hi, uint32_t& lo)
{
    __half h0 = __float2half(a), h1 = __float2half(b);
    float r0 = a - __half2float(h0), r1 = b - __half2float(h1);
    hi = ((uint32_t)__half_as_ushort(h1) << 16) | __half_as_ushort(h0);
    lo = ((uint32_t)__half_as_ushort(__float2half(r1)) << 16)
       |  __half_as_ushort(__float2half(r0));
}

// ---------------------------------------------------------------------------
// Segmented fp32 -> fp16 split: x gets hi/lo, weights single. 2x ILP/thread.
// ---------------------------------------------------------------------------
struct SplitSegs {
    const float* in[5];
    __half* hi[5];
    __half* lo[5];
    int end[5];        // cumulative end, in float4 units
};

__global__ void split_all_kernel(SplitSegs segs)
{
    int base = blockIdx.x * 512 + threadIdx.x;
    #pragma unroll
    for (int u = 0; u < 2; u++) {
        int idx = base + u * 256;
        if (idx >= segs.end[4]) continue;
        int s = 0;
        if (idx >= segs.end[0]) s = 1;
        if (idx >= segs.end[1]) s = 2;
        if (idx >= segs.end[2]) s = 3;
        if (idx >= segs.end[3]) s = 4;
        int sb = s ? segs.end[s - 1] : 0;
        int i = idx - sb;

        float4 v = ((const float4*)segs.in[s])[i];
        if (segs.lo[s]) {
            uint32_t h0, l0, h1, l1;
            pack_hilo_h(v.x, v.y, h0, l0);
            pack_hilo_h(v.z, v.w, h1, l1);
            ((uint2*)segs.hi[s])[i] = make_uint2(h0, h1);
            ((uint2*)segs.lo[s])[i] = make_uint2(l0, l1);
        } else {
            ((uint2*)segs.hi[s])[i] = make_uint2(pack_h2(v.x, v.y), pack_h2(v.z, v.w));
        }
    }
}

// ---------------------------------------------------------------------------
// Fused RoPE + fp16 split (hi/lo if lo != null, else single)
// ---------------------------------------------------------------------------
__global__ void rope_split_kernel(const float* __restrict__ t,
                                  const float* __restrict__ cs,
                                  const float* __restrict__ sn,
                                  __half* __restrict__ hi,
                                  __half* __restrict__ lo,
                                  int nh, int total)
{
    int idx = blockIdx.x * 256 + threadIdx.x;
    if (idx >= total) return;
    int d  = idx & 63;
    int h  = (idx >> 6) % nh;
    int bs = idx / (64 * nh);

    float c0 = cs[(size_t)bs * D_ + d];
    float s0 = sn[(size_t)bs * D_ + d];
    float c1 = cs[(size_t)bs * D_ + d + 64];
    float s1 = sn[(size_t)bs * D_ + d + 64];

    size_t base = ((size_t)bs * nh + h) * D_;
    float a  = t[base + d];
    float b2 = t[base + d + 64];
    float r0 = a  * c0 - b2 * s0;
    float r1 = b2 * c1 + a  * s1;

    __half h0 = __float2half(r0);
    __half h1 = __float2half(r1);
    hi[base + d]      = h0;
    hi[base + d + 64] = h1;
    if (lo) {
        lo[base + d]      = __float2half(r0 - __half2float(h0));
        lo[base + d + 64] = __float2half(r1 - __half2float(h1));
    }
}

// ---------------------------------------------------------------------------
// V transpose + fp16: g_v [B][S][KV][D] fp32 -> g_vth [B][KV][D][S]
// ---------------------------------------------------------------------------
__global__ void vtrans_kernel(const float* __restrict__ v,
                              __half* __restrict__ vth)
{
    __shared__ float ts[32][33];
    const int bkv = blockIdx.z;
    const int b   = bkv >> 2, kv = bkv & 3;
    const int s0  = blockIdx.x * 32, d0 = blockIdx.y * 32;
    const int tx  = threadIdx.x, ty = threadIdx.y;   // 32 x 8

    #pragma unroll
    for (int i = 0; i < 4; i++) {
        int s = s0 + ty + i * 8;
        ts[ty + i * 8][tx] = v[((size_t)(b * S_ + s) * KV_ + kv) * D_ + d0 + tx];
    }
    __syncthreads();
    #pragma unroll
    for (int i = 0; i < 4; i++) {
        int d = d0 + ty + i * 8;
        size_t idx = ((size_t)bkv * D_ + d) * S_ + s0 + tx;
        vth[idx] = __float2half(ts[tx][ty + i * 8]);
    }
}

// ---------------------------------------------------------------------------
// GEMM core (NT), fp16 2-term, 3-stage cp.async ring + ldmatrix.
// Block 128x128x32, 8 warps, warp tile 64x32.
// smem stage: [Ahi][Alo][B] regions of 128*SSTRIDE u32 each, x3 stages.
// ---------------------------------------------------------------------------
#define SSTRIDE 20
#define G_HALF  (128 * SSTRIDE)          // u32 per region
#define G_STG   (3 * G_HALF)             // u32 per stage
#define G_ALO_B (G_HALF * 4)
#define G_B_B   (2 * G_HALF * 4)
#define GEMM_SMEM_BYTES (3 * G_STG * 4)  // 92160

__device__ __forceinline__ void gemm_core(
    const __half* __restrict__ Ahi, const __half* __restrict__ Alo,
    const __half* __restrict__ Bm,
    const float* __restrict__ bias, float* __restrict__ C,
    int N, int K, int bm, int bn)
{
    extern __shared__ uint32_t sm[];

    const int tid  = threadIdx.x;
    const int lane = tid & 31;
    const int warp = tid >> 5;
    const int wm   = warp & 1;
    const int wn   = warp >> 1;

    const int lrow = tid >> 2;
    const int lkc  = tid & 3;

    const uint32_t smB = (uint32_t)__cvta_generic_to_shared(sm);

    const int a_row = (lane & 7) + ((lane >> 3) & 1) * 8;
    const int a_chk = ((lane >> 4) & 1) * 4;
    const int b_row = (lane & 7) + ((lane >> 4) & 1) * 8;
    const int b_chk = ((lane >> 3) & 1) * 4;

    uint32_t aoff[4], boff[2];
    #pragma unroll
    for (int mf = 0; mf < 4; mf++)
        aoff[mf] = (uint32_t)(((wm * 64 + mf * 16 + a_row) * SSTRIDE + a_chk) * 4);
    #pragma unroll
    for (int p = 0; p < 2; p++)
        boff[p] = (uint32_t)(((wn * 32 + p * 16 + b_row) * SSTRIDE + b_chk) * 4);

    float acc[4][4][4];
    #pragma unroll
    for (int mf = 0; mf < 4; mf++)
        #pragma unroll
        for (int nf = 0; nf < 4; nf++)
            #pragma unroll
            for (int r = 0; r < 4; r++) acc[mf][nf][r] = 0.f;

    const int niter = K / 32;   // >= 2 always here (K = 2048)

    auto load_stage = [&](int st, int k0) {
        uint32_t sbase = (uint32_t)(st * G_STG) * 4;
        #pragma unroll
        for (int r = 0; r < 2; r++) {
            int row = lrow + r * 64;
            size_t ga = (size_t)(bm + row) * K + k0 + lkc * 8;
            size_t gb = (size_t)(bn + row) * K + k0 + lkc * 8;
            uint32_t off = (uint32_t)(row * SSTRIDE + lkc * 4) * 4;
            cp16(smB + sbase + off,           Ahi + ga);
            cp16(smB + sbase + G_ALO_B + off, Alo + ga);
            cp16(smB + sbase + G_B_B + off,   Bm  + gb);
        }
    };

    load_stage(0, 0);
    CP_COMMIT();
    load_stage(1, 32);
    CP_COMMIT();

    for (int it = 0; it < niter; it++) {
        if (it < niter - 1) cp_wait<1>(); else cp_wait<0>();
        __syncthreads();
        if (it + 2 < niter) {
            load_stage((it + 2) % 3, (it + 2) * 32);
            CP_COMMIT();
        }

        const uint32_t stg = smB + (uint32_t)((it % 3) * G_STG) * 4;

        #pragma unroll
        for (int kq = 0; kq < 2; kq++) {
            const uint32_t ko = kq * 32;
            uint32_t ah[4][4], al[4][4], bh[4][2];

            #pragma unroll
            for (int mf = 0; mf < 4; mf++) {
                ldsm_x4(ah[mf], stg + aoff[mf] + ko);
                ldsm_x4(al[mf], stg + G_ALO_B + aoff[mf] + ko);
            }
            #pragma unroll
            for (int p = 0; p < 2; p++) {
                uint32_t r[4];
                ldsm_x4(r, stg + G_B_B + boff[p] + ko);
                bh[2*p][0] = r[0]; bh[2*p][1] = r[1];
                bh[2*p+1][0] = r[2]; bh[2*p+1][1] = r[3];
            }
            #pragma unroll
            for (int mf = 0; mf < 4; mf++)
                #pragma unroll
                for (int nf = 0; nf < 4; nf++) {
                    mma16816(acc[mf][nf], ah[mf], bh[nf]);
                    mma16816(acc[mf][nf], al[mf], bh[nf]);
                }
        }
    }
    __syncthreads();

    #pragma unroll
    for (int mf = 0; mf < 4; mf++) {
        int m0 = bm + wm * 64 + mf * 16 + (lane >> 2);
        #pragma unroll
        for (int nf = 0; nf < 4; nf++) {
            int n0 = bn + wn * 32 + nf * 8 + (lane & 3) * 2;
            float b0 = bias ? bias[n0]     : 0.f;
            float b1 = bias ? bias[n0 + 1] : 0.f;
            C[(size_t)m0 * N + n0]           = acc[mf][nf][0] + b0;
            C[(size_t)m0 * N + n0 + 1]       = acc[mf][nf][1] + b1;
            C[(size_t)(m0 + 8) * N + n0]     = acc[mf][nf][2] + b0;
            C[(size_t)(m0 + 8) * N + n0 + 1] = acc[mf][nf][3] + b1;
        }
    }
}

// O-projection GEMM
__global__ __launch_bounds__(256) void gemm_o(
    const __half* __restrict__ Ahi, const __half* __restrict__ Alo,
    const __half* __restrict__ Bm, float* __restrict__ C, int N, int K)
{
    gemm_core(Ahi, Alo, Bm, nullptr, C, N, K, blockIdx.y * 128, blockIdx.x * 128);
}

// Fused QKV projection: grid.x = 24 column tiles (16 Q, 4 K, 4 V)
__global__ __launch_bounds__(256) void gemm_qkv(
    const __half* __restrict__ xhi, const __half* __restrict__ xlo,
    const __half* __restrict__ wq, const __half* __restrict__ wk,
    const __half* __restrict__ wv,
    const float* __restrict__ bq, const float* __restrict__ bk,
    const float* __restrict__ bv,
    float* __restrict__ q, float* __restrict__ k, float* __restrict__ v)
{
    const int ct = blockIdx.x;
    const __half* Bm;
    const float* bias;
    float* C;
    int N, bn;
    if (ct < 16)      { Bm = wq; bias = bq; C = q; N = 2048; bn = ct * 128; }
    else if (ct < 20) { Bm = wk; bias = bk; C = k; N = 512;  bn = (ct - 16) * 128; }
    else              { Bm = wv; bias = bv; C = v; N = 512;  bn = (ct - 20) * 128; }
    gemm_core(xhi, xlo, Bm, bias, C, N, DM_, blockIdx.y * 128, bn);
}

// ---------------------------------------------------------------------------
// MMA flash attention (causal, GQA), fp16 2-term, DOUBLE-BUFFERED K/V:
// tile kt+1's K/V cp.async issued while computing tile kt.
// Wait-group counting: mid-loop pending {V(kt),K(kt+1),V(kt+1)} after K(kt)
// completes -> wait<3>; after V(kt) -> wait<2>; last tile -> wait<1>/<0>.
// ---------------------------------------------------------------------------
#define AQS 68
#define AVS 36
#define A_QOFF (64 * AQS)
#define QLO_B (A_QOFF * 4)
#define KSTG_B (64 * AQS * 4)            // one K stage, bytes
#define VSTG_B (128 * AVS * 4)           // one V stage, bytes
#define ATTN_SMEM_BYTES ((2*64*AQS + 2*64*AQS + 2*128*AVS) * 4)  // 106,496

__global__ __launch_bounds__(128) void attn_mma_kernel()
{
    extern __shared__ uint32_t smu[];
    uint32_t* sQ  = smu;                       // [2][64][AQS] hi/lo

    const int tid  = threadIdx.x;
    const int lane = tid & 31;
    const int warp = tid >> 5;
    const int g    = lane >> 2;
    const int t    = lane & 3;
    const int qt   = gridDim.x - 1 - blockIdx.x;
    const int h    = blockIdx.y;
    const int b    = blockIdx.z;
    const int qs   = qt * 64;
    const int kvh  = h >> 2;
    const float scale = 0.08838834764831845f;

    const uint32_t smB   = (uint32_t)__cvta_generic_to_shared(smu);
    const uint32_t sQ_b  = smB;
    const uint32_t sK_b  = smB + 2 * 64 * AQS * 4;       // 2 stages follow
    const uint32_t sVT_b = sK_b + 2 * KSTG_B;            // 2 stages

    const int a_row = (lane & 7) + ((lane >> 3) & 1) * 8;
    const int a_chk = ((lane >> 4) & 1) * 4;
    const int b_row = (lane & 7) + ((lane >> 4) & 1) * 8;
    const int b_chk = ((lane >> 3) & 1) * 4;

    const uint32_t qoff = (uint32_t)(((warp * 16 + a_row) * AQS + a_chk) * 4);
    uint32_t koff[4], voff[8];
    #pragma unroll
    for (int p = 0; p < 4; p++)
        koff[p] = (uint32_t)(((p * 16 + b_row) * AQS + b_chk) * 4);
    #pragma unroll
    for (int p = 0; p < 8; p++)
        voff[p] = (uint32_t)(((p * 16 + b_row) * AVS + b_chk) * 4);

    auto load_k = [&](int kt_, int st) {
        const int ks = kt_ * 64;
        uint32_t kb = sK_b + st * KSTG_B;
        #pragma unroll
        for (int it = 0; it < 8; it++) {
            int idx = tid + it * 128;
            int row = idx >> 4, c4 = idx & 15;
            size_t gk = ((size_t)((b * S_ + ks + row) * KV_ + kvh)) * D_ + c4 * 8;
            cp16(kb + (uint32_t)((row * AQS + c4 * 4) * 4), g_kh + gk);
        }
    };
    auto load_v = [&](int kt_, int st) {
        const int ks = kt_ * 64;
        uint32_t vb = sVT_b + st * VSTG_B;
        #pragma unroll
        for (int it = 0; it < 8; it++) {
            int idx = tid + it * 128;
            int vrow = idx >> 3, vc = idx & 7;
            size_t gv = ((size_t)((b * KV_ + kvh) * D_ + vrow)) * S_ + ks + vc * 8;
            cp16(vb + (uint32_t)((vrow * AVS + vc * 4) * 4), g_vth + gv);
        }
    };

    // Load Q tile (hi/lo) - plain stores, covered by first __syncthreads
    #pragma unroll
    for (int it = 0; it < 8; it++) {
        int idx = tid + it * 128;
        int row = idx >> 4;
        int c4  = idx & 15;
        size_t gq = ((size_t)((b * S_ + qs + row) * H_ + h)) * D_ + c4 * 8;
        *(uint4*)&sQ[row * AQS + c4 * 4]          = *(const uint4*)(g_qhi + gq);
        *(uint4*)&sQ[A_QOFF + row * AQS + c4 * 4] = *(const uint4*)(g_qlo + gq);
    }

    // Preload tile 0 (K then V, separate groups)
    load_k(0, 0); CP_COMMIT();
    load_v(0, 0); CP_COMMIT();

    float o[16][4];
    #pragma unroll
    for (int nf = 0; nf < 16; nf++)
        #pragma unroll
        for (int r = 0; r < 4; r++) o[nf][r] = 0.f;
    float mrow[2] = {-1e30f, -1e30f};
    float lrow[2] = {0.f, 0.f};

    for (int kt = 0; kt <= qt; kt++) {
        const int cur = kt & 1;
        __syncthreads();   // all warps done reading buffer cur^1 (iter kt-1)

        if (kt < qt) {
            load_k(kt + 1, cur ^ 1); CP_COMMIT();
            load_v(kt + 1, cur ^ 1); CP_COMMIT();
            cp_wait<3>();            // K(kt) complete
        } else {
            cp_wait<1>();
        }
        __syncthreads();

        const uint32_t kb = sK_b + cur * KSTG_B;
        const uint32_t vb = sVT_b + cur * VSTG_B;

        // ---- QK^T (2-term: Qhi*K + Qlo*K) ----
        float acc[8][4];
        #pragma unroll
        for (int nf = 0; nf < 8; nf++)
            #pragma unroll
            for (int r = 0; r < 4; r++) acc[nf][r] = 0.f;

        #pragma unroll
        for (int kq = 0; kq < 8; kq++) {
            const uint32_t ko = kq * 32;
            uint32_t ah[4], al[4];
            ldsm_x4(ah, sQ_b + qoff + ko);
            ldsm_x4(al, sQ_b + QLO_B + qoff + ko);
            #pragma unroll
            for (int p = 0; p < 4; p++) {
                uint32_t rh[4];
                ldsm_x4(rh, kb + koff[p] + ko);
                mma16816(acc[2*p],   ah, rh);
                mma16816(acc[2*p],   al, rh);
                mma16816(acc[2*p+1], ah, rh + 2);
                mma16816(acc[2*p+1], al, rh + 2);
            }
        }

        // ---- scale + causal mask ----
        if (kt == qt) {
            const int gr = warp * 16 + g;
            #pragma unroll
            for (int nf = 0; nf < 8; nf++) {
                int c0 = nf * 8 + 2 * t;
                acc[nf][0] = (c0     <= gr    ) ? acc[nf][0] * scale : -1e30f;
                acc[nf][1] = (c0 + 1 <= gr    ) ? acc[nf][1] * scale : -1e30f;
                acc[nf][2] = (c0     <= gr + 8) ? acc[nf][2] * scale : -1e30f;
                acc[nf][3] = (c0 + 1 <= gr + 8) ? acc[nf][3] * scale : -1e30f;
            }
        } else {
            #pragma unroll
            for (int nf = 0; nf < 8; nf++)
                #pragma unroll
                for (int r = 0; r < 4; r++) acc[nf][r] *= scale;
        }

        // ---- online softmax ----
        float mx0 = -1e30f, mx1 = -1e30f;
        #pragma unroll
        for (int nf = 0; nf < 8; nf++) {
            mx0 = fmaxf(mx0, fmaxf(acc[nf][0], acc[nf][1]));
            mx1 = fmaxf(mx1, fmaxf(acc[nf][2], acc[nf][3]));
        }
        mx0 = fmaxf(mx0, __shfl_xor_sync(0xffffffffu, mx0, 1));
        mx0 = fmaxf(mx0, __shfl_xor_sync(0xffffffffu, mx0, 2));
        mx1 = fmaxf(mx1, __shfl_xor_sync(0xffffffffu, mx1, 1));
        mx1 = fmaxf(mx1, __shfl_xor_sync(0xffffffffu, mx1, 2));

        float nm0 = fmaxf(mrow[0], mx0), nm1 = fmaxf(mrow[1], mx1);
        float alpha0 = __expf(mrow[0] - nm0), alpha1 = __expf(mrow[1] - nm1);
        mrow[0] = nm0; mrow[1] = nm1;

        float sum0 = 0.f, sum1 = 0.f;
        #pragma unroll
        for (int nf = 0; nf < 8; nf++) {
            acc[nf][0] = __expf(acc[nf][0] - nm0); sum0 += acc[nf][0];
            acc[nf][1] = __expf(acc[nf][1] - nm0); sum0 += acc[nf][1];
            acc[nf][2] = __expf(acc[nf][2] - nm1); sum1 += acc[nf][2];
            acc[nf][3] = __expf(acc[nf][3] - nm1); sum1 += acc[nf][3];
        }
        sum0 += __shfl_xor_sync(0xffffffffu, sum0, 1);
        sum0 += __shfl_xor_sync(0xffffffffu, sum0, 2);
        sum1 += __shfl_xor_sync(0xffffffffu, sum1, 1);
        sum1 += __shfl_xor_sync(0xffffffffu, sum1, 2);
        lrow[0] = lrow[0] * alpha0 + sum0;
        lrow[1] = lrow[1] * alpha1 + sum1;

        #pragma unroll
        for (int nf = 0; nf < 16; nf++) {
            o[nf][0] *= alpha0; o[nf][1] *= alpha0;
            o[nf][2] *= alpha1; o[nf][3] *= alpha1;
        }

        if (kt < qt) cp_wait<2>(); else cp_wait<0>();   // V(kt) complete
        __syncthreads();

        // ---- P @ V (P split hi/lo in regs; V single) ----
        #pragma unroll
        for (int kq = 0; kq < 4; kq++) {
            uint32_t pah[4], pal[4];
            pack_hilo_h(acc[2*kq  ][0], acc[2*kq  ][1], pah[0], pal[0]);
            pack_hilo_h(acc[2*kq  ][2], acc[2*kq  ][3], pah[1], pal[1]);
            pack_hilo_h(acc[2*kq+1][0], acc[2*kq+1][1], pah[2], pal[2]);
            pack_hilo_h(acc[2*kq+1][2], acc[2*kq+1][3], pah[3], pal[3]);
            const uint32_t ko = kq * 32;
            #pragma unroll
            for (int p = 0; p < 8; p++) {
                uint32_t rh[4];
                ldsm_x4(rh, vb + voff[p] + ko);
                mma16816(o[2*p],   pah, rh);
                mma16816(o[2*p],   pal, rh);
                mma16816(o[2*p+1], pah, rh + 2);
                mma16816(o[2*p+1], pal, rh + 2);
            }
        }
    }

    // ---- epilogue: normalize, write ao hi/lo fp16 ----
    float inv0 = 1.f / lrow[0], inv1 = 1.f / lrow[1];
    size_t base0 = ((size_t)((b * S_ + qs + warp * 16 + g)) * H_ + h) * D_;
    size_t base1 = base0 + (size_t)8 * H_ * D_;
    #pragma unroll
    for (int nf = 0; nf < 16; nf++) {
        int d0 = nf * 8 + 2 * t;
        uint32_t hh, ll;
        pack_hilo_h(o[nf][0] * inv0, o[nf][1] * inv0, hh, ll);
        *(uint32_t*)&g_aohi[base0 + d0] = hh;
        *(uint32_t*)&g_aolo[base0 + d0] = ll;
        pack_hilo_h(o[nf][2] * inv1, o[nf][3] * inv1, hh, ll);
        *(uint32_t*)&g_aohi[base1 + d0] = hh;
        *(uint32_t*)&g_aolo[base1 + d0] = ll;
    }
}

// ---------------------------------------------------------------------------
// kernel_launch
// ---------------------------------------------------------------------------
extern "C" void kernel_launch(void* const* d_in, const int* in_sizes, int n_in,
                              void* d_out, int out_size)
{
    const float* x    = (const float*)d_in[0];
    const float* cosp = (const float*)d_in[1];
    const float* sinp = (const float*)d_in[2];
    // d_in[3] = attention_mask (all ones; unused by reference)
    const float* Wq = (const float*)d_in[4];
    const float* bq = (const float*)d_in[5];
    const float* Wk = (const float*)d_in[6];
    const float* bk = (const float*)d_in[7];
    const float* Wv = (const float*)d_in[8];
    const float* bv = (const float*)d_in[9];
    const float* Wo = (const float*)d_in[10];
    float* out = (float*)d_out;

    float *q, *k, *v;
    cudaGetSymbolAddress((void**)&q, g_q);
    cudaGetSymbolAddress((void**)&k, g_k);
    cudaGetSymbolAddress((void**)&v, g_v);

    __half *xhi, *xlo, *wq, *wk, *wv, *wo, *aohi, *aolo, *qhi, *qlo, *kh, *vth;
    cudaGetSymbolAddress((void**)&xhi,  g_xhi);  cudaGetSymbolAddress((void**)&xlo,  g_xlo);
    cudaGetSymbolAddress((void**)&wq,   g_wq);
    cudaGetSymbolAddress((void**)&wk,   g_wk);
    cudaGetSymbolAddress((void**)&wv,   g_wv);
    cudaGetSymbolAddress((void**)&wo,   g_wo);
    cudaGetSymbolAddress((void**)&aohi, g_aohi); cudaGetSymbolAddress((void**)&aolo, g_aolo);
    cudaGetSymbolAddress((void**)&qhi,  g_qhi);  cudaGetSymbolAddress((void**)&qlo,  g_qlo);
    cudaGetSymbolAddress((void**)&kh,   g_kh);
    cudaGetSymbolAddress((void**)&vth,  g_vth);

    const int M = B_ * S_;   // 4096

    // One segmented split launch: x -> hi/lo, weights -> single fp16
    {
        SplitSegs s;
        s.in[0] = x;  s.hi[0] = xhi; s.lo[0] = xlo;
        s.in[1] = Wq; s.hi[1] = wq;  s.lo[1] = nullptr;
        s.in[2] = Wk; s.hi[2] = wk;  s.lo[2] = nullptr;
        s.in[3] = Wv; s.hi[3] = wv;  s.lo[3] = nullptr;
        s.in[4] = Wo; s.hi[4] = wo;  s.lo[4] = nullptr;
        int c0 = (int)(XN / 4);
        int c1 = c0 + (int)(WQN / 4);
        int c2 = c1 + (int)(WKN / 4);
        int c3 = c2 + (int)(WKN / 4);
        int c4 = c3 + (int)(WON / 4);
        s.end[0] = c0; s.end[1] = c1; s.end[2] = c2; s.end[3] = c3; s.end[4] = c4;
        split_all_kernel<<<(c4 + 511) / 512, 256>>>(s);
    }

    cudaFuncSetAttribute(gemm_qkv, cudaFuncAttributeMaxDynamicSharedMemorySize, GEMM_SMEM_BYTES);
    cudaFuncSetAttribute(gemm_o,   cudaFuncAttributeMaxDynamicSharedMemorySize, GEMM_SMEM_BYTES);

    // Fused QKV projection (one launch, 24x32 = 768 blocks)
    gemm_qkv<<<dim3(24, M / 128), 256, GEMM_SMEM_BYTES>>>(
        xhi, xlo, wq, wk, wv, bq, bk, bv, q, k, v);

    // Fused RoPE + split (q hi/lo, k single); V transpose (single)
    {
        int tq = B_ * S_ * H_  * 64;
        int tk = B_ * S_ * KV_ * 64;
        rope_split_kernel<<<(tq + 255) / 256, 256>>>(q, cosp, sinp, qhi, qlo, H_,  tq);
        rope_split_kernel<<<(tk + 255) / 256, 256>>>(k, cosp, sinp, kh, nullptr, KV_, tk);
        vtrans_kernel<<<dim3(S_ / 32, D_ / 32, B_ * KV_), dim3(32, 8)>>>(v, vth);
    }

    // MMA flash attention (double-buffered K/V)
    cudaFuncSetAttribute(attn_mma_kernel, cudaFuncAttributeMaxDynamicSharedMemorySize,
                         ATTN_SMEM_BYTES);
    attn_mma_kernel<<<dim3(S_ / 64, H_, B_), 128, ATTN_SMEM_BYTES>>>();

    // O projection
    gemm_o<<<dim3(DM_ / 128, M / 128), 256, GEMM_SMEM_BYTES>>>(
        aohi, aolo, wo, out, DM_, DM_);
}

// round 12
// speedup vs baseline: 4.8694x; 1.0223x over previous
#include <cuda_runtime.h>
#include <cuda_fp16.h>
#include <cstdint>

// Problem constants
#define B_  2
#define S_  2048
#define DM_ 2048
#define H_  16
#define KV_ 4
#define D_  128

#define XN  ((size_t)B_ * S_ * DM_)
#define QN  ((size_t)B_ * S_ * H_ * D_)
#define KN  ((size_t)B_ * S_ * KV_ * D_)
#define WQN ((size_t)H_ * D_ * DM_)
#define WKN ((size_t)KV_ * D_ * DM_)
#define WON ((size_t)DM_ * H_ * D_)

// fp16 scratch. A-side operands: hi/lo pairs. B-side operands: single fp16.
__device__ __half g_xhi [XN],  g_xlo [XN];
__device__ __half g_wq  [WQN];
__device__ __half g_wk  [WKN];
__device__ __half g_wv  [WKN];
__device__ __half g_wo  [WON];
__device__ __half g_aohi[QN],  g_aolo[QN];
__device__ __half g_qhi [QN],  g_qlo [QN];
__device__ __half g_kh  [KN];
__device__ __half g_vth [KN];               // [B][KV][D][S]

// ---------------------------------------------------------------------------
// helpers
// ---------------------------------------------------------------------------
__device__ __forceinline__ void mma16816(float* c, const uint32_t* a, const uint32_t* b)
{
    asm volatile(
        "mma.sync.aligned.m16n8k16.row.col.f32.f16.f16.f32 "
        "{%0,%1,%2,%3}, {%4,%5,%6,%7}, {%8,%9}, {%0,%1,%2,%3};\n"
        : "+f"(c[0]), "+f"(c[1]), "+f"(c[2]), "+f"(c[3])
        : "r"(a[0]), "r"(a[1]), "r"(a[2]), "r"(a[3]),
          "r"(b[0]), "r"(b[1]));
}

__device__ __forceinline__ void ldsm_x4(uint32_t* r, uint32_t addr)
{
    asm volatile("ldmatrix.sync.aligned.m8n8.x4.shared.b16 {%0,%1,%2,%3}, [%4];\n"
                 : "=r"(r[0]), "=r"(r[1]), "=r"(r[2]), "=r"(r[3]) : "r"(addr));
}

__device__ __forceinline__ void cp16(uint32_t smem_byte_addr, const void* gptr)
{
    asm volatile("cp.async.cg.shared.global [%0], [%1], 16;\n"
                 :: "r"(smem_byte_addr), "l"(gptr));
}
#define CP_COMMIT() asm volatile("cp.async.commit_group;\n" ::: "memory")
template <int N> __device__ __forceinline__ void cp_wait()
{
    asm volatile("cp.async.wait_group %0;\n" :: "n"(N) : "memory");
}

__device__ __forceinline__ uint32_t pack_h2(float a, float b)
{
    __half h0 = __float2half(a), h1 = __float2half(b);
    return ((uint32_t)__half_as_ushort(h1) << 16) | __half_as_ushort(h0);
}

__device__ __forceinline__ void pack_hilo_h(float a, float b, uint32_t& hi, uint32_t& lo)
{
    __half h0 = __float2half(a), h1 = __float2half(b);
    float r0 = a - __half2float(h0), r1 = b - __half2float(h1);
    hi = ((uint32_t)__half_as_ushort(h1) << 16) | __half_as_ushort(h0);
    lo = ((uint32_t)__half_as_ushort(__float2half(r1)) << 16)
       |  __half_as_ushort(__float2half(r0));
}

// ---------------------------------------------------------------------------
// Segmented fp32 -> fp16 split: x gets hi/lo, weights single. 2x ILP/thread.
// ---------------------------------------------------------------------------
struct SplitSegs {
    const float* in[5];
    __half* hi[5];
    __half* lo[5];
    int end[5];        // cumulative end, in float4 units
};

__global__ void split_all_kernel(SplitSegs segs)
{
    int base = blockIdx.x * 512 + threadIdx.x;
    #pragma unroll
    for (int u = 0; u < 2; u++) {
        int idx = base + u * 256;
        if (idx >= segs.end[4]) continue;
        int s = 0;
        if (idx >= segs.end[0]) s = 1;
        if (idx >= segs.end[1]) s = 2;
        if (idx >= segs.end[2]) s = 3;
        if (idx >= segs.end[3]) s = 4;
        int sb = s ? segs.end[s - 1] : 0;
        int i = idx - sb;

        float4 v = ((const float4*)segs.in[s])[i];
        if (segs.lo[s]) {
            uint32_t h0, l0, h1, l1;
            pack_hilo_h(v.x, v.y, h0, l0);
            pack_hilo_h(v.z, v.w, h1, l1);
            ((uint2*)segs.hi[s])[i] = make_uint2(h0, h1);
            ((uint2*)segs.lo[s])[i] = make_uint2(l0, l1);
        } else {
            ((uint2*)segs.hi[s])[i] = make_uint2(pack_h2(v.x, v.y), pack_h2(v.z, v.w));
        }
    }
}

// ---------------------------------------------------------------------------
// GEMM core (NT), fp16 2-term, 3-stage cp.async ring + ldmatrix.
// Block 128x128x32, 8 warps, warp tile 64x32.
// MODE 0: fp32 C output (O projection)
// MODE 1: fused RoPE + hi/lo fp16 (Q)  — column tile == one head
// MODE 2: fused RoPE + single fp16 (K)
// MODE 3: fused transpose + single fp16 (V) -> [B][KV][D][S]
// ---------------------------------------------------------------------------
#define SSTRIDE 20
#define G_HALF  (128 * SSTRIDE)          // u32 per region
#define G_STG   (3 * G_HALF)             // u32 per stage
#define G_ALO_B (G_HALF * 4)
#define G_B_B   (2 * G_HALF * 4)
#define GEMM_SMEM_BYTES (3 * G_STG * 4)  // 92160 (>= 128*129*4 = 66048 for staging)

template <int MODE>
__device__ __forceinline__ void gemm_core(
    const __half* __restrict__ Ahi, const __half* __restrict__ Alo,
    const __half* __restrict__ Bm,
    const float* __restrict__ bias,
    const float* __restrict__ cs, const float* __restrict__ sn,
    float* __restrict__ Cf,
    __half* __restrict__ Oh, __half* __restrict__ Ol,
    int N, int K, int bm, int bn, int head)
{
    extern __shared__ uint32_t sm[];

    const int tid  = threadIdx.x;
    const int lane = tid & 31;
    const int warp = tid >> 5;
    const int wm   = warp & 1;
    const int wn   = warp >> 1;

    const int lrow = tid >> 2;
    const int lkc  = tid & 3;

    const uint32_t smB = (uint32_t)__cvta_generic_to_shared(sm);

    const int a_row = (lane & 7) + ((lane >> 3) & 1) * 8;
    const int a_chk = ((lane >> 4) & 1) * 4;
    const int b_row = (lane & 7) + ((lane >> 4) & 1) * 8;
    const int b_chk = ((lane >> 3) & 1) * 4;

    uint32_t aoff[4], boff[2];
    #pragma unroll
    for (int mf = 0; mf < 4; mf++)
        aoff[mf] = (uint32_t)(((wm * 64 + mf * 16 + a_row) * SSTRIDE + a_chk) * 4);
    #pragma unroll
    for (int p = 0; p < 2; p++)
        boff[p] = (uint32_t)(((wn * 32 + p * 16 + b_row) * SSTRIDE + b_chk) * 4);

    float acc[4][4][4];
    #pragma unroll
    for (int mf = 0; mf < 4; mf++)
        #pragma unroll
        for (int nf = 0; nf < 4; nf++)
            #pragma unroll
            for (int r = 0; r < 4; r++) acc[mf][nf][r] = 0.f;

    const int niter = K / 32;

    auto load_stage = [&](int st, int k0) {
        uint32_t sbase = (uint32_t)(st * G_STG) * 4;
        #pragma unroll
        for (int r = 0; r < 2; r++) {
            int row = lrow + r * 64;
            size_t ga = (size_t)(bm + row) * K + k0 + lkc * 8;
            size_t gb = (size_t)(bn + row) * K + k0 + lkc * 8;
            uint32_t off = (uint32_t)(row * SSTRIDE + lkc * 4) * 4;
            cp16(smB + sbase + off,           Ahi + ga);
            cp16(smB + sbase + G_ALO_B + off, Alo + ga);
            cp16(smB + sbase + G_B_B + off,   Bm  + gb);
        }
    };

    load_stage(0, 0);
    CP_COMMIT();
    load_stage(1, 32);
    CP_COMMIT();

    for (int it = 0; it < niter; it++) {
        if (it < niter - 1) cp_wait<1>(); else cp_wait<0>();
        __syncthreads();
        if (it + 2 < niter) {
            load_stage((it + 2) % 3, (it + 2) * 32);
            CP_COMMIT();
        }

        const uint32_t stg = smB + (uint32_t)((it % 3) * G_STG) * 4;

        #pragma unroll
        for (int kq = 0; kq < 2; kq++) {
            const uint32_t ko = kq * 32;
            uint32_t ah[4][4], al[4][4], bh[4][2];

            #pragma unroll
            for (int mf = 0; mf < 4; mf++) {
                ldsm_x4(ah[mf], stg + aoff[mf] + ko);
                ldsm_x4(al[mf], stg + G_ALO_B + aoff[mf] + ko);
            }
            #pragma unroll
            for (int p = 0; p < 2; p++) {
                uint32_t r[4];
                ldsm_x4(r, stg + G_B_B + boff[p] + ko);
                bh[2*p][0] = r[0]; bh[2*p][1] = r[1];
                bh[2*p+1][0] = r[2]; bh[2*p+1][1] = r[3];
            }
            #pragma unroll
            for (int mf = 0; mf < 4; mf++)
                #pragma unroll
                for (int nf = 0; nf < 4; nf++) {
                    mma16816(acc[mf][nf], ah[mf], bh[nf]);
                    mma16816(acc[mf][nf], al[mf], bh[nf]);
                }
        }
    }
    __syncthreads();   // all smem pipeline reads done

    if (MODE == 0) {
        #pragma unroll
        for (int mf = 0; mf < 4; mf++) {
            int m0 = bm + wm * 64 + mf * 16 + (lane >> 2);
            #pragma unroll
            for (int nf = 0; nf < 4; nf++) {
                int n0 = bn + wn * 32 + nf * 8 + (lane & 3) * 2;
                Cf[(size_t)m0 * N + n0]           = acc[mf][nf][0];
                Cf[(size_t)m0 * N + n0 + 1]       = acc[mf][nf][1];
                Cf[(size_t)(m0 + 8) * N + n0]     = acc[mf][nf][2];
                Cf[(size_t)(m0 + 8) * N + n0 + 1] = acc[mf][nf][3];
            }
        }
        return;
    }

    // ---- staged epilogue: acc (+bias) -> smem fp32 [128][129] ----
    float* ts = (float*)sm;
    #define TSX(r, c) ts[(r) * 129 + (c)]
    #pragma unroll
    for (int mf = 0; mf < 4; mf++) {
        int r0 = wm * 64 + mf * 16 + (lane >> 2);
        #pragma unroll
        for (int nf = 0; nf < 4; nf++) {
            int c0 = wn * 32 + nf * 8 + (lane & 3) * 2;
            float b0 = bias[bn + c0], b1 = bias[bn + c0 + 1];
            TSX(r0, c0)         = acc[mf][nf][0] + b0;
            TSX(r0, c0 + 1)     = acc[mf][nf][1] + b1;
            TSX(r0 + 8, c0)     = acc[mf][nf][2] + b0;
            TSX(r0 + 8, c0 + 1) = acc[mf][nf][3] + b1;
        }
    }
    __syncthreads();

    if (MODE == 1 || MODE == 2) {
        // RoPE over (d, d+64) pairs; row r maps to global (b*S+s) = bm + r
        for (int i = tid; i < 128 * 64; i += 256) {
            int r = i >> 6, d = i & 63;
            size_t gr = (size_t)(bm + r);
            float cv0 = cs[gr * D_ + d],      sv0 = sn[gr * D_ + d];
            float cv1 = cs[gr * D_ + d + 64], sv1 = sn[gr * D_ + d + 64];
            float a  = TSX(r, d);
            float b2 = TSX(r, d + 64);
            float r0 = a  * cv0 - b2 * sv0;
            float r1 = b2 * cv1 + a  * sv1;
            if (MODE == 1) {
                size_t base = (gr * H_ + head) * D_;
                __half h0 = __float2half(r0), h1 = __float2half(r1);
                Oh[base + d]      = h0;
                Oh[base + d + 64] = h1;
                Ol[base + d]      = __float2half(r0 - __half2float(h0));
                Ol[base + d + 64] = __float2half(r1 - __half2float(h1));
            } else {
                size_t base = (gr * KV_ + head) * D_;
                Oh[base + d]      = __float2half(r0);
                Oh[base + d + 64] = __float2half(r1);
            }
        }
    } else {
        // MODE 3: transpose to [B][KV][D][S]; smem column reads stride 129
        int d  = tid >> 1;
        int sh = (tid & 1) * 64;
        int bb = bm >> 11;          // bm / S_
        int s0 = bm & 2047;         // bm % S_
        size_t ob = (((size_t)bb * KV_ + head) * D_ + d) * S_ + s0 + sh;
        #pragma unroll
        for (int j = 0; j < 64; j += 8) {
            uint32_t w0 = pack_h2(TSX(sh + j,     d), TSX(sh + j + 1, d));
            uint32_t w1 = pack_h2(TSX(sh + j + 2, d), TSX(sh + j + 3, d));
            uint32_t w2 = pack_h2(TSX(sh + j + 4, d), TSX(sh + j + 5, d));
            uint32_t w3 = pack_h2(TSX(sh + j + 6, d), TSX(sh + j + 7, d));
            *(uint4*)&Oh[ob + j] = make_uint4(w0, w1, w2, w3);
        }
    }
    #undef TSX
}

// O-projection GEMM (fp32 out, no bias)
__global__ __launch_bounds__(256) void gemm_o(
    const __half* __restrict__ Ahi, const __half* __restrict__ Alo,
    const __half* __restrict__ Bm, float* __restrict__ C, int N, int K)
{
    gemm_core<0>(Ahi, Alo, Bm, nullptr, nullptr, nullptr, C, nullptr, nullptr,
                 N, K, blockIdx.y * 128, blockIdx.x * 128, 0);
}

// Fused QKV projection + RoPE + split + V-transpose.
// grid.x = 24 column tiles (16 Q heads, 4 K heads, 4 V heads)
__global__ __launch_bounds__(256) void gemm_qkv(
    const __half* __restrict__ xhi, const __half* __restrict__ xlo,
    const __half* __restrict__ wq, const __half* __restrict__ wk,
    const __half* __restrict__ wv,
    const float* __restrict__ bq, const float* __restrict__ bk,
    const float* __restrict__ bv,
    const float* __restrict__ cs, const float* __restrict__ sn,
    __half* __restrict__ qhi, __half* __restrict__ qlo,
    __half* __restrict__ kh,  __half* __restrict__ vth)
{
    const int ct = blockIdx.x;
    const int bm = blockIdx.y * 128;
    if (ct < 16) {
        gemm_core<1>(xhi, xlo, wq + (size_t)ct * 128 * DM_ - (size_t)ct * 128 * DM_ + 0, // keep wq base; bn selects
                     bq, cs, sn, nullptr, qhi, qlo, 2048, DM_, bm, ct * 128, ct);
    } else if (ct < 20) {
        gemm_core<2>(xhi, xlo, wk, bk, cs, sn, nullptr, kh, nullptr,
                     512, DM_, bm, (ct - 16) * 128, ct - 16);
    } else {
        gemm_core<3>(xhi, xlo, wv, bv, nullptr, nullptr, nullptr, vth, nullptr,
                     512, DM_, bm, (ct - 20) * 128, ct - 20);
    }
}

// ---------------------------------------------------------------------------
// MMA flash attention (causal, GQA), fp16 2-term, double-buffered K/V.
// Unchanged from R10 (validated).
// ---------------------------------------------------------------------------
#define AQS 68
#define AVS 36
#define A_QOFF (64 * AQS)
#define QLO_B (A_QOFF * 4)
#define KSTG_B (64 * AQS * 4)
#define VSTG_B (128 * AVS * 4)
#define ATTN_SMEM_BYTES ((2*64*AQS + 2*64*AQS + 2*128*AVS) * 4)  // 106,496

__global__ __launch_bounds__(128) void attn_mma_kernel()
{
    extern __shared__ uint32_t smu[];
    uint32_t* sQ  = smu;

    const int tid  = threadIdx.x;
    const int lane = tid & 31;
    const int warp = tid >> 5;
    const int g    = lane >> 2;
    const int t    = lane & 3;
    const int qt   = gridDim.x - 1 - blockIdx.x;
    const int h    = blockIdx.y;
    const int b    = blockIdx.z;
    const int qs   = qt * 64;
    const int kvh  = h >> 2;
    const float scale = 0.08838834764831845f;

    const uint32_t smB   = (uint32_t)__cvta_generic_to_shared(smu);
    const uint32_t sQ_b  = smB;
    const uint32_t sK_b  = smB + 2 * 64 * AQS * 4;
    const uint32_t sVT_b = sK_b + 2 * KSTG_B;

    const int a_row = (lane & 7) + ((lane >> 3) & 1) * 8;
    const int a_chk = ((lane >> 4) & 1) * 4;
    const int b_row = (lane & 7) + ((lane >> 4) & 1) * 8;
    const int b_chk = ((lane >> 3) & 1) * 4;

    const uint32_t qoff = (uint32_t)(((warp * 16 + a_row) * AQS + a_chk) * 4);
    uint32_t koff[4], voff[8];
    #pragma unroll
    for (int p = 0; p < 4; p++)
        koff[p] = (uint32_t)(((p * 16 + b_row) * AQS + b_chk) * 4);
    #pragma unroll
    for (int p = 0; p < 8; p++)
        voff[p] = (uint32_t)(((p * 16 + b_row) * AVS + b_chk) * 4);

    auto load_k = [&](int kt_, int st) {
        const int ks = kt_ * 64;
        uint32_t kb = sK_b + st * KSTG_B;
        #pragma unroll
        for (int it = 0; it < 8; it++) {
            int idx = tid + it * 128;
            int row = idx >> 4, c4 = idx & 15;
            size_t gk = ((size_t)((b * S_ + ks + row) * KV_ + kvh)) * D_ + c4 * 8;
            cp16(kb + (uint32_t)((row * AQS + c4 * 4) * 4), g_kh + gk);
        }
    };
    auto load_v = [&](int kt_, int st) {
        const int ks = kt_ * 64;
        uint32_t vb = sVT_b + st * VSTG_B;
        #pragma unroll
        for (int it = 0; it < 8; it++) {
            int idx = tid + it * 128;
            int vrow = idx >> 3, vc = idx & 7;
            size_t gv = ((size_t)((b * KV_ + kvh) * D_ + vrow)) * S_ + ks + vc * 8;
            cp16(vb + (uint32_t)((vrow * AVS + vc * 4) * 4), g_vth + gv);
        }
    };

    #pragma unroll
    for (int it = 0; it < 8; it++) {
        int idx = tid + it * 128;
        int row = idx >> 4;
        int c4  = idx & 15;
        size_t gq = ((size_t)((b * S_ + qs + row) * H_ + h)) * D_ + c4 * 8;
        *(uint4*)&sQ[row * AQS + c4 * 4]          = *(const uint4*)(g_qhi + gq);
        *(uint4*)&sQ[A_QOFF + row * AQS + c4 * 4] = *(const uint4*)(g_qlo + gq);
    }

    load_k(0, 0); CP_COMMIT();
    load_v(0, 0); CP_COMMIT();

    float o[16][4];
    #pragma unroll
    for (int nf = 0; nf < 16; nf++)
        #pragma unroll
        for (int r = 0; r < 4; r++) o[nf][r] = 0.f;
    float mrow[2] = {-1e30f, -1e30f};
    float lrow[2] = {0.f, 0.f};

    for (int kt = 0; kt <= qt; kt++) {
        const int cur = kt & 1;
        __syncthreads();

        if (kt < qt) {
            load_k(kt + 1, cur ^ 1); CP_COMMIT();
            load_v(kt + 1, cur ^ 1); CP_COMMIT();
            cp_wait<3>();
        } else {
            cp_wait<1>();
        }
        __syncthreads();

        const uint32_t kb = sK_b + cur * KSTG_B;
        const uint32_t vb = sVT_b + cur * VSTG_B;

        float acc[8][4];
        #pragma unroll
        for (int nf = 0; nf < 8; nf++)
            #pragma unroll
            for (int r = 0; r < 4; r++) acc[nf][r] = 0.f;

        #pragma unroll
        for (int kq = 0; kq < 8; kq++) {
            const uint32_t ko = kq * 32;
            uint32_t ah[4], al[4];
            ldsm_x4(ah, sQ_b + qoff + ko);
            ldsm_x4(al, sQ_b + QLO_B + qoff + ko);
            #pragma unroll
            for (int p = 0; p < 4; p++) {
                uint32_t rh[4];
                ldsm_x4(rh, kb + koff[p] + ko);
                mma16816(acc[2*p],   ah, rh);
                mma16816(acc[2*p],   al, rh);
                mma16816(acc[2*p+1], ah, rh + 2);
                mma16816(acc[2*p+1], al, rh + 2);
            }
        }

        if (kt == qt) {
            const int gr = warp * 16 + g;
            #pragma unroll
            for (int nf = 0; nf < 8; nf++) {
                int c0 = nf * 8 + 2 * t;
                acc[nf][0] = (c0     <= gr    ) ? acc[nf][0] * scale : -1e30f;
                acc[nf][1] = (c0 + 1 <= gr    ) ? acc[nf][1] * scale : -1e30f;
                acc[nf][2] = (c0     <= gr + 8) ? acc[nf][2] * scale : -1e30f;
                acc[nf][3] = (c0 + 1 <= gr + 8) ? acc[nf][3] * scale : -1e30f;
            }
        } else {
            #pragma unroll
            for (int nf = 0; nf < 8; nf++)
                #pragma unroll
                for (int r = 0; r < 4; r++) acc[nf][r] *= scale;
        }

        float mx0 = -1e30f, mx1 = -1e30f;
        #pragma unroll
        for (int nf = 0; nf < 8; nf++) {
            mx0 = fmaxf(mx0, fmaxf(acc[nf][0], acc[nf][1]));
            mx1 = fmaxf(mx1, fmaxf(acc[nf][2], acc[nf][3]));
        }
        mx0 = fmaxf(mx0, __shfl_xor_sync(0xffffffffu, mx0, 1));
        mx0 = fmaxf(mx0, __shfl_xor_sync(0xffffffffu, mx0, 2));
        mx1 = fmaxf(mx1, __shfl_xor_sync(0xffffffffu, mx1, 1));
        mx1 = fmaxf(mx1, __shfl_xor_sync(0xffffffffu, mx1, 2));

        float nm0 = fmaxf(mrow[0], mx0), nm1 = fmaxf(mrow[1], mx1);
        float alpha0 = __expf(mrow[0] - nm0), alpha1 = __expf(mrow[1] - nm1);
        mrow[0] = nm0; mrow[1] = nm1;

        float sum0 = 0.f, sum1 = 0.f;
        #pragma unroll
        for (int nf = 0; nf < 8; nf++) {
            acc[nf][0] = __expf(acc[nf][0] - nm0); sum0 += acc[nf][0];
            acc[nf][1] = __expf(acc[nf][1] - nm0); sum0 += acc[nf][1];
            acc[nf][2] = __expf(acc[nf][2] - nm1); sum1 += acc[nf][2];
            acc[nf][3] = __expf(acc[nf][3] - nm1); sum1 += acc[nf][3];
        }
        sum0 += __shfl_xor_sync(0xffffffffu, sum0, 1);
        sum0 += __shfl_xor_sync(0xffffffffu, sum0, 2);
        sum1 += __shfl_xor_sync(0xffffffffu, sum1, 1);
        sum1 += __shfl_xor_sync(0xffffffffu, sum1, 2);
        lrow[0] = lrow[0] * alpha0 + sum0;
        lrow[1] = lrow[1] * alpha1 + sum1;

        #pragma unroll
        for (int nf = 0; nf < 16; nf++) {
            o[nf][0] *= alpha0; o[nf][1] *= alpha0;
            o[nf][2] *= alpha1; o[nf][3] *= alpha1;
        }

        if (kt < qt) cp_wait<2>(); else cp_wait<0>();
        __syncthreads();

        #pragma unroll
        for (int kq = 0; kq < 4; kq++) {
            uint32_t pah[4], pal[4];
            pack_hilo_h(acc[2*kq  ][0], acc[2*kq  ][1], pah[0], pal[0]);
            pack_hilo_h(acc[2*kq  ][2], acc[2*kq  ][3], pah[1], pal[1]);
            pack_hilo_h(acc[2*kq+1][0], acc[2*kq+1][1], pah[2], pal[2]);
            pack_hilo_h(acc[2*kq+1][2], acc[2*kq+1][3], pah[3], pal[3]);
            const uint32_t ko = kq * 32;
            #pragma unroll
            for (int p = 0; p < 8; p++) {
                uint32_t rh[4];
                ldsm_x4(rh, vb + voff[p] + ko);
                mma16816(o[2*p],   pah, rh);
                mma16816(o[2*p],   pal, rh);
                mma16816(o[2*p+1], pah, rh + 2);
                mma16816(o[2*p+1], pal, rh + 2);
            }
        }
    }

    float inv0 = 1.f / lrow[0], inv1 = 1.f / lrow[1];
    size_t base0 = ((size_t)((b * S_ + qs + warp * 16 + g)) * H_ + h) * D_;
    size_t base1 = base0 + (size_t)8 * H_ * D_;
    #pragma unroll
    for (int nf = 0; nf < 16; nf++) {
        int d0 = nf * 8 + 2 * t;
        uint32_t hh, ll;
        pack_hilo_h(o[nf][0] * inv0, o[nf][1] * inv0, hh, ll);
        *(uint32_t*)&g_aohi[base0 + d0] = hh;
        *(uint32_t*)&g_aolo[base0 + d0] = ll;
        pack_hilo_h(o[nf][2] * inv1, o[nf][3] * inv1, hh, ll);
        *(uint32_t*)&g_aohi[base1 + d0] = hh;
        *(uint32_t*)&g_aolo[base1 + d0] = ll;
    }
}

// ---------------------------------------------------------------------------
// kernel_launch
// ---------------------------------------------------------------------------
extern "C" void kernel_launch(void* const* d_in, const int* in_sizes, int n_in,
                              void* d_out, int out_size)
{
    const float* x    = (const float*)d_in[0];
    const float* cosp = (const float*)d_in[1];
    const float* sinp = (const float*)d_in[2];
    // d_in[3] = attention_mask (all ones; unused by reference)
    const float* Wq = (const float*)d_in[4];
    const float* bq = (const float*)d_in[5];
    const float* Wk = (const float*)d_in[6];
    const float* bk = (const float*)d_in[7];
    const float* Wv = (const float*)d_in[8];
    const float* bv = (const float*)d_in[9];
    const float* Wo = (const float*)d_in[10];
    float* out = (float*)d_out;

    __half *xhi, *xlo, *wq, *wk, *wv, *wo, *aohi, *aolo, *qhi, *qlo, *kh, *vth;
    cudaGetSymbolAddress((void**)&xhi,  g_xhi);  cudaGetSymbolAddress((void**)&xlo,  g_xlo);
    cudaGetSymbolAddress((void**)&wq,   g_wq);
    cudaGetSymbolAddress((void**)&wk,   g_wk);
    cudaGetSymbolAddress((void**)&wv,   g_wv);
    cudaGetSymbolAddress((void**)&wo,   g_wo);
    cudaGetSymbolAddress((void**)&aohi, g_aohi); cudaGetSymbolAddress((void**)&aolo, g_aolo);
    cudaGetSymbolAddress((void**)&qhi,  g_qhi);  cudaGetSymbolAddress((void**)&qlo,  g_qlo);
    cudaGetSymbolAddress((void**)&kh,   g_kh);
    cudaGetSymbolAddress((void**)&vth,  g_vth);

    const int M = B_ * S_;   // 4096

    // One segmented split launch: x -> hi/lo, weights -> single fp16
    {
        SplitSegs s;
        s.in[0] = x;  s.hi[0] = xhi; s.lo[0] = xlo;
        s.in[1] = Wq; s.hi[1] = wq;  s.lo[1] = nullptr;
        s.in[2] = Wk; s.hi[2] = wk;  s.lo[2] = nullptr;
        s.in[3] = Wv; s.hi[3] = wv;  s.lo[3] = nullptr;
        s.in[4] = Wo; s.hi[4] = wo;  s.lo[4] = nullptr;
        int c0 = (int)(XN / 4);
        int c1 = c0 + (int)(WQN / 4);
        int c2 = c1 + (int)(WKN / 4);
        int c3 = c2 + (int)(WKN / 4);
        int c4 = c3 + (int)(WON / 4);
        s.end[0] = c0; s.end[1] = c1; s.end[2] = c2; s.end[3] = c3; s.end[4] = c4;
        split_all_kernel<<<(c4 + 511) / 512, 256>>>(s);
    }

    cudaFuncSetAttribute(gemm_qkv, cudaFuncAttributeMaxDynamicSharedMemorySize, GEMM_SMEM_BYTES);
    cudaFuncSetAttribute(gemm_o,   cudaFuncAttributeMaxDynamicSharedMemorySize, GEMM_SMEM_BYTES);

    // Fused QKV projection + RoPE + split + V-transpose (one launch)
    gemm_qkv<<<dim3(24, M / 128), 256, GEMM_SMEM_BYTES>>>(
        xhi, xlo, wq, wk, wv, bq, bk, bv, cosp, sinp, qhi, qlo, kh, vth);

    // MMA flash attention (double-buffered K/V)
    cudaFuncSetAttribute(attn_mma_kernel, cudaFuncAttributeMaxDynamicSharedMemorySize,
                         ATTN_SMEM_BYTES);
    attn_mma_kernel<<<dim3(S_ / 64, H_, B_), 128, ATTN_SMEM_BYTES>>>();

    // O projection
    gemm_o<<<dim3(DM_ / 128, M / 128), 256, GEMM_SMEM_BYTES>>>(
        aohi, aolo, wo, out, DM_, DM_);
}

// round 13
// speedup vs baseline: 4.9920x; 1.0252x over previous
#include <cuda_runtime.h>
#include <cuda_fp16.h>
#include <cstdint>

// Problem constants
#define B_  2
#define S_  2048
#define DM_ 2048
#define H_  16
#define KV_ 4
#define D_  128

#define XN  ((size_t)B_ * S_ * DM_)
#define QN  ((size_t)B_ * S_ * H_ * D_)
#define KN  ((size_t)B_ * S_ * KV_ * D_)
#define WQN ((size_t)H_ * D_ * DM_)
#define WKN ((size_t)KV_ * D_ * DM_)
#define WON ((size_t)DM_ * H_ * D_)

// fp16 scratch. A-side operands: hi/lo pairs. B-side operands: single fp16.
__device__ __half g_xhi [XN],  g_xlo [XN];
__device__ __half g_wq  [WQN];
__device__ __half g_wk  [WKN];
__device__ __half g_wv  [WKN];
__device__ __half g_wo  [WON];
__device__ __half g_aohi[QN],  g_aolo[QN];
__device__ __half g_qhi [QN],  g_qlo [QN];
__device__ __half g_kh  [KN];
__device__ __half g_vth [KN];               // [B][KV][D][S]

// ---------------------------------------------------------------------------
// helpers
// ---------------------------------------------------------------------------
__device__ __forceinline__ void mma16816(float* c, const uint32_t* a, const uint32_t* b)
{
    asm volatile(
        "mma.sync.aligned.m16n8k16.row.col.f32.f16.f16.f32 "
        "{%0,%1,%2,%3}, {%4,%5,%6,%7}, {%8,%9}, {%0,%1,%2,%3};\n"
        : "+f"(c[0]), "+f"(c[1]), "+f"(c[2]), "+f"(c[3])
        : "r"(a[0]), "r"(a[1]), "r"(a[2]), "r"(a[3]),
          "r"(b[0]), "r"(b[1]));
}

__device__ __forceinline__ void ldsm_x4(uint32_t* r, uint32_t addr)
{
    asm volatile("ldmatrix.sync.aligned.m8n8.x4.shared.b16 {%0,%1,%2,%3}, [%4];\n"
                 : "=r"(r[0]), "=r"(r[1]), "=r"(r[2]), "=r"(r[3]) : "r"(addr));
}

__device__ __forceinline__ void cp16(uint32_t smem_byte_addr, const void* gptr)
{
    asm volatile("cp.async.cg.shared.global [%0], [%1], 16;\n"
                 :: "r"(smem_byte_addr), "l"(gptr));
}
#define CP_COMMIT() asm volatile("cp.async.commit_group;\n" ::: "memory")
template <int N> __device__ __forceinline__ void cp_wait()
{
    asm volatile("cp.async.wait_group %0;\n" :: "n"(N) : "memory");
}

__device__ __forceinline__ uint32_t pack_h2(float a, float b)
{
    __half h0 = __float2half(a), h1 = __float2half(b);
    return ((uint32_t)__half_as_ushort(h1) << 16) | __half_as_ushort(h0);
}

__device__ __forceinline__ void pack_hilo_h(float a, float b, uint32_t& hi, uint32_t& lo)
{
    __half h0 = __float2half(a), h1 = __float2half(b);
    float r0 = a - __half2float(h0), r1 = b - __half2float(h1);
    hi = ((uint32_t)__half_as_ushort(h1) << 16) | __half_as_ushort(h0);
    lo = ((uint32_t)__half_as_ushort(__float2half(r1)) << 16)
       |  __half_as_ushort(__float2half(r0));
}

// ---------------------------------------------------------------------------
// Segmented fp32 -> fp16 split: x gets hi/lo, weights single. 2x ILP/thread.
// ---------------------------------------------------------------------------
struct SplitSegs {
    const float* in[5];
    __half* hi[5];
    __half* lo[5];
    int end[5];        // cumulative end, in float4 units
};

__global__ void split_all_kernel(SplitSegs segs)
{
    int base = blockIdx.x * 512 + threadIdx.x;
    #pragma unroll
    for (int u = 0; u < 2; u++) {
        int idx = base + u * 256;
        if (idx >= segs.end[4]) continue;
        int s = 0;
        if (idx >= segs.end[0]) s = 1;
        if (idx >= segs.end[1]) s = 2;
        if (idx >= segs.end[2]) s = 3;
        if (idx >= segs.end[3]) s = 4;
        int sb = s ? segs.end[s - 1] : 0;
        int i = idx - sb;

        float4 v = ((const float4*)segs.in[s])[i];
        if (segs.lo[s]) {
            uint32_t h0, l0, h1, l1;
            pack_hilo_h(v.x, v.y, h0, l0);
            pack_hilo_h(v.z, v.w, h1, l1);
            ((uint2*)segs.hi[s])[i] = make_uint2(h0, h1);
            ((uint2*)segs.lo[s])[i] = make_uint2(l0, l1);
        } else {
            ((uint2*)segs.hi[s])[i] = make_uint2(pack_h2(v.x, v.y), pack_h2(v.z, v.w));
        }
    }
}

// ---------------------------------------------------------------------------
// GEMM core (NT), fp16 2-term, 3-stage cp.async ring + ldmatrix.
// Block 128x128x32, 8 warps, warp tile 64x32.
// MMA issue order: all hi-terms across 16 independent accumulators, then all
// lo-terms (per-acc order hi->lo preserved => bit-identical numerics; reuse
// distance 16 mmas hides HMMA latency).
// MODE 0: fp32 C output (O projection)
// MODE 1: fused RoPE + hi/lo fp16 (Q)  — column tile == one head
// MODE 2: fused RoPE + single fp16 (K)
// MODE 3: fused transpose + single fp16 (V) -> [B][KV][D][S]
// ---------------------------------------------------------------------------
#define SSTRIDE 20
#define G_HALF  (128 * SSTRIDE)          // u32 per region
#define G_STG   (3 * G_HALF)             // u32 per stage
#define G_ALO_B (G_HALF * 4)
#define G_B_B   (2 * G_HALF * 4)
#define GEMM_SMEM_BYTES (3 * G_STG * 4)  // 92160 (>= 128*129*4 = 66048 for staging)

template <int MODE>
__device__ __forceinline__ void gemm_core(
    const __half* __restrict__ Ahi, const __half* __restrict__ Alo,
    const __half* __restrict__ Bm,
    const float* __restrict__ bias,
    const float* __restrict__ cs, const float* __restrict__ sn,
    float* __restrict__ Cf,
    __half* __restrict__ Oh, __half* __restrict__ Ol,
    int N, int K, int bm, int bn, int head)
{
    extern __shared__ uint32_t sm[];

    const int tid  = threadIdx.x;
    const int lane = tid & 31;
    const int warp = tid >> 5;
    const int wm   = warp & 1;
    const int wn   = warp >> 1;

    const int lrow = tid >> 2;
    const int lkc  = tid & 3;

    const uint32_t smB = (uint32_t)__cvta_generic_to_shared(sm);

    const int a_row = (lane & 7) + ((lane >> 3) & 1) * 8;
    const int a_chk = ((lane >> 4) & 1) * 4;
    const int b_row = (lane & 7) + ((lane >> 4) & 1) * 8;
    const int b_chk = ((lane >> 3) & 1) * 4;

    uint32_t aoff[4], boff[2];
    #pragma unroll
    for (int mf = 0; mf < 4; mf++)
        aoff[mf] = (uint32_t)(((wm * 64 + mf * 16 + a_row) * SSTRIDE + a_chk) * 4);
    #pragma unroll
    for (int p = 0; p < 2; p++)
        boff[p] = (uint32_t)(((wn * 32 + p * 16 + b_row) * SSTRIDE + b_chk) * 4);

    float acc[4][4][4];
    #pragma unroll
    for (int mf = 0; mf < 4; mf++)
        #pragma unroll
        for (int nf = 0; nf < 4; nf++)
            #pragma unroll
            for (int r = 0; r < 4; r++) acc[mf][nf][r] = 0.f;

    const int niter = K / 32;

    auto load_stage = [&](int st, int k0) {
        uint32_t sbase = (uint32_t)(st * G_STG) * 4;
        #pragma unroll
        for (int r = 0; r < 2; r++) {
            int row = lrow + r * 64;
            size_t ga = (size_t)(bm + row) * K + k0 + lkc * 8;
            size_t gb = (size_t)(bn + row) * K + k0 + lkc * 8;
            uint32_t off = (uint32_t)(row * SSTRIDE + lkc * 4) * 4;
            cp16(smB + sbase + off,           Ahi + ga);
            cp16(smB + sbase + G_ALO_B + off, Alo + ga);
            cp16(smB + sbase + G_B_B + off,   Bm  + gb);
        }
    };

    load_stage(0, 0);
    CP_COMMIT();
    load_stage(1, 32);
    CP_COMMIT();

    for (int it = 0; it < niter; it++) {
        if (it < niter - 1) cp_wait<1>(); else cp_wait<0>();
        __syncthreads();
        if (it + 2 < niter) {
            load_stage((it + 2) % 3, (it + 2) * 32);
            CP_COMMIT();
        }

        const uint32_t stg = smB + (uint32_t)((it % 3) * G_STG) * 4;

        #pragma unroll
        for (int kq = 0; kq < 2; kq++) {
            const uint32_t ko = kq * 32;
            uint32_t ah[4][4], al[4][4], bh[4][2];

            #pragma unroll
            for (int mf = 0; mf < 4; mf++) {
                ldsm_x4(ah[mf], stg + aoff[mf] + ko);
                ldsm_x4(al[mf], stg + G_ALO_B + aoff[mf] + ko);
            }
            #pragma unroll
            for (int p = 0; p < 2; p++) {
                uint32_t r[4];
                ldsm_x4(r, stg + G_B_B + boff[p] + ko);
                bh[2*p][0] = r[0]; bh[2*p][1] = r[1];
                bh[2*p+1][0] = r[2]; bh[2*p+1][1] = r[3];
            }
            // hi-terms: 16 independent accumulators
            #pragma unroll
            for (int mf = 0; mf < 4; mf++)
                #pragma unroll
                for (int nf = 0; nf < 4; nf++)
                    mma16816(acc[mf][nf], ah[mf], bh[nf]);
            // lo-terms
            #pragma unroll
            for (int mf = 0; mf < 4; mf++)
                #pragma unroll
                for (int nf = 0; nf < 4; nf++)
                    mma16816(acc[mf][nf], al[mf], bh[nf]);
        }
    }
    __syncthreads();   // all smem pipeline reads done

    if (MODE == 0) {
        #pragma unroll
        for (int mf = 0; mf < 4; mf++) {
            int m0 = bm + wm * 64 + mf * 16 + (lane >> 2);
            #pragma unroll
            for (int nf = 0; nf < 4; nf++) {
                int n0 = bn + wn * 32 + nf * 8 + (lane & 3) * 2;
                Cf[(size_t)m0 * N + n0]           = acc[mf][nf][0];
                Cf[(size_t)m0 * N + n0 + 1]       = acc[mf][nf][1];
                Cf[(size_t)(m0 + 8) * N + n0]     = acc[mf][nf][2];
                Cf[(size_t)(m0 + 8) * N + n0 + 1] = acc[mf][nf][3];
            }
        }
        return;
    }

    // ---- staged epilogue: acc (+bias) -> smem fp32 [128][129] ----
    float* ts = (float*)sm;
    #define TSX(r, c) ts[(r) * 129 + (c)]
    #pragma unroll
    for (int mf = 0; mf < 4; mf++) {
        int r0 = wm * 64 + mf * 16 + (lane >> 2);
        #pragma unroll
        for (int nf = 0; nf < 4; nf++) {
            int c0 = wn * 32 + nf * 8 + (lane & 3) * 2;
            float b0 = bias[bn + c0], b1 = bias[bn + c0 + 1];
            TSX(r0, c0)         = acc[mf][nf][0] + b0;
            TSX(r0, c0 + 1)     = acc[mf][nf][1] + b1;
            TSX(r0 + 8, c0)     = acc[mf][nf][2] + b0;
            TSX(r0 + 8, c0 + 1) = acc[mf][nf][3] + b1;
        }
    }
    __syncthreads();

    if (MODE == 1 || MODE == 2) {
        // RoPE over (d, d+64) pairs; row r maps to global (b*S+s) = bm + r
        for (int i = tid; i < 128 * 64; i += 256) {
            int r = i >> 6, d = i & 63;
            size_t gr = (size_t)(bm + r);
            float cv0 = cs[gr * D_ + d],      sv0 = sn[gr * D_ + d];
            float cv1 = cs[gr * D_ + d + 64], sv1 = sn[gr * D_ + d + 64];
            float a  = TSX(r, d);
            float b2 = TSX(r, d + 64);
            float r0 = a  * cv0 - b2 * sv0;
            float r1 = b2 * cv1 + a  * sv1;
            if (MODE == 1) {
                size_t base = (gr * H_ + head) * D_;
                __half h0 = __float2half(r0), h1 = __float2half(r1);
                Oh[base + d]      = h0;
                Oh[base + d + 64] = h1;
                Ol[base + d]      = __float2half(r0 - __half2float(h0));
                Ol[base + d + 64] = __float2half(r1 - __half2float(h1));
            } else {
                size_t base = (gr * KV_ + head) * D_;
                Oh[base + d]      = __float2half(r0);
                Oh[base + d + 64] = __float2half(r1);
            }
        }
    } else {
        // MODE 3: transpose to [B][KV][D][S]; smem column reads stride 129
        int d  = tid >> 1;
        int sh = (tid & 1) * 64;
        int bb = bm >> 11;          // bm / S_
        int s0 = bm & 2047;         // bm % S_
        size_t ob = (((size_t)bb * KV_ + head) * D_ + d) * S_ + s0 + sh;
        #pragma unroll
        for (int j = 0; j < 64; j += 8) {
            uint32_t w0 = pack_h2(TSX(sh + j,     d), TSX(sh + j + 1, d));
            uint32_t w1 = pack_h2(TSX(sh + j + 2, d), TSX(sh + j + 3, d));
            uint32_t w2 = pack_h2(TSX(sh + j + 4, d), TSX(sh + j + 5, d));
            uint32_t w3 = pack_h2(TSX(sh + j + 6, d), TSX(sh + j + 7, d));
            *(uint4*)&Oh[ob + j] = make_uint4(w0, w1, w2, w3);
        }
    }
    #undef TSX
}

// O-projection GEMM (fp32 out, no bias)
__global__ __launch_bounds__(256) void gemm_o(
    const __half* __restrict__ Ahi, const __half* __restrict__ Alo,
    const __half* __restrict__ Bm, float* __restrict__ C, int N, int K)
{
    gemm_core<0>(Ahi, Alo, Bm, nullptr, nullptr, nullptr, C, nullptr, nullptr,
                 N, K, blockIdx.y * 128, blockIdx.x * 128, 0);
}

// Fused QKV projection + RoPE + split + V-transpose.
// grid.x = 24 column tiles (16 Q heads, 4 K heads, 4 V heads)
__global__ __launch_bounds__(256) void gemm_qkv(
    const __half* __restrict__ xhi, const __half* __restrict__ xlo,
    const __half* __restrict__ wq, const __half* __restrict__ wk,
    const __half* __restrict__ wv,
    const float* __restrict__ bq, const float* __restrict__ bk,
    const float* __restrict__ bv,
    const float* __restrict__ cs, const float* __restrict__ sn,
    __half* __restrict__ qhi, __half* __restrict__ qlo,
    __half* __restrict__ kh,  __half* __restrict__ vth)
{
    const int ct = blockIdx.x;
    const int bm = blockIdx.y * 128;
    if (ct < 16) {
        gemm_core<1>(xhi, xlo, wq, bq, cs, sn, nullptr, qhi, qlo,
                     2048, DM_, bm, ct * 128, ct);
    } else if (ct < 20) {
        gemm_core<2>(xhi, xlo, wk, bk, cs, sn, nullptr, kh, nullptr,
                     512, DM_, bm, (ct - 16) * 128, ct - 16);
    } else {
        gemm_core<3>(xhi, xlo, wv, bv, nullptr, nullptr, nullptr, vth, nullptr,
                     512, DM_, bm, (ct - 20) * 128, ct - 20);
    }
}

// ---------------------------------------------------------------------------
// MMA flash attention (causal, GQA), fp16 2-term, double-buffered K/V.
// MMA issue order reordered for accumulator-reuse distance (same trick).
// ---------------------------------------------------------------------------
#define AQS 68
#define AVS 36
#define A_QOFF (64 * AQS)
#define QLO_B (A_QOFF * 4)
#define KSTG_B (64 * AQS * 4)
#define VSTG_B (128 * AVS * 4)
#define ATTN_SMEM_BYTES ((2*64*AQS + 2*64*AQS + 2*128*AVS) * 4)  // 106,496

__global__ __launch_bounds__(128) void attn_mma_kernel()
{
    extern __shared__ uint32_t smu[];
    uint32_t* sQ  = smu;

    const int tid  = threadIdx.x;
    const int lane = tid & 31;
    const int warp = tid >> 5;
    const int g    = lane >> 2;
    const int t    = lane & 3;
    const int qt   = gridDim.x - 1 - blockIdx.x;
    const int h    = blockIdx.y;
    const int b    = blockIdx.z;
    const int qs   = qt * 64;
    const int kvh  = h >> 2;
    const float scale = 0.08838834764831845f;

    const uint32_t smB   = (uint32_t)__cvta_generic_to_shared(smu);
    const uint32_t sQ_b  = smB;
    const uint32_t sK_b  = smB + 2 * 64 * AQS * 4;
    const uint32_t sVT_b = sK_b + 2 * KSTG_B;

    const int a_row = (lane & 7) + ((lane >> 3) & 1) * 8;
    const int a_chk = ((lane >> 4) & 1) * 4;
    const int b_row = (lane & 7) + ((lane >> 4) & 1) * 8;
    const int b_chk = ((lane >> 3) & 1) * 4;

    const uint32_t qoff = (uint32_t)(((warp * 16 + a_row) * AQS + a_chk) * 4);
    uint32_t koff[4], voff[8];
    #pragma unroll
    for (int p = 0; p < 4; p++)
        koff[p] = (uint32_t)(((p * 16 + b_row) * AQS + b_chk) * 4);
    #pragma unroll
    for (int p = 0; p < 8; p++)
        voff[p] = (uint32_t)(((p * 16 + b_row) * AVS + b_chk) * 4);

    auto load_k = [&](int kt_, int st) {
        const int ks = kt_ * 64;
        uint32_t kb = sK_b + st * KSTG_B;
        #pragma unroll
        for (int it = 0; it < 8; it++) {
            int idx = tid + it * 128;
            int row = idx >> 4, c4 = idx & 15;
            size_t gk = ((size_t)((b * S_ + ks + row) * KV_ + kvh)) * D_ + c4 * 8;
            cp16(kb + (uint32_t)((row * AQS + c4 * 4) * 4), g_kh + gk);
        }
    };
    auto load_v = [&](int kt_, int st) {
        const int ks = kt_ * 64;
        uint32_t vb = sVT_b + st * VSTG_B;
        #pragma unroll
        for (int it = 0; it < 8; it++) {
            int idx = tid + it * 128;
            int vrow = idx >> 3, vc = idx & 7;
            size_t gv = ((size_t)((b * KV_ + kvh) * D_ + vrow)) * S_ + ks + vc * 8;
            cp16(vb + (uint32_t)((vrow * AVS + vc * 4) * 4), g_vth + gv);
        }
    };

    #pragma unroll
    for (int it = 0; it < 8; it++) {
        int idx = tid + it * 128;
        int row = idx >> 4;
        int c4  = idx & 15;
        size_t gq = ((size_t)((b * S_ + qs + row) * H_ + h)) * D_ + c4 * 8;
        *(uint4*)&sQ[row * AQS + c4 * 4]          = *(const uint4*)(g_qhi + gq);
        *(uint4*)&sQ[A_QOFF + row * AQS + c4 * 4] = *(const uint4*)(g_qlo + gq);
    }

    load_k(0, 0); CP_COMMIT();
    load_v(0, 0); CP_COMMIT();

    float o[16][4];
    #pragma unroll
    for (int nf = 0; nf < 16; nf++)
        #pragma unroll
        for (int r = 0; r < 4; r++) o[nf][r] = 0.f;
    float mrow[2] = {-1e30f, -1e30f};
    float lrow[2] = {0.f, 0.f};

    for (int kt = 0; kt <= qt; kt++) {
        const int cur = kt & 1;
        __syncthreads();

        if (kt < qt) {
            load_k(kt + 1, cur ^ 1); CP_COMMIT();
            load_v(kt + 1, cur ^ 1); CP_COMMIT();
            cp_wait<3>();
        } else {
            cp_wait<1>();
        }
        __syncthreads();

        const uint32_t kb = sK_b + cur * KSTG_B;
        const uint32_t vb = sVT_b + cur * VSTG_B;

        // ---- QK^T: load all K frags, then hi-terms x8, then lo-terms x8 ----
        float acc[8][4];
        #pragma unroll
        for (int nf = 0; nf < 8; nf++)
            #pragma unroll
            for (int r = 0; r < 4; r++) acc[nf][r] = 0.f;

        #pragma unroll
        for (int kq = 0; kq < 8; kq++) {
            const uint32_t ko = kq * 32;
            uint32_t ah[4], al[4], rh[4][4];
            ldsm_x4(ah, sQ_b + qoff + ko);
            ldsm_x4(al, sQ_b + QLO_B + qoff + ko);
            #pragma unroll
            for (int p = 0; p < 4; p++)
                ldsm_x4(rh[p], kb + koff[p] + ko);
            #pragma unroll
            for (int p = 0; p < 4; p++) {
                mma16816(acc[2*p],   ah, rh[p]);
                mma16816(acc[2*p+1], ah, rh[p] + 2);
            }
            #pragma unroll
            for (int p = 0; p < 4; p++) {
                mma16816(acc[2*p],   al, rh[p]);
                mma16816(acc[2*p+1], al, rh[p] + 2);
            }
        }

        // ---- scale + causal mask ----
        if (kt == qt) {
            const int gr = warp * 16 + g;
            #pragma unroll
            for (int nf = 0; nf < 8; nf++) {
                int c0 = nf * 8 + 2 * t;
                acc[nf][0] = (c0     <= gr    ) ? acc[nf][0] * scale : -1e30f;
                acc[nf][1] = (c0 + 1 <= gr    ) ? acc[nf][1] * scale : -1e30f;
                acc[nf][2] = (c0     <= gr + 8) ? acc[nf][2] * scale : -1e30f;
                acc[nf][3] = (c0 + 1 <= gr + 8) ? acc[nf][3] * scale : -1e30f;
            }
        } else {
            #pragma unroll
            for (int nf = 0; nf < 8; nf++)
                #pragma unroll
                for (int r = 0; r < 4; r++) acc[nf][r] *= scale;
        }

        // ---- online softmax ----
        float mx0 = -1e30f, mx1 = -1e30f;
        #pragma unroll
        for (int nf = 0; nf < 8; nf++) {
            mx0 = fmaxf(mx0, fmaxf(acc[nf][0], acc[nf][1]));
            mx1 = fmaxf(mx1, fmaxf(acc[nf][2], acc[nf][3]));
        }
        mx0 = fmaxf(mx0, __shfl_xor_sync(0xffffffffu, mx0, 1));
        mx0 = fmaxf(mx0, __shfl_xor_sync(0xffffffffu, mx0, 2));
        mx1 = fmaxf(mx1, __shfl_xor_sync(0xffffffffu, mx1, 1));
        mx1 = fmaxf(mx1, __shfl_xor_sync(0xffffffffu, mx1, 2));

        float nm0 = fmaxf(mrow[0], mx0), nm1 = fmaxf(mrow[1], mx1);
        float alpha0 = __expf(mrow[0] - nm0), alpha1 = __expf(mrow[1] - nm1);
        mrow[0] = nm0; mrow[1] = nm1;

        float sum0 = 0.f, sum1 = 0.f;
        #pragma unroll
        for (int nf = 0; nf < 8; nf++) {
            acc[nf][0] = __expf(acc[nf][0] - nm0); sum0 += acc[nf][0];
            acc[nf][1] = __expf(acc[nf][1] - nm0); sum0 += acc[nf][1];
            acc[nf][2] = __expf(acc[nf][2] - nm1); sum1 += acc[nf][2];
            acc[nf][3] = __expf(acc[nf][3] - nm1); sum1 += acc[nf][3];
        }
        sum0 += __shfl_xor_sync(0xffffffffu, sum0, 1);
        sum0 += __shfl_xor_sync(0xffffffffu, sum0, 2);
        sum1 += __shfl_xor_sync(0xffffffffu, sum1, 1);
        sum1 += __shfl_xor_sync(0xffffffffu, sum1, 2);
        lrow[0] = lrow[0] * alpha0 + sum0;
        lrow[1] = lrow[1] * alpha1 + sum1;

        #pragma unroll
        for (int nf = 0; nf < 16; nf++) {
            o[nf][0] *= alpha0; o[nf][1] *= alpha0;
            o[nf][2] *= alpha1; o[nf][3] *= alpha1;
        }

        if (kt < qt) cp_wait<2>(); else cp_wait<0>();
        __syncthreads();

        // ---- P @ V: per kq, per half (4 p): load frags, hi-terms x8, lo x8 ----
        #pragma unroll
        for (int kq = 0; kq < 4; kq++) {
            uint32_t pah[4], pal[4];
            pack_hilo_h(acc[2*kq  ][0], acc[2*kq  ][1], pah[0], pal[0]);
            pack_hilo_h(acc[2*kq  ][2], acc[2*kq  ][3], pah[1], pal[1]);
            pack_hilo_h(acc[2*kq+1][0], acc[2*kq+1][1], pah[2], pal[2]);
            pack_hilo_h(acc[2*kq+1][2], acc[2*kq+1][3], pah[3], pal[3]);
            const uint32_t ko = kq * 32;
            #pragma unroll
            for (int hf = 0; hf < 2; hf++) {
                uint32_t rh[4][4];
                #pragma unroll
                for (int p = 0; p < 4; p++)
                    ldsm_x4(rh[p], vb + voff[hf * 4 + p] + ko);
                #pragma unroll
                for (int p = 0; p < 4; p++) {
                    int op = 2 * (hf * 4 + p);
                    mma16816(o[op],     pah, rh[p]);
                    mma16816(o[op + 1], pah, rh[p] + 2);
                }
                #pragma unroll
                for (int p = 0; p < 4; p++) {
                    int op = 2 * (hf * 4 + p);
                    mma16816(o[op],     pal, rh[p]);
                    mma16816(o[op + 1], pal, rh[p] + 2);
                }
            }
        }
    }

    float inv0 = 1.f / lrow[0], inv1 = 1.f / lrow[1];
    size_t base0 = ((size_t)((b * S_ + qs + warp * 16 + g)) * H_ + h) * D_;
    size_t base1 = base0 + (size_t)8 * H_ * D_;
    #pragma unroll
    for (int nf = 0; nf < 16; nf++) {
        int d0 = nf * 8 + 2 * t;
        uint32_t hh, ll;
        pack_hilo_h(o[nf][0] * inv0, o[nf][1] * inv0, hh, ll);
        *(uint32_t*)&g_aohi[base0 + d0] = hh;
        *(uint32_t*)&g_aolo[base0 + d0] = ll;
        pack_hilo_h(o[nf][2] * inv1, o[nf][3] * inv1, hh, ll);
        *(uint32_t*)&g_aohi[base1 + d0] = hh;
        *(uint32_t*)&g_aolo[base1 + d0] = ll;
    }
}

// ---------------------------------------------------------------------------
// kernel_launch
// ---------------------------------------------------------------------------
extern "C" void kernel_launch(void* const* d_in, const int* in_sizes, int n_in,
                              void* d_out, int out_size)
{
    const float* x    = (const float*)d_in[0];
    const float* cosp = (const float*)d_in[1];
    const float* sinp = (const float*)d_in[2];
    // d_in[3] = attention_mask (all ones; unused by reference)
    const float* Wq = (const float*)d_in[4];
    const float* bq = (const float*)d_in[5];
    const float* Wk = (const float*)d_in[6];
    const float* bk = (const float*)d_in[7];
    const float* Wv = (const float*)d_in[8];
    const float* bv = (const float*)d_in[9];
    const float* Wo = (const float*)d_in[10];
    float* out = (float*)d_out;

    __half *xhi, *xlo, *wq, *wk, *wv, *wo, *aohi, *aolo, *qhi, *qlo, *kh, *vth;
    cudaGetSymbolAddress((void**)&xhi,  g_xhi);  cudaGetSymbolAddress((void**)&xlo,  g_xlo);
    cudaGetSymbolAddress((void**)&wq,   g_wq);
    cudaGetSymbolAddress((void**)&wk,   g_wk);
    cudaGetSymbolAddress((void**)&wv,   g_wv);
    cudaGetSymbolAddress((void**)&wo,   g_wo);
    cudaGetSymbolAddress((void**)&aohi, g_aohi); cudaGetSymbolAddress((void**)&aolo, g_aolo);
    cudaGetSymbolAddress((void**)&qhi,  g_qhi);  cudaGetSymbolAddress((void**)&qlo,  g_qlo);
    cudaGetSymbolAddress((void**)&kh,   g_kh);
    cudaGetSymbolAddress((void**)&vth,  g_vth);

    const int M = B_ * S_;   // 4096

    // One segmented split launch: x -> hi/lo, weights -> single fp16
    {
        SplitSegs s;
        s.in[0] = x;  s.hi[0] = xhi; s.lo[0] = xlo;
        s.in[1] = Wq; s.hi[1] = wq;  s.lo[1] = nullptr;
        s.in[2] = Wk; s.hi[2] = wk;  s.lo[2] = nullptr;
        s.in[3] = Wv; s.hi[3] = wv;  s.lo[3] = nullptr;
        s.in[4] = Wo; s.hi[4] = wo;  s.lo[4] = nullptr;
        int c0 = (int)(XN / 4);
        int c1 = c0 + (int)(WQN / 4);
        int c2 = c1 + (int)(WKN / 4);
        int c3 = c2 + (int)(WKN / 4);
        int c4 = c3 + (int)(WON / 4);
        s.end[0] = c0; s.end[1] = c1; s.end[2] = c2; s.end[3] = c3; s.end[4] = c4;
        split_all_kernel<<<(c4 + 511) / 512, 256>>>(s);
    }

    cudaFuncSetAttribute(gemm_qkv, cudaFuncAttributeMaxDynamicSharedMemorySize, GEMM_SMEM_BYTES);
    cudaFuncSetAttribute(gemm_o,   cudaFuncAttributeMaxDynamicSharedMemorySize, GEMM_SMEM_BYTES);

    // Fused QKV projection + RoPE + split + V-transpose (one launch)
    gemm_qkv<<<dim3(24, M / 128), 256, GEMM_SMEM_BYTES>>>(
        xhi, xlo, wq, wk, wv, bq, bk, bv, cosp, sinp, qhi, qlo, kh, vth);

    // MMA flash attention (double-buffered K/V)
    cudaFuncSetAttribute(attn_mma_kernel, cudaFuncAttributeMaxDynamicSharedMemorySize,
                         ATTN_SMEM_BYTES);
    attn_mma_kernel<<<dim3(S_ / 64, H_, B_), 128, ATTN_SMEM_BYTES>>>();

    // O projection
    gemm_o<<<dim3(DM_ / 128, M / 128), 256, GEMM_SMEM_BYTES>>>(
        aohi, aolo, wo, out, DM_, DM_);
}

// round 14
// speedup vs baseline: 7.5633x; 1.5151x over previous
#include <cuda_runtime.h>
#include <cuda_fp16.h>
#include <cstdint>

// Problem constants
#define B_  2
#define S_  2048
#define DM_ 2048
#define H_  16
#define KV_ 4
#define D_  128

#define XN  ((size_t)B_ * S_ * DM_)
#define QN  ((size_t)B_ * S_ * H_ * D_)
#define KN  ((size_t)B_ * S_ * KV_ * D_)
#define WQN ((size_t)H_ * D_ * DM_)
#define WKN ((size_t)KV_ * D_ * DM_)
#define WON ((size_t)DM_ * H_ * D_)

// fp16 scratch — ALL single precision fp16 now (no hi/lo pairs).
__device__ __half g_xh  [XN];
__device__ __half g_wq  [WQN];
__device__ __half g_wk  [WKN];
__device__ __half g_wv  [WKN];
__device__ __half g_wo  [WON];
__device__ __half g_aoh [QN];
__device__ __half g_qh  [QN];
__device__ __half g_kh  [KN];
__device__ __half g_vth [KN];               // [B][KV][D][S]

// ---------------------------------------------------------------------------
// helpers
// ---------------------------------------------------------------------------
__device__ __forceinline__ void mma16816(float* c, const uint32_t* a, const uint32_t* b)
{
    asm volatile(
        "mma.sync.aligned.m16n8k16.row.col.f32.f16.f16.f32 "
        "{%0,%1,%2,%3}, {%4,%5,%6,%7}, {%8,%9}, {%0,%1,%2,%3};\n"
        : "+f"(c[0]), "+f"(c[1]), "+f"(c[2]), "+f"(c[3])
        : "r"(a[0]), "r"(a[1]), "r"(a[2]), "r"(a[3]),
          "r"(b[0]), "r"(b[1]));
}

__device__ __forceinline__ void ldsm_x4(uint32_t* r, uint32_t addr)
{
    asm volatile("ldmatrix.sync.aligned.m8n8.x4.shared.b16 {%0,%1,%2,%3}, [%4];\n"
                 : "=r"(r[0]), "=r"(r[1]), "=r"(r[2]), "=r"(r[3]) : "r"(addr));
}

__device__ __forceinline__ void cp16(uint32_t smem_byte_addr, const void* gptr)
{
    asm volatile("cp.async.cg.shared.global [%0], [%1], 16;\n"
                 :: "r"(smem_byte_addr), "l"(gptr));
}
#define CP_COMMIT() asm volatile("cp.async.commit_group;\n" ::: "memory")
template <int N> __device__ __forceinline__ void cp_wait()
{
    asm volatile("cp.async.wait_group %0;\n" :: "n"(N) : "memory");
}

__device__ __forceinline__ uint32_t pack_h2(float a, float b)
{
    __half h0 = __float2half(a), h1 = __float2half(b);
    return ((uint32_t)__half_as_ushort(h1) << 16) | __half_as_ushort(h0);
}

// ---------------------------------------------------------------------------
// Segmented fp32 -> fp16 convert: all 5 tensors single fp16. 2x ILP/thread.
// ---------------------------------------------------------------------------
struct SplitSegs {
    const float* in[5];
    __half* hi[5];
    int end[5];        // cumulative end, in float4 units
};

__global__ void split_all_kernel(SplitSegs segs)
{
    int base = blockIdx.x * 512 + threadIdx.x;
    #pragma unroll
    for (int u = 0; u < 2; u++) {
        int idx = base + u * 256;
        if (idx >= segs.end[4]) continue;
        int s = 0;
        if (idx >= segs.end[0]) s = 1;
        if (idx >= segs.end[1]) s = 2;
        if (idx >= segs.end[2]) s = 3;
        if (idx >= segs.end[3]) s = 4;
        int sb = s ? segs.end[s - 1] : 0;
        int i = idx - sb;

        float4 v = ((const float4*)segs.in[s])[i];
        ((uint2*)segs.hi[s])[i] = make_uint2(pack_h2(v.x, v.y), pack_h2(v.z, v.w));
    }
}

// ---------------------------------------------------------------------------
// GEMM core (NT), pure fp16, 3-stage cp.async ring + ldmatrix.
// Block 128x128x32, 8 warps, warp tile 64x32. 16 MMAs per kq.
// MODE 0: fp32 C output (O projection)
// MODE 1: fused RoPE + fp16 (Q)  — column tile == one head
// MODE 2: fused RoPE + fp16 (K)
// MODE 3: fused transpose + fp16 (V) -> [B][KV][D][S]
// ---------------------------------------------------------------------------
#define SSTRIDE 20
#define G_HALF  (128 * SSTRIDE)          // u32 per region
#define G_STG   (2 * G_HALF)             // u32 per stage (A + B regions)
#define G_B_B   (G_HALF * 4)             // byte offset of B region
#define GEMM_SMEM_BYTES 66048            // max(3*G_STG*4 = 61440, 128*129*4 staging)

template <int MODE>
__device__ __forceinline__ void gemm_core(
    const __half* __restrict__ Am, const __half* __restrict__ Bm,
    const float* __restrict__ bias,
    const float* __restrict__ cs, const float* __restrict__ sn,
    float* __restrict__ Cf, __half* __restrict__ Oh,
    int N, int K, int bm, int bn, int head)
{
    extern __shared__ uint32_t sm[];

    const int tid  = threadIdx.x;
    const int lane = tid & 31;
    const int warp = tid >> 5;
    const int wm   = warp & 1;
    const int wn   = warp >> 1;

    const int lrow = tid >> 2;
    const int lkc  = tid & 3;

    const uint32_t smB = (uint32_t)__cvta_generic_to_shared(sm);

    const int a_row = (lane & 7) + ((lane >> 3) & 1) * 8;
    const int a_chk = ((lane >> 4) & 1) * 4;
    const int b_row = (lane & 7) + ((lane >> 4) & 1) * 8;
    const int b_chk = ((lane >> 3) & 1) * 4;

    uint32_t aoff[4], boff[2];
    #pragma unroll
    for (int mf = 0; mf < 4; mf++)
        aoff[mf] = (uint32_t)(((wm * 64 + mf * 16 + a_row) * SSTRIDE + a_chk) * 4);
    #pragma unroll
    for (int p = 0; p < 2; p++)
        boff[p] = (uint32_t)(((wn * 32 + p * 16 + b_row) * SSTRIDE + b_chk) * 4);

    float acc[4][4][4];
    #pragma unroll
    for (int mf = 0; mf < 4; mf++)
        #pragma unroll
        for (int nf = 0; nf < 4; nf++)
            #pragma unroll
            for (int r = 0; r < 4; r++) acc[mf][nf][r] = 0.f;

    const int niter = K / 32;

    auto load_stage = [&](int st, int k0) {
        uint32_t sbase = (uint32_t)(st * G_STG) * 4;
        #pragma unroll
        for (int r = 0; r < 2; r++) {
            int row = lrow + r * 64;
            size_t ga = (size_t)(bm + row) * K + k0 + lkc * 8;
            size_t gb = (size_t)(bn + row) * K + k0 + lkc * 8;
            uint32_t off = (uint32_t)(row * SSTRIDE + lkc * 4) * 4;
            cp16(smB + sbase + off,         Am + ga);
            cp16(smB + sbase + G_B_B + off, Bm + gb);
        }
    };

    load_stage(0, 0);
    CP_COMMIT();
    load_stage(1, 32);
    CP_COMMIT();

    for (int it = 0; it < niter; it++) {
        if (it < niter - 1) cp_wait<1>(); else cp_wait<0>();
        __syncthreads();
        if (it + 2 < niter) {
            load_stage((it + 2) % 3, (it + 2) * 32);
            CP_COMMIT();
        }

        const uint32_t stg = smB + (uint32_t)((it % 3) * G_STG) * 4;

        #pragma unroll
        for (int kq = 0; kq < 2; kq++) {
            const uint32_t ko = kq * 32;
            uint32_t ah[4][4], bh[4][2];

            #pragma unroll
            for (int mf = 0; mf < 4; mf++)
                ldsm_x4(ah[mf], stg + aoff[mf] + ko);
            #pragma unroll
            for (int p = 0; p < 2; p++) {
                uint32_t r[4];
                ldsm_x4(r, stg + G_B_B + boff[p] + ko);
                bh[2*p][0] = r[0]; bh[2*p][1] = r[1];
                bh[2*p+1][0] = r[2]; bh[2*p+1][1] = r[3];
            }
            #pragma unroll
            for (int mf = 0; mf < 4; mf++)
                #pragma unroll
                for (int nf = 0; nf < 4; nf++)
                    mma16816(acc[mf][nf], ah[mf], bh[nf]);
        }
    }
    __syncthreads();   // all smem pipeline reads done

    if (MODE == 0) {
        #pragma unroll
        for (int mf = 0; mf < 4; mf++) {
            int m0 = bm + wm * 64 + mf * 16 + (lane >> 2);
            #pragma unroll
            for (int nf = 0; nf < 4; nf++) {
                int n0 = bn + wn * 32 + nf * 8 + (lane & 3) * 2;
                Cf[(size_t)m0 * N + n0]           = acc[mf][nf][0];
                Cf[(size_t)m0 * N + n0 + 1]       = acc[mf][nf][1];
                Cf[(size_t)(m0 + 8) * N + n0]     = acc[mf][nf][2];
                Cf[(size_t)(m0 + 8) * N + n0 + 1] = acc[mf][nf][3];
            }
        }
        return;
    }

    // ---- staged epilogue: acc (+bias) -> smem fp32 [128][129] ----
    float* ts = (float*)sm;
    #define TSX(r, c) ts[(r) * 129 + (c)]
    #pragma unroll
    for (int mf = 0; mf < 4; mf++) {
        int r0 = wm * 64 + mf * 16 + (lane >> 2);
        #pragma unroll
        for (int nf = 0; nf < 4; nf++) {
            int c0 = wn * 32 + nf * 8 + (lane & 3) * 2;
            float b0 = bias[bn + c0], b1 = bias[bn + c0 + 1];
            TSX(r0, c0)         = acc[mf][nf][0] + b0;
            TSX(r0, c0 + 1)     = acc[mf][nf][1] + b1;
            TSX(r0 + 8, c0)     = acc[mf][nf][2] + b0;
            TSX(r0 + 8, c0 + 1) = acc[mf][nf][3] + b1;
        }
    }
    __syncthreads();

    if (MODE == 1 || MODE == 2) {
        // RoPE over (d, d+64) pairs; row r maps to global (b*S+s) = bm + r
        for (int i = tid; i < 128 * 64; i += 256) {
            int r = i >> 6, d = i & 63;
            size_t gr = (size_t)(bm + r);
            float cv0 = cs[gr * D_ + d],      sv0 = sn[gr * D_ + d];
            float cv1 = cs[gr * D_ + d + 64], sv1 = sn[gr * D_ + d + 64];
            float a  = TSX(r, d);
            float b2 = TSX(r, d + 64);
            float r0 = a  * cv0 - b2 * sv0;
            float r1 = b2 * cv1 + a  * sv1;
            size_t base = (MODE == 1) ? (gr * H_ + head) * D_
                                      : (gr * KV_ + head) * D_;
            Oh[base + d]      = __float2half(r0);
            Oh[base + d + 64] = __float2half(r1);
        }
    } else {
        // MODE 3: transpose to [B][KV][D][S]; smem column reads stride 129
        int d  = tid >> 1;
        int sh = (tid & 1) * 64;
        int bb = bm >> 11;          // bm / S_
        int s0 = bm & 2047;         // bm % S_
        size_t ob = (((size_t)bb * KV_ + head) * D_ + d) * S_ + s0 + sh;
        #pragma unroll
        for (int j = 0; j < 64; j += 8) {
            uint32_t w0 = pack_h2(TSX(sh + j,     d), TSX(sh + j + 1, d));
            uint32_t w1 = pack_h2(TSX(sh + j + 2, d), TSX(sh + j + 3, d));
            uint32_t w2 = pack_h2(TSX(sh + j + 4, d), TSX(sh + j + 5, d));
            uint32_t w3 = pack_h2(TSX(sh + j + 6, d), TSX(sh + j + 7, d));
            *(uint4*)&Oh[ob + j] = make_uint4(w0, w1, w2, w3);
        }
    }
    #undef TSX
}

// O-projection GEMM (fp32 out, no bias)
__global__ __launch_bounds__(256) void gemm_o(
    const __half* __restrict__ Am, const __half* __restrict__ Bm,
    float* __restrict__ C, int N, int K)
{
    gemm_core<0>(Am, Bm, nullptr, nullptr, nullptr, C, nullptr,
                 N, K, blockIdx.y * 128, blockIdx.x * 128, 0);
}

// Fused QKV projection + RoPE + V-transpose.
// grid.x = 24 column tiles (16 Q heads, 4 K heads, 4 V heads)
__global__ __launch_bounds__(256) void gemm_qkv(
    const __half* __restrict__ xh,
    const __half* __restrict__ wq, const __half* __restrict__ wk,
    const __half* __restrict__ wv,
    const float* __restrict__ bq, const float* __restrict__ bk,
    const float* __restrict__ bv,
    const float* __restrict__ cs, const float* __restrict__ sn,
    __half* __restrict__ qh, __half* __restrict__ kh, __half* __restrict__ vth)
{
    const int ct = blockIdx.x;
    const int bm = blockIdx.y * 128;
    if (ct < 16) {
        gemm_core<1>(xh, wq, bq, cs, sn, nullptr, qh,
                     2048, DM_, bm, ct * 128, ct);
    } else if (ct < 20) {
        gemm_core<2>(xh, wk, bk, cs, sn, nullptr, kh,
                     512, DM_, bm, (ct - 16) * 128, ct - 16);
    } else {
        gemm_core<3>(xh, wv, bv, nullptr, nullptr, nullptr, vth,
                     512, DM_, bm, (ct - 20) * 128, ct - 20);
    }
}

// ---------------------------------------------------------------------------
// MMA flash attention (causal, GQA), pure fp16, double-buffered K/V.
// ---------------------------------------------------------------------------
#define AQS 68
#define AVS 36
#define QREG_B (64 * AQS * 4)            // Q region bytes (single)
#define KSTG_B (64 * AQS * 4)
#define VSTG_B (128 * AVS * 4)
#define ATTN_SMEM_BYTES (QREG_B + 2 * KSTG_B + 2 * VSTG_B)  // 89,088

__global__ __launch_bounds__(128) void attn_mma_kernel()
{
    extern __shared__ uint32_t smu[];
    uint32_t* sQ  = smu;                       // [64][AQS]

    const int tid  = threadIdx.x;
    const int lane = tid & 31;
    const int warp = tid >> 5;
    const int g    = lane >> 2;
    const int t    = lane & 3;
    const int qt   = gridDim.x - 1 - blockIdx.x;
    const int h    = blockIdx.y;
    const int b    = blockIdx.z;
    const int qs   = qt * 64;
    const int kvh  = h >> 2;
    const float scale = 0.08838834764831845f;

    const uint32_t smB   = (uint32_t)__cvta_generic_to_shared(smu);
    const uint32_t sQ_b  = smB;
    const uint32_t sK_b  = smB + QREG_B;
    const uint32_t sVT_b = sK_b + 2 * KSTG_B;

    const int a_row = (lane & 7) + ((lane >> 3) & 1) * 8;
    const int a_chk = ((lane >> 4) & 1) * 4;
    const int b_row = (lane & 7) + ((lane >> 4) & 1) * 8;
    const int b_chk = ((lane >> 3) & 1) * 4;

    const uint32_t qoff = (uint32_t)(((warp * 16 + a_row) * AQS + a_chk) * 4);
    uint32_t koff[4], voff[8];
    #pragma unroll
    for (int p = 0; p < 4; p++)
        koff[p] = (uint32_t)(((p * 16 + b_row) * AQS + b_chk) * 4);
    #pragma unroll
    for (int p = 0; p < 8; p++)
        voff[p] = (uint32_t)(((p * 16 + b_row) * AVS + b_chk) * 4);

    auto load_k = [&](int kt_, int st) {
        const int ks = kt_ * 64;
        uint32_t kb = sK_b + st * KSTG_B;
        #pragma unroll
        for (int it = 0; it < 8; it++) {
            int idx = tid + it * 128;
            int row = idx >> 4, c4 = idx & 15;
            size_t gk = ((size_t)((b * S_ + ks + row) * KV_ + kvh)) * D_ + c4 * 8;
            cp16(kb + (uint32_t)((row * AQS + c4 * 4) * 4), g_kh + gk);
        }
    };
    auto load_v = [&](int kt_, int st) {
        const int ks = kt_ * 64;
        uint32_t vb = sVT_b + st * VSTG_B;
        #pragma unroll
        for (int it = 0; it < 8; it++) {
            int idx = tid + it * 128;
            int vrow = idx >> 3, vc = idx & 7;
            size_t gv = ((size_t)((b * KV_ + kvh) * D_ + vrow)) * S_ + ks + vc * 8;
            cp16(vb + (uint32_t)((vrow * AVS + vc * 4) * 4), g_vth + gv);
        }
    };

    // Load Q tile (single fp16) - plain stores, covered by first __syncthreads
    #pragma unroll
    for (int it = 0; it < 4; it++) {
        int idx = tid + it * 128;
        int row = idx >> 3;
        int c4  = idx & 7;
        size_t gq = ((size_t)((b * S_ + qs + row) * H_ + h)) * D_ + c4 * 16;
        *(uint4*)&sQ[row * AQS + c4 * 8]     = *(const uint4*)(g_qh + gq);
        *(uint4*)&sQ[row * AQS + c4 * 8 + 4] = *(const uint4*)(g_qh + gq + 8);
    }

    load_k(0, 0); CP_COMMIT();
    load_v(0, 0); CP_COMMIT();

    float o[16][4];
    #pragma unroll
    for (int nf = 0; nf < 16; nf++)
        #pragma unroll
        for (int r = 0; r < 4; r++) o[nf][r] = 0.f;
    float mrow[2] = {-1e30f, -1e30f};
    float lrow[2] = {0.f, 0.f};

    for (int kt = 0; kt <= qt; kt++) {
        const int cur = kt & 1;
        __syncthreads();

        if (kt < qt) {
            load_k(kt + 1, cur ^ 1); CP_COMMIT();
            load_v(kt + 1, cur ^ 1); CP_COMMIT();
            cp_wait<3>();
        } else {
            cp_wait<1>();
        }
        __syncthreads();

        const uint32_t kb = sK_b + cur * KSTG_B;
        const uint32_t vb = sVT_b + cur * VSTG_B;

        // ---- QK^T (single-term) ----
        float acc[8][4];
        #pragma unroll
        for (int nf = 0; nf < 8; nf++)
            #pragma unroll
            for (int r = 0; r < 4; r++) acc[nf][r] = 0.f;

        #pragma unroll
        for (int kq = 0; kq < 8; kq++) {
            const uint32_t ko = kq * 32;
            uint32_t ah[4], rh[4][4];
            ldsm_x4(ah, sQ_b + qoff + ko);
            #pragma unroll
            for (int p = 0; p < 4; p++)
                ldsm_x4(rh[p], kb + koff[p] + ko);
            #pragma unroll
            for (int p = 0; p < 4; p++) {
                mma16816(acc[2*p],   ah, rh[p]);
                mma16816(acc[2*p+1], ah, rh[p] + 2);
            }
        }

        // ---- scale + causal mask ----
        if (kt == qt) {
            const int gr = warp * 16 + g;
            #pragma unroll
            for (int nf = 0; nf < 8; nf++) {
                int c0 = nf * 8 + 2 * t;
                acc[nf][0] = (c0     <= gr    ) ? acc[nf][0] * scale : -1e30f;
                acc[nf][1] = (c0 + 1 <= gr    ) ? acc[nf][1] * scale : -1e30f;
                acc[nf][2] = (c0     <= gr + 8) ? acc[nf][2] * scale : -1e30f;
                acc[nf][3] = (c0 + 1 <= gr + 8) ? acc[nf][3] * scale : -1e30f;
            }
        } else {
            #pragma unroll
            for (int nf = 0; nf < 8; nf++)
                #pragma unroll
                for (int r = 0; r < 4; r++) acc[nf][r] *= scale;
        }

        // ---- online softmax ----
        float mx0 = -1e30f, mx1 = -1e30f;
        #pragma unroll
        for (int nf = 0; nf < 8; nf++) {
            mx0 = fmaxf(mx0, fmaxf(acc[nf][0], acc[nf][1]));
            mx1 = fmaxf(mx1, fmaxf(acc[nf][2], acc[nf][3]));
        }
        mx0 = fmaxf(mx0, __shfl_xor_sync(0xffffffffu, mx0, 1));
        mx0 = fmaxf(mx0, __shfl_xor_sync(0xffffffffu, mx0, 2));
        mx1 = fmaxf(mx1, __shfl_xor_sync(0xffffffffu, mx1, 1));
        mx1 = fmaxf(mx1, __shfl_xor_sync(0xffffffffu, mx1, 2));

        float nm0 = fmaxf(mrow[0], mx0), nm1 = fmaxf(mrow[1], mx1);
        float alpha0 = __expf(mrow[0] - nm0), alpha1 = __expf(mrow[1] - nm1);
        mrow[0] = nm0; mrow[1] = nm1;

        float sum0 = 0.f, sum1 = 0.f;
        #pragma unroll
        for (int nf = 0; nf < 8; nf++) {
            acc[nf][0] = __expf(acc[nf][0] - nm0); sum0 += acc[nf][0];
            acc[nf][1] = __expf(acc[nf][1] - nm0); sum0 += acc[nf][1];
            acc[nf][2] = __expf(acc[nf][2] - nm1); sum1 += acc[nf][2];
            acc[nf][3] = __expf(acc[nf][3] - nm1); sum1 += acc[nf][3];
        }
        sum0 += __shfl_xor_sync(0xffffffffu, sum0, 1);
        sum0 += __shfl_xor_sync(0xffffffffu, sum0, 2);
        sum1 += __shfl_xor_sync(0xffffffffu, sum1, 1);
        sum1 += __shfl_xor_sync(0xffffffffu, sum1, 2);
        lrow[0] = lrow[0] * alpha0 + sum0;
        lrow[1] = lrow[1] * alpha1 + sum1;

        #pragma unroll
        for (int nf = 0; nf < 16; nf++) {
            o[nf][0] *= alpha0; o[nf][1] *= alpha0;
            o[nf][2] *= alpha1; o[nf][3] *= alpha1;
        }

        if (kt < qt) cp_wait<2>(); else cp_wait<0>();
        __syncthreads();

        // ---- P @ V (P single fp16 in regs; V single) ----
        #pragma unroll
        for (int kq = 0; kq < 4; kq++) {
            uint32_t pah[4];
            pah[0] = pack_h2(acc[2*kq  ][0], acc[2*kq  ][1]);
            pah[1] = pack_h2(acc[2*kq  ][2], acc[2*kq  ][3]);
            pah[2] = pack_h2(acc[2*kq+1][0], acc[2*kq+1][1]);
            pah[3] = pack_h2(acc[2*kq+1][2], acc[2*kq+1][3]);
            const uint32_t ko = kq * 32;
            #pragma unroll
            for (int p = 0; p < 8; p++) {
                uint32_t rh[4];
                ldsm_x4(rh, vb + voff[p] + ko);
                mma16816(o[2*p],   pah, rh);
                mma16816(o[2*p+1], pah, rh + 2);
            }
        }
    }

    // ---- epilogue: normalize, write ao single fp16 ----
    float inv0 = 1.f / lrow[0], inv1 = 1.f / lrow[1];
    size_t base0 = ((size_t)((b * S_ + qs + warp * 16 + g)) * H_ + h) * D_;
    size_t base1 = base0 + (size_t)8 * H_ * D_;
    #pragma unroll
    for (int nf = 0; nf < 16; nf++) {
        int d0 = nf * 8 + 2 * t;
        *(uint32_t*)&g_aoh[base0 + d0] = pack_h2(o[nf][0] * inv0, o[nf][1] * inv0);
        *(uint32_t*)&g_aoh[base1 + d0] = pack_h2(o[nf][2] * inv1, o[nf][3] * inv1);
    }
}

// ---------------------------------------------------------------------------
// kernel_launch
// ---------------------------------------------------------------------------
extern "C" void kernel_launch(void* const* d_in, const int* in_sizes, int n_in,
                              void* d_out, int out_size)
{
    const float* x    = (const float*)d_in[0];
    const float* cosp = (const float*)d_in[1];
    const float* sinp = (const float*)d_in[2];
    // d_in[3] = attention_mask (all ones; unused by reference)
    const float* Wq = (const float*)d_in[4];
    const float* bq = (const float*)d_in[5];
    const float* Wk = (const float*)d_in[6];
    const float* bk = (const float*)d_in[7];
    const float* Wv = (const float*)d_in[8];
    const float* bv = (const float*)d_in[9];
    const float* Wo = (const float*)d_in[10];
    float* out = (float*)d_out;

    __half *xh, *wq, *wk, *wv, *wo, *aoh, *qh, *kh, *vth;
    cudaGetSymbolAddress((void**)&xh,  g_xh);
    cudaGetSymbolAddress((void**)&wq,  g_wq);
    cudaGetSymbolAddress((void**)&wk,  g_wk);
    cudaGetSymbolAddress((void**)&wv,  g_wv);
    cudaGetSymbolAddress((void**)&wo,  g_wo);
    cudaGetSymbolAddress((void**)&aoh, g_aoh);
    cudaGetSymbolAddress((void**)&qh,  g_qh);
    cudaGetSymbolAddress((void**)&kh,  g_kh);
    cudaGetSymbolAddress((void**)&vth, g_vth);

    const int M = B_ * S_;   // 4096

    // One segmented convert launch: everything -> single fp16
    {
        SplitSegs s;
        s.in[0] = x;  s.hi[0] = xh;
        s.in[1] = Wq; s.hi[1] = wq;
        s.in[2] = Wk; s.hi[2] = wk;
        s.in[3] = Wv; s.hi[3] = wv;
        s.in[4] = Wo; s.hi[4] = wo;
        int c0 = (int)(XN / 4);
        int c1 = c0 + (int)(WQN / 4);
        int c2 = c1 + (int)(WKN / 4);
        int c3 = c2 + (int)(WKN / 4);
        int c4 = c3 + (int)(WON / 4);
        s.end[0] = c0; s.end[1] = c1; s.end[2] = c2; s.end[3] = c3; s.end[4] = c4;
        split_all_kernel<<<(c4 + 511) / 512, 256>>>(s);
    }

    cudaFuncSetAttribute(gemm_qkv, cudaFuncAttributeMaxDynamicSharedMemorySize, GEMM_SMEM_BYTES);
    cudaFuncSetAttribute(gemm_o,   cudaFuncAttributeMaxDynamicSharedMemorySize, GEMM_SMEM_BYTES);

    // Fused QKV projection + RoPE + V-transpose (one launch)
    gemm_qkv<<<dim3(24, M / 128), 256, GEMM_SMEM_BYTES>>>(
        xh, wq, wk, wv, bq, bk, bv, cosp, sinp, qh, kh, vth);

    // MMA flash attention (double-buffered K/V)
    cudaFuncSetAttribute(attn_mma_kernel, cudaFuncAttributeMaxDynamicSharedMemorySize,
                         ATTN_SMEM_BYTES);
    attn_mma_kernel<<<dim3(S_ / 64, H_, B_), 128, ATTN_SMEM_BYTES>>>();

    // O projection
    gemm_o<<<dim3(DM_ / 128, M / 128), 256, GEMM_SMEM_BYTES>>>(
        aoh, wo, out, DM_, DM_);
}